// round 1
// baseline (speedup 1.0000x reference)
#include <cuda_runtime.h>
#include <cmath>

// ---------------- problem constants ----------------
constexpr int Bn  = 2;
constexpr int Sn  = 1024;
constexpr int Dn  = 512;
constexpr int Hn  = 8;
constexpr int HDn = 64;
constexpr int FFn = 2048;
constexpr int Ln  = 4;
constexpr int Mn  = Bn * Sn;   // 2048
constexpr int BHn = Bn * Hn;   // 16

#define EPSf   1e-7f
#define MAXNf  (1.0f - 1e-3f)

// ---------------- scratch (device globals; no allocation allowed) ----------------
__device__ float g_x   [Mn * Dn];
__device__ float g_h   [Mn * Dn];
__device__ float g_p   [Mn * Dn];
__device__ float g_t   [Mn * FFn];
__device__ float g_u   [Mn * FFn];
__device__ float g_qh  [Mn * Dn];      // [B,H,S,HD]
__device__ float g_kh  [Mn * Dn];
__device__ float g_vh  [Mn * Dn];
__device__ float g_w   [(size_t)BHn * Sn * Sn];   // 64 MB scores/weights
__device__ float g_lamv[Mn * Dn];
__device__ float g_lm1 [BHn * Sn];
__device__ float g_num [Mn * Dn];
__device__ float g_den [BHn * Sn];
__device__ float g_mid [Mn * Dn];

// ---------------- helpers ----------------
static __device__ __forceinline__ float atanh_f(float x) {
    return 0.5f * (log1pf(x) - log1pf(-x));
}

template<int NT>
__device__ __forceinline__ float block_sum(float v) {
    __shared__ float sh[NT / 32];
#pragma unroll
    for (int o = 16; o > 0; o >>= 1) v += __shfl_xor_sync(0xffffffffu, v, o);
    int w = threadIdx.x >> 5;
    if ((threadIdx.x & 31) == 0) sh[w] = v;
    __syncthreads();
    float r = sh[0];
#pragma unroll
    for (int i = 1; i < NT / 32; i++) r += sh[i];
    __syncthreads();
    return r;
}

template<int NT>
__device__ __forceinline__ float block_max(float v) {
    __shared__ float sh[NT / 32];
#pragma unroll
    for (int o = 16; o > 0; o >>= 1) v = fmaxf(v, __shfl_xor_sync(0xffffffffu, v, o));
    int w = threadIdx.x >> 5;
    if ((threadIdx.x & 31) == 0) sh[w] = v;
    __syncthreads();
    float r = sh[0];
#pragma unroll
    for (int i = 1; i < NT / 32; i++) r = fmaxf(r, sh[i]);
    __syncthreads();
    return r;
}

__device__ __forceinline__ float warp_sum(float v) {
#pragma unroll
    for (int o = 16; o > 0; o >>= 1) v += __shfl_xor_sync(0xffffffffu, v, o);
    return v;
}

// ---------------- row-wise hyperbolic kernels ----------------

// out = project(mobius_add(x_row, y_row))  ; y row index = r % ymod (broadcast for pos_tab)
template<int NT>
__global__ void k_mobius_add(const float* __restrict__ x, const float* __restrict__ y,
                             float* __restrict__ out, int ymod) {
    constexpr int P = Dn / NT;
    int r = blockIdx.x;
    const float* xr = x + (size_t)r * Dn;
    const float* yr = y + (size_t)(r % ymod) * Dn;
    float xl[P], yl[P];
    float x2 = 0.f, y2 = 0.f, xy = 0.f;
#pragma unroll
    for (int i = 0; i < P; i++) {
        int j = threadIdx.x + i * NT;
        xl[i] = xr[j]; yl[i] = yr[j];
        x2 += xl[i] * xl[i]; y2 += yl[i] * yl[i]; xy += xl[i] * yl[i];
    }
    x2 = block_sum<NT>(x2);
    y2 = block_sum<NT>(y2);
    xy = block_sum<NT>(xy);
    float den = fmaxf(1.f + 2.f * xy + x2 * y2, EPSf);
    float ca = (1.f + 2.f * xy + y2) / den;
    float cb = (1.f - x2) / den;
    float zl[P]; float n2 = 0.f;
#pragma unroll
    for (int i = 0; i < P; i++) { zl[i] = ca * xl[i] + cb * yl[i]; n2 += zl[i] * zl[i]; }
    n2 = block_sum<NT>(n2);
    float n = sqrtf(fmaxf(n2, EPSf * EPSf));
    float sc = fminf(1.f, MAXNf / n);
#pragma unroll
    for (int i = 0; i < P; i++) out[(size_t)r * Dn + threadIdx.x + i * NT] = zl[i] * sc;
}

// Poincare layernorm: expmap0(LN(logmap0(x)) * w + b)
template<int NT>
__global__ void k_pln(const float* __restrict__ x, const float* __restrict__ w,
                      const float* __restrict__ b, float* __restrict__ out) {
    constexpr int P = Dn / NT;
    int r = blockIdx.x;
    const float* xr = x + (size_t)r * Dn;
    float xl[P]; float ss = 0.f;
#pragma unroll
    for (int i = 0; i < P; i++) { xl[i] = xr[threadIdx.x + i * NT]; ss += xl[i] * xl[i]; }
    ss = block_sum<NT>(ss);
    float n  = sqrtf(fmaxf(ss, EPSf * EPSf));
    float nc = fminf(fmaxf(n, EPSf), MAXNf);
    float ls = atanh_f(nc) / nc;
    float tl[P]; float st = 0.f;
#pragma unroll
    for (int i = 0; i < P; i++) { tl[i] = ls * xl[i]; st += tl[i]; }
    st = block_sum<NT>(st);
    float mu = st / (float)Dn;
    float sv = 0.f;
#pragma unroll
    for (int i = 0; i < P; i++) { float d = tl[i] - mu; sv += d * d; }
    sv = block_sum<NT>(sv);
    float inv = rsqrtf(sv / (float)Dn + 1e-5f);
    float yl[P]; float sy = 0.f;
#pragma unroll
    for (int i = 0; i < P; i++) {
        int j = threadIdx.x + i * NT;
        yl[i] = (tl[i] - mu) * inv * w[j] + b[j];
        sy += yl[i] * yl[i];
    }
    sy = block_sum<NT>(sy);
    float ny = sqrtf(fmaxf(sy, EPSf * EPSf));
    float es = tanhf(ny) / ny;
#pragma unroll
    for (int i = 0; i < P; i++) out[(size_t)r * Dn + threadIdx.x + i * NT] = es * yl[i];
}

template<int DIM, int NT>
__global__ void k_logmap(const float* __restrict__ x, float* __restrict__ out, float scale) {
    constexpr int P = DIM / NT;
    int r = blockIdx.x;
    const float* xr = x + (size_t)r * DIM;
    float xl[P]; float ss = 0.f;
#pragma unroll
    for (int i = 0; i < P; i++) { xl[i] = xr[threadIdx.x + i * NT]; ss += xl[i] * xl[i]; }
    ss = block_sum<NT>(ss);
    float n  = sqrtf(fmaxf(ss, EPSf * EPSf));
    float nc = fminf(fmaxf(n, EPSf), MAXNf);
    float s  = atanh_f(nc) / nc * scale;
#pragma unroll
    for (int i = 0; i < P; i++) out[(size_t)r * DIM + threadIdx.x + i * NT] = s * xl[i];
}

template<int DIM, int NT>
__global__ void k_expmap(const float* __restrict__ x, float* __restrict__ out) {
    constexpr int P = DIM / NT;
    int r = blockIdx.x;
    const float* xr = x + (size_t)r * DIM;
    float xl[P]; float ss = 0.f;
#pragma unroll
    for (int i = 0; i < P; i++) { xl[i] = xr[threadIdx.x + i * NT]; ss += xl[i] * xl[i]; }
    ss = block_sum<NT>(ss);
    float n = sqrtf(fmaxf(ss, EPSf * EPSf));
    float s = tanhf(n) / n;
#pragma unroll
    for (int i = 0; i < P; i++) out[(size_t)r * DIM + threadIdx.x + i * NT] = s * xl[i];
}

// expmap0(relu(logmap0(x))) in-place, rows of FF
template<int DIM, int NT>
__global__ void k_relu_tan(float* __restrict__ x) {
    constexpr int P = DIM / NT;
    int r = blockIdx.x;
    float* xr = x + (size_t)r * DIM;
    float xl[P]; float ss = 0.f;
#pragma unroll
    for (int i = 0; i < P; i++) { xl[i] = xr[threadIdx.x + i * NT]; ss += xl[i] * xl[i]; }
    ss = block_sum<NT>(ss);
    float n  = sqrtf(fmaxf(ss, EPSf * EPSf));
    float nc = fminf(fmaxf(n, EPSf), MAXNf);
    float ls = atanh_f(nc) / nc;
    float tl[P]; float st = 0.f;
#pragma unroll
    for (int i = 0; i < P; i++) { tl[i] = fmaxf(ls * xl[i], 0.f); st += tl[i] * tl[i]; }
    st = block_sum<NT>(st);
    float n2 = sqrtf(fmaxf(st, EPSf * EPSf));
    float es = tanhf(n2) / n2;
#pragma unroll
    for (int i = 0; i < P; i++) xr[threadIdx.x + i * NT] = es * tl[i];
}

// split: input t[B,S,D] = logmap0(p)*ratio, output per-head expmap0 -> [B,H,S,HD]
__global__ void k_split(const float* __restrict__ t, float* __restrict__ out) {
    int gw   = (blockIdx.x * blockDim.x + threadIdx.x) >> 5;
    int lane = threadIdx.x & 31;
    int bh = gw / Sn, s = gw % Sn;
    int b = bh / Hn, h = bh % Hn;
    const float* src = t + ((size_t)(b * Sn + s)) * Dn + h * HDn;
    float v0 = src[lane], v1 = src[lane + 32];
    float ss = warp_sum(v0 * v0 + v1 * v1);
    float n = sqrtf(fmaxf(ss, EPSf * EPSf));
    float sc = tanhf(n) / n;
    float* dst = out + (size_t)gw * HDn;
    dst[lane] = sc * v0; dst[lane + 32] = sc * v1;
}

// concat: [B,H,S,HD] -> logmap per head * ratio -> gather D -> expmap0 -> [B,S,D]
template<int NT>
__global__ void k_concat(const float* __restrict__ mh, float* __restrict__ out, float ratio) {
    int r = blockIdx.x;
    int b = r / Sn, s = r % Sn;
    __shared__ float row[Dn];
    int warp = threadIdx.x >> 5, lane = threadIdx.x & 31;
#pragma unroll
    for (int hh = 0; hh < Hn / (NT / 32); hh++) {
        int h = warp * (Hn / (NT / 32)) + hh;
        const float* src = mh + ((size_t)((b * Hn + h) * Sn + s)) * HDn;
        float v0 = src[lane], v1 = src[lane + 32];
        float ss = warp_sum(v0 * v0 + v1 * v1);
        float n  = sqrtf(fmaxf(ss, EPSf * EPSf));
        float nc = fminf(fmaxf(n, EPSf), MAXNf);
        float sc = atanh_f(nc) / nc * ratio;
        row[h * HDn + lane]      = sc * v0;
        row[h * HDn + lane + 32] = sc * v1;
    }
    __syncthreads();
    constexpr int P = Dn / NT;
    float vl[P]; float ss = 0.f;
#pragma unroll
    for (int i = 0; i < P; i++) { vl[i] = row[threadIdx.x + i * NT]; ss += vl[i] * vl[i]; }
    ss = block_sum<NT>(ss);
    float n = sqrtf(fmaxf(ss, EPSf * EPSf));
    float es = tanhf(n) / n;
#pragma unroll
    for (int i = 0; i < P; i++) out[(size_t)r * Dn + threadIdx.x + i * NT] = es * vl[i];
}

// ---------------- GEMM: C[M,N] = A[M,K] @ W[N,K]^T + bias ----------------
template<int BM, int BN, int BK, int TM, int TN>
__global__ __launch_bounds__((BM / TM) * (BN / TN))
void k_gemm(const float* __restrict__ A, const float* __restrict__ W,
            const float* __restrict__ bias, float* __restrict__ C,
            int Mi, int Ni, int Ki) {
    constexpr int NT = (BM / TM) * (BN / TN);
    __shared__ float As[BK][BM];
    __shared__ float Bs[BK][BN];
    const int bn = blockIdx.x * BN, bm = blockIdx.y * BM;
    const int tid = threadIdx.x;
    const int tx = tid % (BN / TN), ty = tid / (BN / TN);
    float acc[TM][TN];
#pragma unroll
    for (int i = 0; i < TM; i++)
#pragma unroll
        for (int j = 0; j < TN; j++) acc[i][j] = 0.f;

    for (int k0 = 0; k0 < Ki; k0 += BK) {
        for (int f = tid; f < BM * BK / 4; f += NT) {
            int row = f / (BK / 4), c = (f % (BK / 4)) * 4;
            float4 v = *(const float4*)(A + (size_t)(bm + row) * Ki + k0 + c);
            As[c + 0][row] = v.x; As[c + 1][row] = v.y;
            As[c + 2][row] = v.z; As[c + 3][row] = v.w;
        }
        for (int f = tid; f < BN * BK / 4; f += NT) {
            int row = f / (BK / 4), c = (f % (BK / 4)) * 4;
            float4 v = *(const float4*)(W + (size_t)(bn + row) * Ki + k0 + c);
            Bs[c + 0][row] = v.x; Bs[c + 1][row] = v.y;
            Bs[c + 2][row] = v.z; Bs[c + 3][row] = v.w;
        }
        __syncthreads();
#pragma unroll
        for (int k = 0; k < BK; k++) {
            float a[TM], bb[TN];
#pragma unroll
            for (int i = 0; i < TM; i += 4) {
                float4 v = *(const float4*)&As[k][ty * TM + i];
                a[i] = v.x; a[i + 1] = v.y; a[i + 2] = v.z; a[i + 3] = v.w;
            }
#pragma unroll
            for (int j = 0; j < TN; j += 4) {
                float4 v = *(const float4*)&Bs[k][tx * TN + j];
                bb[j] = v.x; bb[j + 1] = v.y; bb[j + 2] = v.z; bb[j + 3] = v.w;
            }
#pragma unroll
            for (int i = 0; i < TM; i++)
#pragma unroll
                for (int j = 0; j < TN; j++) acc[i][j] += a[i] * bb[j];
        }
        __syncthreads();
    }
    float bv[TN];
#pragma unroll
    for (int j = 0; j < TN; j++) bv[j] = bias[bn + tx * TN + j];
#pragma unroll
    for (int i = 0; i < TM; i++) {
        int r = bm + ty * TM + i;
#pragma unroll
        for (int j = 0; j < TN; j += 4) {
            float4 o;
            o.x = acc[i][j + 0] + bv[j + 0];
            o.y = acc[i][j + 1] + bv[j + 1];
            o.z = acc[i][j + 2] + bv[j + 2];
            o.w = acc[i][j + 3] + bv[j + 3];
            *(float4*)(C + (size_t)r * Ni + bn + tx * TN + j) = o;
        }
    }
}

// ---------------- attention pieces ----------------

// scores tile: 64x64 per block, only lower-triangular tiles, writes tau*(-dist)-gamma
__global__ __launch_bounds__(256)
void k_scores(const float* __restrict__ qh, const float* __restrict__ kh,
              const float* __restrict__ tau, const float* __restrict__ gamma,
              int l, float* __restrict__ wbuf) {
    int it = blockIdx.x, jt = blockIdx.y, bh = blockIdx.z;
    if (jt > it) return;
    __shared__ float Qs[HDn][68];
    __shared__ float Ks[HDn][68];
    __shared__ float q2[64], k2[64];
    int tid = threadIdx.x;
    const float* Q = qh + ((size_t)bh * Sn + it * 64) * HDn;
    const float* K = kh + ((size_t)bh * Sn + jt * 64) * HDn;
    for (int f = tid; f < 1024; f += 256) {
        int row = f >> 4, c = (f & 15) * 4;
        float4 v = *(const float4*)(Q + row * HDn + c);
        Qs[c + 0][row] = v.x; Qs[c + 1][row] = v.y;
        Qs[c + 2][row] = v.z; Qs[c + 3][row] = v.w;
        float4 u = *(const float4*)(K + row * HDn + c);
        Ks[c + 0][row] = u.x; Ks[c + 1][row] = u.y;
        Ks[c + 2][row] = u.z; Ks[c + 3][row] = u.w;
    }
    __syncthreads();
    if (tid < 64) {
        float s = 0.f;
        for (int d = 0; d < HDn; d++) { float a = Qs[d][tid]; s += a * a; }
        q2[tid] = s;
    } else if (tid < 128) {
        int j = tid - 64;
        float s = 0.f;
        for (int d = 0; d < HDn; d++) { float a = Ks[d][j]; s += a * a; }
        k2[j] = s;
    }
    __syncthreads();
    int tx = tid & 15, ty = tid >> 4;
    float acc[4][4] = {};
#pragma unroll 8
    for (int d = 0; d < HDn; d++) {
        float4 av = *(const float4*)&Qs[d][ty * 4];
        float4 bv = *(const float4*)&Ks[d][tx * 4];
        float a[4] = {av.x, av.y, av.z, av.w};
        float b[4] = {bv.x, bv.y, bv.z, bv.w};
#pragma unroll
        for (int i = 0; i < 4; i++)
#pragma unroll
            for (int j = 0; j < 4; j++) acc[i][j] += a[i] * b[j];
    }
    float tv = tau[l], gv = gamma[l];
#pragma unroll
    for (int ii = 0; ii < 4; ii++)
#pragma unroll
        for (int jj = 0; jj < 4; jj++) {
            int i = ty * 4 + ii, j = tx * 4 + jj;
            float d2 = fmaxf(q2[i] + k2[j] - 2.f * acc[ii][jj], 0.f);
            float dn = fmaxf((1.f - q2[i]) * (1.f - k2[j]), EPSf);
            float u  = fmaxf(2.f * d2 / dn, 1.1920929e-7f);
            float dist = log1pf(u + sqrtf(u * (u + 2.f)));
            wbuf[((size_t)bh * Sn + it * 64 + i) * Sn + jt * 64 + j] = -tv * dist - gv;
        }
}

// causal softmax over row prefix [0, i]
template<int NT>
__global__ void k_softmax(float* __restrict__ wbuf) {
    int r = blockIdx.x;           // bh*Sn + i
    int i = r % Sn;
    float* row = wbuf + (size_t)r * Sn;
    int n = i + 1;
    float mx = -1e30f;
    for (int j = threadIdx.x; j < n; j += NT) mx = fmaxf(mx, row[j]);
    mx = block_max<NT>(mx);
    float sum = 0.f;
    for (int j = threadIdx.x; j < n; j += NT) {
        float e = expf(row[j] - mx);
        row[j] = e;
        sum += e;
    }
    sum = block_sum<NT>(sum);
    float inv = 1.f / sum;
    for (int j = threadIdx.x; j < n; j += NT) row[j] *= inv;
}

// lam = 2 / max(1-||v||^2, EPS); lamv = lam*v; lm1 = lam - 1
__global__ void k_lamv(const float* __restrict__ vh, float* __restrict__ lamv,
                       float* __restrict__ lm1) {
    int gw = (blockIdx.x * blockDim.x + threadIdx.x) >> 5;
    int lane = threadIdx.x & 31;
    const float* v = vh + (size_t)gw * HDn;
    float v0 = v[lane], v1 = v[lane + 32];
    float ss = warp_sum(v0 * v0 + v1 * v1);
    float lam = 2.f / fmaxf(1.f - ss, EPSf);
    float* o = lamv + (size_t)gw * HDn;
    o[lane] = lam * v0; o[lane + 32] = lam * v1;
    if (lane == 0) lm1[gw] = lam - 1.f;
}

// num = w @ lamv (causal), den = w @ (lam-1)
__global__ __launch_bounds__(256)
void k_midmm(const float* __restrict__ wbuf, const float* __restrict__ lamv,
             const float* __restrict__ lm1, float* __restrict__ num,
             float* __restrict__ den) {
    int it = blockIdx.x, bh = blockIdx.y;
    __shared__ float Wt[64][68];   // [j][i]
    __shared__ float Lv[64][68];   // [j][d]
    __shared__ float lms[64];
    int tid = threadIdx.x;
    int tx = tid & 15, ty = tid >> 4;
    float acc[4][4] = {};
    float dac[4] = {};
    for (int jt = 0; jt <= it; jt++) {
        for (int f = tid; f < 1024; f += 256) {
            int ii = f >> 4, c = (f & 15) * 4;
            int gi = it * 64 + ii;
            float4 v = *(const float4*)(wbuf + ((size_t)bh * Sn + gi) * Sn + jt * 64 + c);
            int j0 = jt * 64 + c;
            Wt[c + 0][ii] = (j0 + 0 <= gi) ? v.x : 0.f;
            Wt[c + 1][ii] = (j0 + 1 <= gi) ? v.y : 0.f;
            Wt[c + 2][ii] = (j0 + 2 <= gi) ? v.z : 0.f;
            Wt[c + 3][ii] = (j0 + 3 <= gi) ? v.w : 0.f;
            float4 u = *(const float4*)(lamv + ((size_t)bh * Sn + jt * 64 + ii) * HDn + c);
            *(float4*)&Lv[ii][c] = u;
        }
        if (tid < 64) lms[tid] = lm1[(size_t)bh * Sn + jt * 64 + tid];
        __syncthreads();
#pragma unroll 8
        for (int k = 0; k < 64; k++) {
            float4 av = *(const float4*)&Wt[k][ty * 4];
            float4 bv = *(const float4*)&Lv[k][tx * 4];
            float a[4] = {av.x, av.y, av.z, av.w};
            float b[4] = {bv.x, bv.y, bv.z, bv.w};
#pragma unroll
            for (int i = 0; i < 4; i++)
#pragma unroll
                for (int j = 0; j < 4; j++) acc[i][j] += a[i] * b[j];
            if (tx == 0) {
                float lmk = lms[k];
#pragma unroll
                for (int i = 0; i < 4; i++) dac[i] += a[i] * lmk;
            }
        }
        __syncthreads();
    }
#pragma unroll
    for (int ii = 0; ii < 4; ii++)
#pragma unroll
        for (int jj = 0; jj < 4; jj++)
            num[((size_t)bh * Sn + it * 64 + ty * 4 + ii) * HDn + tx * 4 + jj] = acc[ii][jj];
    if (tx == 0)
#pragma unroll
        for (int ii = 0; ii < 4; ii++)
            den[(size_t)bh * Sn + it * 64 + ty * 4 + ii] = dac[ii];
}

// mid = num/max(den,EPS); project(mobius_scalar_mul(0.5, mid))
__global__ void k_midfin(const float* __restrict__ num, const float* __restrict__ den,
                         float* __restrict__ out) {
    int gw = (blockIdx.x * blockDim.x + threadIdx.x) >> 5;
    int lane = threadIdx.x & 31;
    float dn = fmaxf(den[gw], EPSf);
    const float* nr = num + (size_t)gw * HDn;
    float m0 = nr[lane] / dn, m1 = nr[lane + 32] / dn;
    float ss = warp_sum(m0 * m0 + m1 * m1);
    float n  = sqrtf(fmaxf(ss, EPSf * EPSf));
    float nc = fminf(fmaxf(n, EPSf), MAXNf);
    float tt = tanhf(0.5f * atanh_f(nc));
    float s1 = tt / nc;
    float y0 = s1 * m0, y1 = s1 * m1;
    float ny2 = s1 * s1 * ss;
    float ny  = sqrtf(fmaxf(ny2, EPSf * EPSf));
    float s2  = fminf(1.f, MAXNf / ny);
    float* o = out + (size_t)gw * HDn;
    o[lane] = y0 * s2; o[lane + 32] = y1 * s2;
}

// ---------------- host orchestration ----------------
extern "C" void kernel_launch(void* const* d_in, const int* in_sizes, int n_in,
                              void* d_out, int out_size) {
    (void)in_sizes; (void)n_in; (void)out_size;
    const float* x    = (const float*)d_in[0];
    const float* pos  = (const float*)d_in[1];
    const float* ln1w = (const float*)d_in[2];
    const float* ln1b = (const float*)d_in[3];
    const float* ln2w = (const float*)d_in[4];
    const float* ln2b = (const float*)d_in[5];
    const float* Wq   = (const float*)d_in[6];
    const float* bq   = (const float*)d_in[7];
    const float* Wk   = (const float*)d_in[8];
    const float* bk   = (const float*)d_in[9];
    const float* Wv   = (const float*)d_in[10];
    const float* bv   = (const float*)d_in[11];
    const float* Wo   = (const float*)d_in[12];
    const float* bo   = (const float*)d_in[13];
    const float* W1   = (const float*)d_in[14];
    const float* b1   = (const float*)d_in[15];
    const float* W2   = (const float*)d_in[16];
    const float* b2   = (const float*)d_in[17];
    const float* tau  = (const float*)d_in[18];
    const float* gam  = (const float*)d_in[19];
    const float* Wout = (const float*)d_in[20];
    const float* bout = (const float*)d_in[21];
    float* outp = (float*)d_out;

    float *px, *ph, *pp, *pt, *pu, *pq, *pk, *pv, *pw, *plv, *plm, *pn, *pd, *pm;
    cudaGetSymbolAddress((void**)&px,  g_x);
    cudaGetSymbolAddress((void**)&ph,  g_h);
    cudaGetSymbolAddress((void**)&pp,  g_p);
    cudaGetSymbolAddress((void**)&pt,  g_t);
    cudaGetSymbolAddress((void**)&pu,  g_u);
    cudaGetSymbolAddress((void**)&pq,  g_qh);
    cudaGetSymbolAddress((void**)&pk,  g_kh);
    cudaGetSymbolAddress((void**)&pv,  g_vh);
    cudaGetSymbolAddress((void**)&pw,  g_w);
    cudaGetSymbolAddress((void**)&plv, g_lamv);
    cudaGetSymbolAddress((void**)&plm, g_lm1);
    cudaGetSymbolAddress((void**)&pn,  g_num);
    cudaGetSymbolAddress((void**)&pd,  g_den);
    cudaGetSymbolAddress((void**)&pm,  g_mid);

    double betaD  = std::exp(std::lgamma(Dn / 2.0)  + std::lgamma(0.5) - std::lgamma(Dn / 2.0 + 0.5));
    double betaHD = std::exp(std::lgamma(HDn / 2.0) + std::lgamma(0.5) - std::lgamma(HDn / 2.0 + 0.5));
    float ratio_split = (float)(betaHD / betaD);
    float ratio_cat   = (float)(betaD / betaHD);

    dim3 gemmS(Dn / 64, Mn / 64);      // N=512 GEMMs (64x64 tiles)
    dim3 gemmF(FFn / 128, Mn / 128);   // N=2048 GEMM (128x128 tiles)

    // x = mobius_add(x, pos_tab)
    k_mobius_add<128><<<Mn, 128>>>(x, pos, px, Sn);

    for (int l = 0; l < Ln; l++) {
        // ---- attention block ----
        k_pln<128><<<Mn, 128>>>(px, ln1w + l * Dn, ln1b + l * Dn, ph);
        k_logmap<Dn, 128><<<Mn, 128>>>(ph, pt, 1.f);

        // Q
        k_gemm<64, 64, 32, 4, 4><<<gemmS, 256>>>(pt, Wq + (size_t)l * Dn * Dn, bq + l * Dn, pu, Mn, Dn, Dn);
        k_expmap<Dn, 128><<<Mn, 128>>>(pu, pp);
        k_logmap<Dn, 128><<<Mn, 128>>>(pp, pu, ratio_split);
        k_split<<<BHn * Sn / 4, 128>>>(pu, pq);
        // K
        k_gemm<64, 64, 32, 4, 4><<<gemmS, 256>>>(pt, Wk + (size_t)l * Dn * Dn, bk + l * Dn, pu, Mn, Dn, Dn);
        k_expmap<Dn, 128><<<Mn, 128>>>(pu, pp);
        k_logmap<Dn, 128><<<Mn, 128>>>(pp, pu, ratio_split);
        k_split<<<BHn * Sn / 4, 128>>>(pu, pk);
        // V
        k_gemm<64, 64, 32, 4, 4><<<gemmS, 256>>>(pt, Wv + (size_t)l * Dn * Dn, bv + l * Dn, pu, Mn, Dn, Dn);
        k_expmap<Dn, 128><<<Mn, 128>>>(pu, pp);
        k_logmap<Dn, 128><<<Mn, 128>>>(pp, pu, ratio_split);
        k_split<<<BHn * Sn / 4, 128>>>(pu, pv);

        k_scores<<<dim3(Sn / 64, Sn / 64, BHn), 256>>>(pq, pk, tau, gam, l, pw);
        k_softmax<256><<<BHn * Sn, 256>>>(pw);
        k_lamv<<<BHn * Sn / 4, 128>>>(pv, plv, plm);
        k_midmm<<<dim3(Sn / 64, BHn), 256>>>(pw, plv, plm, pn, pd);
        k_midfin<<<BHn * Sn / 4, 128>>>(pn, pd, pm);
        k_concat<128><<<Mn, 128>>>(pm, pp, ratio_cat);

        k_logmap<Dn, 128><<<Mn, 128>>>(pp, pt, 1.f);
        k_gemm<64, 64, 32, 4, 4><<<gemmS, 256>>>(pt, Wo + (size_t)l * Dn * Dn, bo + l * Dn, pu, Mn, Dn, Dn);
        k_expmap<Dn, 128><<<Mn, 128>>>(pu, ph);
        k_mobius_add<128><<<Mn, 128>>>(px, ph, px, Mn);

        // ---- FFN block ----
        k_pln<128><<<Mn, 128>>>(px, ln2w + l * Dn, ln2b + l * Dn, ph);
        k_logmap<Dn, 128><<<Mn, 128>>>(ph, pt, 1.f);
        k_gemm<128, 128, 16, 8, 8><<<gemmF, 256>>>(pt, W1 + (size_t)l * FFn * Dn, b1 + l * FFn, pu, Mn, FFn, Dn);
        k_expmap<FFn, 128><<<Mn, 128>>>(pu, pt);
        k_relu_tan<FFn, 128><<<Mn, 128>>>(pt);
        k_logmap<FFn, 128><<<Mn, 128>>>(pt, pu, 1.f);
        k_gemm<64, 64, 32, 4, 4><<<gemmS, 256>>>(pu, W2 + (size_t)l * Dn * FFn, b2 + l * Dn, ph, Mn, Dn, FFn);
        k_expmap<Dn, 128><<<Mn, 128>>>(ph, pp);
        k_mobius_add<128><<<Mn, 128>>>(px, pp, px, Mn);
    }

    // final plinear
    k_logmap<Dn, 128><<<Mn, 128>>>(px, pt, 1.f);
    k_gemm<64, 64, 32, 4, 4><<<gemmS, 256>>>(pt, Wout, bout, pu, Mn, Dn, Dn);
    k_expmap<Dn, 128><<<Mn, 128>>>(pu, outp);
}

// round 3
// speedup vs baseline: 1.7997x; 1.7997x over previous
#include <cuda_runtime.h>
#include <cuda_bf16.h>
#include <cstdint>
#include <cmath>

// ---------------- problem constants ----------------
constexpr int Bn  = 2;
constexpr int Sn  = 1024;
constexpr int Dn  = 512;
constexpr int Hn  = 8;
constexpr int HDn = 64;
constexpr int FFn = 2048;
constexpr int Ln  = 4;
constexpr int Mn  = Bn * Sn;   // 2048
constexpr int BHn = Bn * Hn;   // 16

#define EPSf   1e-7f
#define MAXNf  (1.0f - 1e-3f)

// ---------------- scratch (device globals; no allocation allowed) ----------------
__device__ float g_x   [Mn * Dn];
__device__ float g_h   [Mn * Dn];
__device__ float g_p   [Mn * Dn];
__device__ float g_t   [Mn * FFn];
__device__ float g_u   [Mn * FFn];
__device__ float g_qh  [Mn * Dn];      // [B,H,S,HD]
__device__ float g_kh  [Mn * Dn];
__device__ float g_vh  [Mn * Dn];
__device__ float g_w   [(size_t)BHn * Sn * Sn];   // 64 MB scores/weights
__device__ float g_lamv[Mn * Dn];
__device__ float g_lm1 [BHn * Sn];
__device__ float g_num [Mn * Dn];
__device__ float g_den [BHn * Sn];
__device__ float g_mid [Mn * Dn];
// bf16 split buffers
__device__ __nv_bfloat16 g_ahi[Mn * FFn];
__device__ __nv_bfloat16 g_alo[Mn * FFn];
__device__ __nv_bfloat16 g_whi[FFn * Dn];
__device__ __nv_bfloat16 g_wlo[FFn * Dn];

// ---------------- PTX helpers (base compute_103 compatible) ----------------
static __device__ __forceinline__ uint32_t smem_u32(const void* p) {
    return (uint32_t)__cvta_generic_to_shared(p);
}
static __device__ __forceinline__ void cp16(uint32_t dst, const void* src) {
    asm volatile("cp.async.cg.shared.global [%0], [%1], 16;" :: "r"(dst), "l"(src));
}
static __device__ __forceinline__ void cp_commit() {
    asm volatile("cp.async.commit_group;" ::: "memory");
}
template<int N>
static __device__ __forceinline__ void cp_wait() {
    asm volatile("cp.async.wait_group %0;" :: "n"(N) : "memory");
}
static __device__ __forceinline__ void ldm4(uint32_t* r, uint32_t addr) {
    asm volatile("ldmatrix.sync.aligned.m8n8.x4.shared.b16 {%0,%1,%2,%3}, [%4];"
                 : "=r"(r[0]), "=r"(r[1]), "=r"(r[2]), "=r"(r[3]) : "r"(addr));
}
static __device__ __forceinline__ void mma16816(float* d, const uint32_t* a, const uint32_t* b) {
    asm volatile("mma.sync.aligned.m16n8k16.row.col.f32.bf16.bf16.f32 "
                 "{%0,%1,%2,%3}, {%4,%5,%6,%7}, {%8,%9}, {%0,%1,%2,%3};"
                 : "+f"(d[0]), "+f"(d[1]), "+f"(d[2]), "+f"(d[3])
                 : "r"(a[0]), "r"(a[1]), "r"(a[2]), "r"(a[3]), "r"(b[0]), "r"(b[1]));
}

// ---------------- reduction helpers ----------------
static __device__ __forceinline__ float atanh_f(float x) {
    return 0.5f * (log1pf(x) - log1pf(-x));
}

template<int NT>
__device__ __forceinline__ float block_sum(float v) {
    __shared__ float sh[NT / 32];
#pragma unroll
    for (int o = 16; o > 0; o >>= 1) v += __shfl_xor_sync(0xffffffffu, v, o);
    int w = threadIdx.x >> 5;
    if ((threadIdx.x & 31) == 0) sh[w] = v;
    __syncthreads();
    float r = sh[0];
#pragma unroll
    for (int i = 1; i < NT / 32; i++) r += sh[i];
    __syncthreads();
    return r;
}

template<int NT>
__device__ __forceinline__ float block_max(float v) {
    __shared__ float sh[NT / 32];
#pragma unroll
    for (int o = 16; o > 0; o >>= 1) v = fmaxf(v, __shfl_xor_sync(0xffffffffu, v, o));
    int w = threadIdx.x >> 5;
    if ((threadIdx.x & 31) == 0) sh[w] = v;
    __syncthreads();
    float r = sh[0];
#pragma unroll
    for (int i = 1; i < NT / 32; i++) r = fmaxf(r, sh[i]);
    __syncthreads();
    return r;
}

__device__ __forceinline__ float warp_sum(float v) {
#pragma unroll
    for (int o = 16; o > 0; o >>= 1) v += __shfl_xor_sync(0xffffffffu, v, o);
    return v;
}

// ---------------- fp32 -> bf16 hi/lo split ----------------
__global__ void k_cvt(const float* __restrict__ x, __nv_bfloat16* __restrict__ hi,
                      __nv_bfloat16* __restrict__ lo, int n4) {
    int i = blockIdx.x * blockDim.x + threadIdx.x;
    if (i >= n4) return;
    float4 v = ((const float4*)x)[i];
    __nv_bfloat16 h0 = __float2bfloat16(v.x);
    __nv_bfloat16 h1 = __float2bfloat16(v.y);
    __nv_bfloat16 h2 = __float2bfloat16(v.z);
    __nv_bfloat16 h3 = __float2bfloat16(v.w);
    __nv_bfloat16 l0 = __float2bfloat16(v.x - __bfloat162float(h0));
    __nv_bfloat16 l1 = __float2bfloat16(v.y - __bfloat162float(h1));
    __nv_bfloat16 l2 = __float2bfloat16(v.z - __bfloat162float(h2));
    __nv_bfloat16 l3 = __float2bfloat16(v.w - __bfloat162float(h3));
    ((__nv_bfloat162*)hi)[2 * i]     = __halves2bfloat162(h0, h1);
    ((__nv_bfloat162*)hi)[2 * i + 1] = __halves2bfloat162(h2, h3);
    ((__nv_bfloat162*)lo)[2 * i]     = __halves2bfloat162(l0, l1);
    ((__nv_bfloat162*)lo)[2 * i + 1] = __halves2bfloat162(l2, l3);
}

// ---------------- HMMA GEMM: C[M,N] = A[M,K] @ W[N,K]^T + bias ----------------
// 3-pass split-bf16: C = Ahi*Bhi + Ahi*Blo + Alo*Bhi (fp32 accum).
// BM=BN=64, BK=64, 128 threads (4 warps, warp tile 32x32), double-buffered cp.async.
constexpr int LDS = 72;                     // 64 + 8 pad: conflict-free ldmatrix
constexpr int GEMM_SMEM = 8 * 64 * LDS * 2; // 73728 B (A hi/lo + B hi/lo, 2 stages)

__global__ void __launch_bounds__(128)
k_gemm_mma(const __nv_bfloat16* __restrict__ Ahi, const __nv_bfloat16* __restrict__ Alo,
           const __nv_bfloat16* __restrict__ Whi, const __nv_bfloat16* __restrict__ Wlo,
           const float* __restrict__ bias, float* __restrict__ C, int Ni, int Ki)
{
    extern __shared__ __nv_bfloat16 sm[];
    const int tid = threadIdx.x, wid = tid >> 5, lane = tid & 31;
    const int bm = blockIdx.y * 64, bn = blockIdx.x * 64;
    const int wm = (wid >> 1) * 32, wn = (wid & 1) * 32;
    const uint32_t sbase = smem_u32(sm);
    const int Boff = 4 * 64 * LDS;   // elements

    float acc[2][4][4];
#pragma unroll
    for (int a = 0; a < 2; a++)
#pragma unroll
        for (int b = 0; b < 4; b++)
#pragma unroll
            for (int c = 0; c < 4; c++) acc[a][b][c] = 0.f;

    const int NC = Ki >> 6;

    auto load_stage = [&](int c) {
        const int s = c & 1;
        const size_t k0 = (size_t)c * 64;
        for (int i = tid; i < 512; i += 128) {
            int row = i >> 3, seg = i & 7;
            const size_t gA = (size_t)(bm + row) * Ki + k0 + seg * 8;
            const size_t gB = (size_t)(bn + row) * Ki + k0 + seg * 8;
            uint32_t off = (uint32_t)(((s * 2 + 0) * 64 + row) * LDS + seg * 8) * 2;
            cp16(sbase + off, Ahi + gA);
            uint32_t off1 = (uint32_t)(((s * 2 + 1) * 64 + row) * LDS + seg * 8) * 2;
            cp16(sbase + off1, Alo + gA);
            uint32_t off2 = (uint32_t)((Boff + ((s * 2 + 0) * 64 + row) * LDS + seg * 8)) * 2;
            cp16(sbase + off2, Whi + gB);
            uint32_t off3 = (uint32_t)((Boff + ((s * 2 + 1) * 64 + row) * LDS + seg * 8)) * 2;
            cp16(sbase + off3, Wlo + gB);
        }
        cp_commit();
    };

    load_stage(0);
    for (int c = 0; c < NC; c++) {
        const int s = c & 1;
        if (c + 1 < NC) { load_stage(c + 1); cp_wait<1>(); }
        else            { cp_wait<0>(); }
        __syncthreads();

#pragma unroll
        for (int kk = 0; kk < 4; kk++) {
            uint32_t ah[2][4], al[2][4];
#pragma unroll
            for (int mt = 0; mt < 2; mt++) {
                uint32_t rA = ((s * 2 + 0) * 64 + wm + mt * 16 + (lane & 15));
                ldm4(ah[mt], sbase + (rA * LDS + kk * 16) * 2 + (lane >> 4) * 16);
                uint32_t rAl = ((s * 2 + 1) * 64 + wm + mt * 16 + (lane & 15));
                ldm4(al[mt], sbase + (rAl * LDS + kk * 16) * 2 + (lane >> 4) * 16);
            }
            uint32_t bh[4][2], bl[4][2];
#pragma unroll
            for (int nt2 = 0; nt2 < 2; nt2++) {
                uint32_t rB = (uint32_t)(Boff + ((s * 2 + 0) * 64 + wn + nt2 * 16 + (lane & 15)) * LDS);
                uint32_t t[4];
                ldm4(t, sbase + (rB + kk * 16) * 2 + (lane >> 4) * 16);
                bh[nt2 * 2][0] = t[0]; bh[nt2 * 2 + 1][0] = t[1];
                bh[nt2 * 2][1] = t[2]; bh[nt2 * 2 + 1][1] = t[3];
                uint32_t rBl = (uint32_t)(Boff + ((s * 2 + 1) * 64 + wn + nt2 * 16 + (lane & 15)) * LDS);
                ldm4(t, sbase + (rBl + kk * 16) * 2 + (lane >> 4) * 16);
                bl[nt2 * 2][0] = t[0]; bl[nt2 * 2 + 1][0] = t[1];
                bl[nt2 * 2][1] = t[2]; bl[nt2 * 2 + 1][1] = t[3];
            }
#pragma unroll
            for (int mt = 0; mt < 2; mt++)
#pragma unroll
                for (int nt = 0; nt < 4; nt++) {
                    mma16816(acc[mt][nt], ah[mt], bh[nt]);
                    mma16816(acc[mt][nt], ah[mt], bl[nt]);
                    mma16816(acc[mt][nt], al[mt], bh[nt]);
                }
        }
        __syncthreads();
    }

    // epilogue: direct float2 stores (+bias)
#pragma unroll
    for (int mt = 0; mt < 2; mt++) {
        int r0 = bm + wm + mt * 16 + (lane >> 2);
#pragma unroll
        for (int nt = 0; nt < 4; nt++) {
            int col = bn + wn + nt * 8 + 2 * (lane & 3);
            float b0 = bias[col], b1 = bias[col + 1];
            float2 v0 = make_float2(acc[mt][nt][0] + b0, acc[mt][nt][1] + b1);
            float2 v1 = make_float2(acc[mt][nt][2] + b0, acc[mt][nt][3] + b1);
            *(float2*)(C + (size_t)r0 * Ni + col) = v0;
            *(float2*)(C + (size_t)(r0 + 8) * Ni + col) = v1;
        }
    }
}

// ---------------- row-wise hyperbolic kernels ----------------

template<int NT>
__global__ void k_mobius_add(const float* __restrict__ x, const float* __restrict__ y,
                             float* __restrict__ out, int ymod) {
    constexpr int P = Dn / NT;
    int r = blockIdx.x;
    const float* xr = x + (size_t)r * Dn;
    const float* yr = y + (size_t)(r % ymod) * Dn;
    float xl[P], yl[P];
    float x2 = 0.f, y2 = 0.f, xy = 0.f;
#pragma unroll
    for (int i = 0; i < P; i++) {
        int j = threadIdx.x + i * NT;
        xl[i] = xr[j]; yl[i] = yr[j];
        x2 += xl[i] * xl[i]; y2 += yl[i] * yl[i]; xy += xl[i] * yl[i];
    }
    x2 = block_sum<NT>(x2);
    y2 = block_sum<NT>(y2);
    xy = block_sum<NT>(xy);
    float den = fmaxf(1.f + 2.f * xy + x2 * y2, EPSf);
    float ca = (1.f + 2.f * xy + y2) / den;
    float cb = (1.f - x2) / den;
    float zl[P]; float n2 = 0.f;
#pragma unroll
    for (int i = 0; i < P; i++) { zl[i] = ca * xl[i] + cb * yl[i]; n2 += zl[i] * zl[i]; }
    n2 = block_sum<NT>(n2);
    float n = sqrtf(fmaxf(n2, EPSf * EPSf));
    float sc = fminf(1.f, MAXNf / n);
#pragma unroll
    for (int i = 0; i < P; i++) out[(size_t)r * Dn + threadIdx.x + i * NT] = zl[i] * sc;
}

template<int NT>
__global__ void k_pln(const float* __restrict__ x, const float* __restrict__ w,
                      const float* __restrict__ b, float* __restrict__ out) {
    constexpr int P = Dn / NT;
    int r = blockIdx.x;
    const float* xr = x + (size_t)r * Dn;
    float xl[P]; float ss = 0.f;
#pragma unroll
    for (int i = 0; i < P; i++) { xl[i] = xr[threadIdx.x + i * NT]; ss += xl[i] * xl[i]; }
    ss = block_sum<NT>(ss);
    float n  = sqrtf(fmaxf(ss, EPSf * EPSf));
    float nc = fminf(fmaxf(n, EPSf), MAXNf);
    float ls = atanh_f(nc) / nc;
    float tl[P]; float st = 0.f;
#pragma unroll
    for (int i = 0; i < P; i++) { tl[i] = ls * xl[i]; st += tl[i]; }
    st = block_sum<NT>(st);
    float mu = st / (float)Dn;
    float sv = 0.f;
#pragma unroll
    for (int i = 0; i < P; i++) { float d = tl[i] - mu; sv += d * d; }
    sv = block_sum<NT>(sv);
    float inv = rsqrtf(sv / (float)Dn + 1e-5f);
    float yl[P]; float sy = 0.f;
#pragma unroll
    for (int i = 0; i < P; i++) {
        int j = threadIdx.x + i * NT;
        yl[i] = (tl[i] - mu) * inv * w[j] + b[j];
        sy += yl[i] * yl[i];
    }
    sy = block_sum<NT>(sy);
    float ny = sqrtf(fmaxf(sy, EPSf * EPSf));
    float es = tanhf(ny) / ny;
#pragma unroll
    for (int i = 0; i < P; i++) out[(size_t)r * Dn + threadIdx.x + i * NT] = es * yl[i];
}

template<int DIM, int NT>
__global__ void k_logmap(const float* __restrict__ x, float* __restrict__ out, float scale) {
    constexpr int P = DIM / NT;
    int r = blockIdx.x;
    const float* xr = x + (size_t)r * DIM;
    float xl[P]; float ss = 0.f;
#pragma unroll
    for (int i = 0; i < P; i++) { xl[i] = xr[threadIdx.x + i * NT]; ss += xl[i] * xl[i]; }
    ss = block_sum<NT>(ss);
    float n  = sqrtf(fmaxf(ss, EPSf * EPSf));
    float nc = fminf(fmaxf(n, EPSf), MAXNf);
    float s  = atanh_f(nc) / nc * scale;
#pragma unroll
    for (int i = 0; i < P; i++) out[(size_t)r * DIM + threadIdx.x + i * NT] = s * xl[i];
}

template<int DIM, int NT>
__global__ void k_expmap(const float* __restrict__ x, float* __restrict__ out) {
    constexpr int P = DIM / NT;
    int r = blockIdx.x;
    const float* xr = x + (size_t)r * DIM;
    float xl[P]; float ss = 0.f;
#pragma unroll
    for (int i = 0; i < P; i++) { xl[i] = xr[threadIdx.x + i * NT]; ss += xl[i] * xl[i]; }
    ss = block_sum<NT>(ss);
    float n = sqrtf(fmaxf(ss, EPSf * EPSf));
    float s = tanhf(n) / n;
#pragma unroll
    for (int i = 0; i < P; i++) out[(size_t)r * DIM + threadIdx.x + i * NT] = s * xl[i];
}

template<int DIM, int NT>
__global__ void k_relu_tan(float* __restrict__ x) {
    constexpr int P = DIM / NT;
    int r = blockIdx.x;
    float* xr = x + (size_t)r * DIM;
    float xl[P]; float ss = 0.f;
#pragma unroll
    for (int i = 0; i < P; i++) { xl[i] = xr[threadIdx.x + i * NT]; ss += xl[i] * xl[i]; }
    ss = block_sum<NT>(ss);
    float n  = sqrtf(fmaxf(ss, EPSf * EPSf));
    float nc = fminf(fmaxf(n, EPSf), MAXNf);
    float ls = atanh_f(nc) / nc;
    float tl[P]; float st = 0.f;
#pragma unroll
    for (int i = 0; i < P; i++) { tl[i] = fmaxf(ls * xl[i], 0.f); st += tl[i] * tl[i]; }
    st = block_sum<NT>(st);
    float n2 = sqrtf(fmaxf(st, EPSf * EPSf));
    float es = tanhf(n2) / n2;
#pragma unroll
    for (int i = 0; i < P; i++) xr[threadIdx.x + i * NT] = es * tl[i];
}

__global__ void k_split(const float* __restrict__ t, float* __restrict__ out) {
    int gw   = (blockIdx.x * blockDim.x + threadIdx.x) >> 5;
    int lane = threadIdx.x & 31;
    int bh = gw / Sn, s = gw % Sn;
    int b = bh / Hn, h = bh % Hn;
    const float* src = t + ((size_t)(b * Sn + s)) * Dn + h * HDn;
    float v0 = src[lane], v1 = src[lane + 32];
    float ss = warp_sum(v0 * v0 + v1 * v1);
    float n = sqrtf(fmaxf(ss, EPSf * EPSf));
    float sc = tanhf(n) / n;
    float* dst = out + (size_t)gw * HDn;
    dst[lane] = sc * v0; dst[lane + 32] = sc * v1;
}

template<int NT>
__global__ void k_concat(const float* __restrict__ mh, float* __restrict__ out, float ratio) {
    int r = blockIdx.x;
    int b = r / Sn, s = r % Sn;
    __shared__ float row[Dn];
    int warp = threadIdx.x >> 5, lane = threadIdx.x & 31;
#pragma unroll
    for (int hh = 0; hh < Hn / (NT / 32); hh++) {
        int h = warp * (Hn / (NT / 32)) + hh;
        const float* src = mh + ((size_t)((b * Hn + h) * Sn + s)) * HDn;
        float v0 = src[lane], v1 = src[lane + 32];
        float ss = warp_sum(v0 * v0 + v1 * v1);
        float n  = sqrtf(fmaxf(ss, EPSf * EPSf));
        float nc = fminf(fmaxf(n, EPSf), MAXNf);
        float sc = atanh_f(nc) / nc * ratio;
        row[h * HDn + lane]      = sc * v0;
        row[h * HDn + lane + 32] = sc * v1;
    }
    __syncthreads();
    constexpr int P = Dn / NT;
    float vl[P]; float ss = 0.f;
#pragma unroll
    for (int i = 0; i < P; i++) { vl[i] = row[threadIdx.x + i * NT]; ss += vl[i] * vl[i]; }
    ss = block_sum<NT>(ss);
    float n = sqrtf(fmaxf(ss, EPSf * EPSf));
    float es = tanhf(n) / n;
#pragma unroll
    for (int i = 0; i < P; i++) out[(size_t)r * Dn + threadIdx.x + i * NT] = es * vl[i];
}

// ---------------- attention pieces ----------------

__global__ __launch_bounds__(256)
void k_scores(const float* __restrict__ qh, const float* __restrict__ kh,
              const float* __restrict__ tau, const float* __restrict__ gamma,
              int l, float* __restrict__ wbuf) {
    int it = blockIdx.x, jt = blockIdx.y, bh = blockIdx.z;
    if (jt > it) return;
    __shared__ float Qs[HDn][68];
    __shared__ float Ks[HDn][68];
    __shared__ float q2[64], k2[64];
    int tid = threadIdx.x;
    const float* Q = qh + ((size_t)bh * Sn + it * 64) * HDn;
    const float* K = kh + ((size_t)bh * Sn + jt * 64) * HDn;
    for (int f = tid; f < 1024; f += 256) {
        int row = f >> 4, c = (f & 15) * 4;
        float4 v = *(const float4*)(Q + row * HDn + c);
        Qs[c + 0][row] = v.x; Qs[c + 1][row] = v.y;
        Qs[c + 2][row] = v.z; Qs[c + 3][row] = v.w;
        float4 u = *(const float4*)(K + row * HDn + c);
        Ks[c + 0][row] = u.x; Ks[c + 1][row] = u.y;
        Ks[c + 2][row] = u.z; Ks[c + 3][row] = u.w;
    }
    __syncthreads();
    if (tid < 64) {
        float s = 0.f;
        for (int d = 0; d < HDn; d++) { float a = Qs[d][tid]; s += a * a; }
        q2[tid] = s;
    } else if (tid < 128) {
        int j = tid - 64;
        float s = 0.f;
        for (int d = 0; d < HDn; d++) { float a = Ks[d][j]; s += a * a; }
        k2[j] = s;
    }
    __syncthreads();
    int tx = tid & 15, ty = tid >> 4;
    float acc[4][4] = {};
#pragma unroll 8
    for (int d = 0; d < HDn; d++) {
        float4 av = *(const float4*)&Qs[d][ty * 4];
        float4 bv = *(const float4*)&Ks[d][tx * 4];
        float a[4] = {av.x, av.y, av.z, av.w};
        float b[4] = {bv.x, bv.y, bv.z, bv.w};
#pragma unroll
        for (int i = 0; i < 4; i++)
#pragma unroll
            for (int j = 0; j < 4; j++) acc[i][j] += a[i] * b[j];
    }
    float tv = tau[l], gv = gamma[l];
#pragma unroll
    for (int ii = 0; ii < 4; ii++)
#pragma unroll
        for (int jj = 0; jj < 4; jj++) {
            int i = ty * 4 + ii, j = tx * 4 + jj;
            float d2 = fmaxf(q2[i] + k2[j] - 2.f * acc[ii][jj], 0.f);
            float dn = fmaxf((1.f - q2[i]) * (1.f - k2[j]), EPSf);
            float u  = fmaxf(2.f * d2 / dn, 1.1920929e-7f);
            float dist = log1pf(u + sqrtf(u * (u + 2.f)));
            wbuf[((size_t)bh * Sn + it * 64 + i) * Sn + jt * 64 + j] = -tv * dist - gv;
        }
}

template<int NT>
__global__ void k_softmax(float* __restrict__ wbuf) {
    int r = blockIdx.x;
    int i = r % Sn;
    float* row = wbuf + (size_t)r * Sn;
    int n = i + 1;
    float mx = -1e30f;
    for (int j = threadIdx.x; j < n; j += NT) mx = fmaxf(mx, row[j]);
    mx = block_max<NT>(mx);
    float sum = 0.f;
    for (int j = threadIdx.x; j < n; j += NT) {
        float e = expf(row[j] - mx);
        row[j] = e;
        sum += e;
    }
    sum = block_sum<NT>(sum);
    float inv = 1.f / sum;
    for (int j = threadIdx.x; j < n; j += NT) row[j] *= inv;
}

__global__ void k_lamv(const float* __restrict__ vh, float* __restrict__ lamv,
                       float* __restrict__ lm1) {
    int gw = (blockIdx.x * blockDim.x + threadIdx.x) >> 5;
    int lane = threadIdx.x & 31;
    const float* v = vh + (size_t)gw * HDn;
    float v0 = v[lane], v1 = v[lane + 32];
    float ss = warp_sum(v0 * v0 + v1 * v1);
    float lam = 2.f / fmaxf(1.f - ss, EPSf);
    float* o = lamv + (size_t)gw * HDn;
    o[lane] = lam * v0; o[lane + 32] = lam * v1;
    if (lane == 0) lm1[gw] = lam - 1.f;
}

__global__ __launch_bounds__(256)
void k_midmm(const float* __restrict__ wbuf, const float* __restrict__ lamv,
             const float* __restrict__ lm1, float* __restrict__ num,
             float* __restrict__ den) {
    int it = blockIdx.x, bh = blockIdx.y;
    __shared__ float Wt[64][68];
    __shared__ float Lv[64][68];
    __shared__ float lms[64];
    int tid = threadIdx.x;
    int tx = tid & 15, ty = tid >> 4;
    float acc[4][4] = {};
    float dac[4] = {};
    for (int jt = 0; jt <= it; jt++) {
        for (int f = tid; f < 1024; f += 256) {
            int ii = f >> 4, c = (f & 15) * 4;
            int gi = it * 64 + ii;
            float4 v = *(const float4*)(wbuf + ((size_t)bh * Sn + gi) * Sn + jt * 64 + c);
            int j0 = jt * 64 + c;
            Wt[c + 0][ii] = (j0 + 0 <= gi) ? v.x : 0.f;
            Wt[c + 1][ii] = (j0 + 1 <= gi) ? v.y : 0.f;
            Wt[c + 2][ii] = (j0 + 2 <= gi) ? v.z : 0.f;
            Wt[c + 3][ii] = (j0 + 3 <= gi) ? v.w : 0.f;
            float4 u = *(const float4*)(lamv + ((size_t)bh * Sn + jt * 64 + ii) * HDn + c);
            *(float4*)&Lv[ii][c] = u;
        }
        if (tid < 64) lms[tid] = lm1[(size_t)bh * Sn + jt * 64 + tid];
        __syncthreads();
#pragma unroll 8
        for (int k = 0; k < 64; k++) {
            float4 av = *(const float4*)&Wt[k][ty * 4];
            float4 bv = *(const float4*)&Lv[k][tx * 4];
            float a[4] = {av.x, av.y, av.z, av.w};
            float b[4] = {bv.x, bv.y, bv.z, bv.w};
#pragma unroll
            for (int i = 0; i < 4; i++)
#pragma unroll
                for (int j = 0; j < 4; j++) acc[i][j] += a[i] * b[j];
            if (tx == 0) {
                float lmk = lms[k];
#pragma unroll
                for (int i = 0; i < 4; i++) dac[i] += a[i] * lmk;
            }
        }
        __syncthreads();
    }
#pragma unroll
    for (int ii = 0; ii < 4; ii++)
#pragma unroll
        for (int jj = 0; jj < 4; jj++)
            num[((size_t)bh * Sn + it * 64 + ty * 4 + ii) * HDn + tx * 4 + jj] = acc[ii][jj];
    if (tx == 0)
#pragma unroll
        for (int ii = 0; ii < 4; ii++)
            den[(size_t)bh * Sn + it * 64 + ty * 4 + ii] = dac[ii];
}

__global__ void k_midfin(const float* __restrict__ num, const float* __restrict__ den,
                         float* __restrict__ out) {
    int gw = (blockIdx.x * blockDim.x + threadIdx.x) >> 5;
    int lane = threadIdx.x & 31;
    float dn = fmaxf(den[gw], EPSf);
    const float* nr = num + (size_t)gw * HDn;
    float m0 = nr[lane] / dn, m1 = nr[lane + 32] / dn;
    float ss = warp_sum(m0 * m0 + m1 * m1);
    float n  = sqrtf(fmaxf(ss, EPSf * EPSf));
    float nc = fminf(fmaxf(n, EPSf), MAXNf);
    float tt = tanhf(0.5f * atanh_f(nc));
    float s1 = tt / nc;
    float y0 = s1 * m0, y1 = s1 * m1;
    float ny2 = s1 * s1 * ss;
    float ny  = sqrtf(fmaxf(ny2, EPSf * EPSf));
    float s2  = fminf(1.f, MAXNf / ny);
    float* o = out + (size_t)gw * HDn;
    o[lane] = y0 * s2; o[lane + 32] = y1 * s2;
}

// ---------------- host orchestration ----------------
extern "C" void kernel_launch(void* const* d_in, const int* in_sizes, int n_in,
                              void* d_out, int out_size) {
    (void)in_sizes; (void)n_in; (void)out_size;
    const float* x    = (const float*)d_in[0];
    const float* pos  = (const float*)d_in[1];
    const float* ln1w = (const float*)d_in[2];
    const float* ln1b = (const float*)d_in[3];
    const float* ln2w = (const float*)d_in[4];
    const float* ln2b = (const float*)d_in[5];
    const float* Wq   = (const float*)d_in[6];
    const float* bq   = (const float*)d_in[7];
    const float* Wk   = (const float*)d_in[8];
    const float* bk   = (const float*)d_in[9];
    const float* Wv   = (const float*)d_in[10];
    const float* bv   = (const float*)d_in[11];
    const float* Wo   = (const float*)d_in[12];
    const float* bo   = (const float*)d_in[13];
    const float* W1   = (const float*)d_in[14];
    const float* b1   = (const float*)d_in[15];
    const float* W2   = (const float*)d_in[16];
    const float* b2   = (const float*)d_in[17];
    const float* tau  = (const float*)d_in[18];
    const float* gam  = (const float*)d_in[19];
    const float* Wout = (const float*)d_in[20];
    const float* bout = (const float*)d_in[21];
    float* outp = (float*)d_out;

    float *px, *ph, *pp, *pt, *pu, *pq, *pk, *pv, *pw, *plv, *plm, *pn, *pd, *pm;
    __nv_bfloat16 *pahi, *palo, *pwhi, *pwlo;
    cudaGetSymbolAddress((void**)&px,  g_x);
    cudaGetSymbolAddress((void**)&ph,  g_h);
    cudaGetSymbolAddress((void**)&pp,  g_p);
    cudaGetSymbolAddress((void**)&pt,  g_t);
    cudaGetSymbolAddress((void**)&pu,  g_u);
    cudaGetSymbolAddress((void**)&pq,  g_qh);
    cudaGetSymbolAddress((void**)&pk,  g_kh);
    cudaGetSymbolAddress((void**)&pv,  g_vh);
    cudaGetSymbolAddress((void**)&pw,  g_w);
    cudaGetSymbolAddress((void**)&plv, g_lamv);
    cudaGetSymbolAddress((void**)&plm, g_lm1);
    cudaGetSymbolAddress((void**)&pn,  g_num);
    cudaGetSymbolAddress((void**)&pd,  g_den);
    cudaGetSymbolAddress((void**)&pm,  g_mid);
    cudaGetSymbolAddress((void**)&pahi, g_ahi);
    cudaGetSymbolAddress((void**)&palo, g_alo);
    cudaGetSymbolAddress((void**)&pwhi, g_whi);
    cudaGetSymbolAddress((void**)&pwlo, g_wlo);

    cudaFuncSetAttribute((const void*)k_gemm_mma,
                         cudaFuncAttributeMaxDynamicSharedMemorySize, GEMM_SMEM);

    double betaD  = std::exp(std::lgamma(Dn / 2.0)  + std::lgamma(0.5) - std::lgamma(Dn / 2.0 + 0.5));
    double betaHD = std::exp(std::lgamma(HDn / 2.0) + std::lgamma(0.5) - std::lgamma(HDn / 2.0 + 0.5));
    float ratio_split = (float)(betaHD / betaD);
    float ratio_cat   = (float)(betaD / betaHD);

    auto cvtA = [&](const float* src, int n) {
        k_cvt<<<(n / 4 + 255) / 256, 256>>>(src, pahi, palo, n / 4);
    };
    auto cvtW = [&](const float* src, int n) {
        k_cvt<<<(n / 4 + 255) / 256, 256>>>(src, pwhi, pwlo, n / 4);
    };
    auto gemm = [&](const float* bias, float* Cout, int Ni, int Ki) {
        k_gemm_mma<<<dim3(Ni / 64, Mn / 64), 128, GEMM_SMEM>>>(
            pahi, palo, pwhi, pwlo, bias, Cout, Ni, Ki);
    };

    // x = mobius_add(x, pos_tab)
    k_mobius_add<128><<<Mn, 128>>>(x, pos, px, Sn);

    for (int l = 0; l < Ln; l++) {
        // ---- attention block ----
        k_pln<128><<<Mn, 128>>>(px, ln1w + l * Dn, ln1b + l * Dn, ph);
        k_logmap<Dn, 128><<<Mn, 128>>>(ph, pt, 1.f);
        cvtA(pt, Mn * Dn);

        // Q
        cvtW(Wq + (size_t)l * Dn * Dn, Dn * Dn);
        gemm(bq + l * Dn, pu, Dn, Dn);
        k_expmap<Dn, 128><<<Mn, 128>>>(pu, pp);
        k_logmap<Dn, 128><<<Mn, 128>>>(pp, pu, ratio_split);
        k_split<<<BHn * Sn / 4, 128>>>(pu, pq);
        // K
        cvtW(Wk + (size_t)l * Dn * Dn, Dn * Dn);
        gemm(bk + l * Dn, pu, Dn, Dn);
        k_expmap<Dn, 128><<<Mn, 128>>>(pu, pp);
        k_logmap<Dn, 128><<<Mn, 128>>>(pp, pu, ratio_split);
        k_split<<<BHn * Sn / 4, 128>>>(pu, pk);
        // V
        cvtW(Wv + (size_t)l * Dn * Dn, Dn * Dn);
        gemm(bv + l * Dn, pu, Dn, Dn);
        k_expmap<Dn, 128><<<Mn, 128>>>(pu, pp);
        k_logmap<Dn, 128><<<Mn, 128>>>(pp, pu, ratio_split);
        k_split<<<BHn * Sn / 4, 128>>>(pu, pv);

        k_scores<<<dim3(Sn / 64, Sn / 64, BHn), 256>>>(pq, pk, tau, gam, l, pw);
        k_softmax<256><<<BHn * Sn, 256>>>(pw);
        k_lamv<<<BHn * Sn / 4, 128>>>(pv, plv, plm);
        k_midmm<<<dim3(Sn / 64, BHn), 256>>>(pw, plv, plm, pn, pd);
        k_midfin<<<BHn * Sn / 4, 128>>>(pn, pd, pm);
        k_concat<128><<<Mn, 128>>>(pm, pp, ratio_cat);

        k_logmap<Dn, 128><<<Mn, 128>>>(pp, pt, 1.f);
        cvtA(pt, Mn * Dn);
        cvtW(Wo + (size_t)l * Dn * Dn, Dn * Dn);
        gemm(bo + l * Dn, pu, Dn, Dn);
        k_expmap<Dn, 128><<<Mn, 128>>>(pu, ph);
        k_mobius_add<128><<<Mn, 128>>>(px, ph, px, Mn);

        // ---- FFN block ----
        k_pln<128><<<Mn, 128>>>(px, ln2w + l * Dn, ln2b + l * Dn, ph);
        k_logmap<Dn, 128><<<Mn, 128>>>(ph, pt, 1.f);
        cvtA(pt, Mn * Dn);
        cvtW(W1 + (size_t)l * FFn * Dn, FFn * Dn);
        gemm(b1 + l * FFn, pu, FFn, Dn);
        k_expmap<FFn, 128><<<Mn, 128>>>(pu, pt);
        k_relu_tan<FFn, 128><<<Mn, 128>>>(pt);
        k_logmap<FFn, 128><<<Mn, 128>>>(pt, pu, 1.f);
        cvtA(pu, Mn * FFn);
        cvtW(W2 + (size_t)l * Dn * FFn, Dn * FFn);
        gemm(b2 + l * Dn, ph, Dn, FFn);
        k_expmap<Dn, 128><<<Mn, 128>>>(ph, pp);
        k_mobius_add<128><<<Mn, 128>>>(px, pp, px, Mn);
    }

    // final plinear
    k_logmap<Dn, 128><<<Mn, 128>>>(px, pt, 1.f);
    cvtA(pt, Mn * Dn);
    cvtW(Wout, Dn * Dn);
    gemm(bout, pu, Dn, Dn);
    k_expmap<Dn, 128><<<Mn, 128>>>(pu, outp);
}

// round 4
// speedup vs baseline: 1.9463x; 1.0815x over previous
#include <cuda_runtime.h>
#include <cuda_bf16.h>
#include <cstdint>
#include <cmath>

// ---------------- problem constants ----------------
constexpr int Bn  = 2;
constexpr int Sn  = 1024;
constexpr int Dn  = 512;
constexpr int Hn  = 8;
constexpr int HDn = 64;
constexpr int FFn = 2048;
constexpr int Ln  = 4;
constexpr int Mn  = Bn * Sn;   // 2048
constexpr int BHn = Bn * Hn;   // 16
constexpr long long WLL = 4LL * Dn * Dn + 2LL * FFn * Dn;  // per-layer weight elems

#define EPSf   1e-7f
#define MAXNf  (1.0f - 1e-3f)

// ---------------- scratch ----------------
__device__ float g_x   [Mn * Dn];
__device__ float g_u   [Mn * FFn];
__device__ float g_qh  [Mn * Dn];
__device__ float g_kh  [Mn * Dn];
__device__ float g_lamv[Mn * Dn];
__device__ float g_lm1 [BHn * Sn];
__device__ float g_mid [Mn * Dn];
__device__ __nv_bfloat16 g_ahi[Mn * FFn];
__device__ __nv_bfloat16 g_alo[Mn * FFn];
__device__ __nv_bfloat16 g_Whi[4 * WLL + Dn * Dn];
__device__ __nv_bfloat16 g_Wlo[4 * WLL + Dn * Dn];

// ---------------- PTX helpers ----------------
static __device__ __forceinline__ uint32_t smem_u32(const void* p) {
    return (uint32_t)__cvta_generic_to_shared(p);
}
static __device__ __forceinline__ void cp16(uint32_t dst, const void* src) {
    asm volatile("cp.async.cg.shared.global [%0], [%1], 16;" :: "r"(dst), "l"(src));
}
static __device__ __forceinline__ void cp_commit() {
    asm volatile("cp.async.commit_group;" ::: "memory");
}
template<int N>
static __device__ __forceinline__ void cp_wait() {
    asm volatile("cp.async.wait_group %0;" :: "n"(N) : "memory");
}
static __device__ __forceinline__ void ldm4(uint32_t* r, uint32_t addr) {
    asm volatile("ldmatrix.sync.aligned.m8n8.x4.shared.b16 {%0,%1,%2,%3}, [%4];"
                 : "=r"(r[0]), "=r"(r[1]), "=r"(r[2]), "=r"(r[3]) : "r"(addr));
}
static __device__ __forceinline__ void mma16816(float* d, const uint32_t* a, const uint32_t* b) {
    asm volatile("mma.sync.aligned.m16n8k16.row.col.f32.bf16.bf16.f32 "
                 "{%0,%1,%2,%3}, {%4,%5,%6,%7}, {%8,%9}, {%0,%1,%2,%3};"
                 : "+f"(d[0]), "+f"(d[1]), "+f"(d[2]), "+f"(d[3])
                 : "r"(a[0]), "r"(a[1]), "r"(a[2]), "r"(a[3]), "r"(b[0]), "r"(b[1]));
}

// ---------------- math helpers ----------------
static __device__ __forceinline__ float atanh_f(float x) {
    return 0.5f * (log1pf(x) - log1pf(-x));
}
template<int NT>
__device__ __forceinline__ float block_sum(float v) {
    __shared__ float sh[NT / 32];
#pragma unroll
    for (int o = 16; o > 0; o >>= 1) v += __shfl_xor_sync(0xffffffffu, v, o);
    int w = threadIdx.x >> 5;
    if ((threadIdx.x & 31) == 0) sh[w] = v;
    __syncthreads();
    float r = sh[0];
#pragma unroll
    for (int i = 1; i < NT / 32; i++) r += sh[i];
    __syncthreads();
    return r;
}
__device__ __forceinline__ float warp_sum(float v) {
#pragma unroll
    for (int o = 16; o > 0; o >>= 1) v += __shfl_xor_sync(0xffffffffu, v, o);
    return v;
}
__device__ __forceinline__ float group16_sum(float v) {
#pragma unroll
    for (int o = 8; o > 0; o >>= 1) v += __shfl_xor_sync(0xffffffffu, v, o);
    return v;
}
static __device__ __forceinline__ void store_split4(__nv_bfloat16* hi, __nv_bfloat16* lo,
                                                    size_t idx, float4 v) {
    __nv_bfloat16 h0 = __float2bfloat16(v.x), h1 = __float2bfloat16(v.y);
    __nv_bfloat16 h2 = __float2bfloat16(v.z), h3 = __float2bfloat16(v.w);
    __nv_bfloat16 l0 = __float2bfloat16(v.x - __bfloat162float(h0));
    __nv_bfloat16 l1 = __float2bfloat16(v.y - __bfloat162float(h1));
    __nv_bfloat16 l2 = __float2bfloat16(v.z - __bfloat162float(h2));
    __nv_bfloat16 l3 = __float2bfloat16(v.w - __bfloat162float(h3));
    ((__nv_bfloat162*)(hi + idx))[0] = __halves2bfloat162(h0, h1);
    ((__nv_bfloat162*)(hi + idx))[1] = __halves2bfloat162(h2, h3);
    ((__nv_bfloat162*)(lo + idx))[0] = __halves2bfloat162(l0, l1);
    ((__nv_bfloat162*)(lo + idx))[1] = __halves2bfloat162(l2, l3);
}

// ---------------- weight conversion (all tensors, one launch) ----------------
struct WCvtArgs {
    const float* src[25];
    long long    off[25];
    int          n4[25];
};
__global__ void k_wcvt(WCvtArgs a, __nv_bfloat16* __restrict__ hi, __nv_bfloat16* __restrict__ lo) {
    int t = blockIdx.y;
    int i = blockIdx.x * blockDim.x + threadIdx.x;
    if (i >= a.n4[t]) return;
    float4 v = ((const float4*)a.src[t])[i];
    store_split4(hi, lo, (size_t)a.off[t] + 4 * (size_t)i, v);
}

// ---------------- HMMA GEMM (3-pass split-bf16) ----------------
constexpr int LDS = 72;
constexpr int GEMM_SMEM = 8 * 64 * LDS * 2;

__global__ void __launch_bounds__(128)
k_gemm_mma(const __nv_bfloat16* __restrict__ Ahi, const __nv_bfloat16* __restrict__ Alo,
           const __nv_bfloat16* __restrict__ Whi, const __nv_bfloat16* __restrict__ Wlo,
           const float* __restrict__ bias, float* __restrict__ C, int Ni, int Ki)
{
    extern __shared__ __nv_bfloat16 sm[];
    const int tid = threadIdx.x, wid = tid >> 5, lane = tid & 31;
    const int bm = blockIdx.y * 64, bn = blockIdx.x * 64;
    const int wm = (wid >> 1) * 32, wn = (wid & 1) * 32;
    const uint32_t sbase = smem_u32(sm);
    const int Boff = 4 * 64 * LDS;

    float acc[2][4][4];
#pragma unroll
    for (int a = 0; a < 2; a++)
#pragma unroll
        for (int b = 0; b < 4; b++)
#pragma unroll
            for (int c = 0; c < 4; c++) acc[a][b][c] = 0.f;

    const int NC = Ki >> 6;

    auto load_stage = [&](int c) {
        const int s = c & 1;
        const size_t k0 = (size_t)c * 64;
        for (int i = tid; i < 512; i += 128) {
            int row = i >> 3, seg = i & 7;
            const size_t gA = (size_t)(bm + row) * Ki + k0 + seg * 8;
            const size_t gB = (size_t)(bn + row) * Ki + k0 + seg * 8;
            uint32_t off = (uint32_t)(((s * 2 + 0) * 64 + row) * LDS + seg * 8) * 2;
            cp16(sbase + off, Ahi + gA);
            uint32_t off1 = (uint32_t)(((s * 2 + 1) * 64 + row) * LDS + seg * 8) * 2;
            cp16(sbase + off1, Alo + gA);
            uint32_t off2 = (uint32_t)((Boff + ((s * 2 + 0) * 64 + row) * LDS + seg * 8)) * 2;
            cp16(sbase + off2, Whi + gB);
            uint32_t off3 = (uint32_t)((Boff + ((s * 2 + 1) * 64 + row) * LDS + seg * 8)) * 2;
            cp16(sbase + off3, Wlo + gB);
        }
        cp_commit();
    };

    load_stage(0);
    for (int c = 0; c < NC; c++) {
        const int s = c & 1;
        if (c + 1 < NC) { load_stage(c + 1); cp_wait<1>(); }
        else            { cp_wait<0>(); }
        __syncthreads();

#pragma unroll
        for (int kk = 0; kk < 4; kk++) {
            uint32_t ah[2][4], al[2][4];
#pragma unroll
            for (int mt = 0; mt < 2; mt++) {
                uint32_t rA = ((s * 2 + 0) * 64 + wm + mt * 16 + (lane & 15));
                ldm4(ah[mt], sbase + (rA * LDS + kk * 16) * 2 + (lane >> 4) * 16);
                uint32_t rAl = ((s * 2 + 1) * 64 + wm + mt * 16 + (lane & 15));
                ldm4(al[mt], sbase + (rAl * LDS + kk * 16) * 2 + (lane >> 4) * 16);
            }
            uint32_t bh[4][2], bl[4][2];
#pragma unroll
            for (int nt2 = 0; nt2 < 2; nt2++) {
                uint32_t rB = (uint32_t)(Boff + ((s * 2 + 0) * 64 + wn + nt2 * 16 + (lane & 15)) * LDS);
                uint32_t t[4];
                ldm4(t, sbase + (rB + kk * 16) * 2 + (lane >> 4) * 16);
                bh[nt2 * 2][0] = t[0]; bh[nt2 * 2 + 1][0] = t[1];
                bh[nt2 * 2][1] = t[2]; bh[nt2 * 2 + 1][1] = t[3];
                uint32_t rBl = (uint32_t)(Boff + ((s * 2 + 1) * 64 + wn + nt2 * 16 + (lane & 15)) * LDS);
                ldm4(t, sbase + (rBl + kk * 16) * 2 + (lane >> 4) * 16);
                bl[nt2 * 2][0] = t[0]; bl[nt2 * 2 + 1][0] = t[1];
                bl[nt2 * 2][1] = t[2]; bl[nt2 * 2 + 1][1] = t[3];
            }
#pragma unroll
            for (int mt = 0; mt < 2; mt++)
#pragma unroll
                for (int nt = 0; nt < 4; nt++) {
                    mma16816(acc[mt][nt], ah[mt], bh[nt]);
                    mma16816(acc[mt][nt], ah[mt], bl[nt]);
                    mma16816(acc[mt][nt], al[mt], bh[nt]);
                }
        }
        __syncthreads();
    }

#pragma unroll
    for (int mt = 0; mt < 2; mt++) {
        int r0 = bm + wm + mt * 16 + (lane >> 2);
#pragma unroll
        for (int nt = 0; nt < 4; nt++) {
            int col = bn + wn + nt * 8 + 2 * (lane & 3);
            float b0 = bias[col], b1 = bias[col + 1];
            float2 v0 = make_float2(acc[mt][nt][0] + b0, acc[mt][nt][1] + b1);
            float2 v1 = make_float2(acc[mt][nt][2] + b0, acc[mt][nt][3] + b1);
            *(float2*)(C + (size_t)r0 * Ni + col) = v0;
            *(float2*)(C + (size_t)(r0 + 8) * Ni + col) = v1;
        }
    }
}

// ---------------- fused elementwise kernels ----------------

// project(mobius_add(x_row, y_row)) -> out (float)
template<int NT>
__global__ void k_mobius_add(const float* __restrict__ x, const float* __restrict__ y,
                             float* __restrict__ out, int ymod) {
    constexpr int P = Dn / NT;
    int r = blockIdx.x;
    const float* xr = x + (size_t)r * Dn;
    const float* yr = y + (size_t)(r % ymod) * Dn;
    float xl[P], yl[P];
    float x2 = 0.f, y2 = 0.f, xy = 0.f;
#pragma unroll
    for (int i = 0; i < P; i++) {
        int j = threadIdx.x + i * NT;
        xl[i] = xr[j]; yl[i] = yr[j];
        x2 += xl[i] * xl[i]; y2 += yl[i] * yl[i]; xy += xl[i] * yl[i];
    }
    x2 = block_sum<NT>(x2);
    y2 = block_sum<NT>(y2);
    xy = block_sum<NT>(xy);
    float den = fmaxf(1.f + 2.f * xy + x2 * y2, EPSf);
    float ca = (1.f + 2.f * xy + y2) / den;
    float cb = (1.f - x2) / den;
    float zl[P]; float n2 = 0.f;
#pragma unroll
    for (int i = 0; i < P; i++) { zl[i] = ca * xl[i] + cb * yl[i]; n2 += zl[i] * zl[i]; }
    n2 = block_sum<NT>(n2);
    float n = sqrtf(fmaxf(n2, EPSf * EPSf));
    float sc = fminf(1.f, MAXNf / n);
#pragma unroll
    for (int i = 0; i < P; i++) out[(size_t)r * Dn + threadIdx.x + i * NT] = zl[i] * sc;
}

// pln -> logmap0 -> bf16 hi/lo  (attn/ffn pre-GEMM input)
__global__ void __launch_bounds__(128)
k_pln2bf(const float* __restrict__ x, const float* __restrict__ w, const float* __restrict__ b,
         __nv_bfloat16* __restrict__ hi, __nv_bfloat16* __restrict__ lo) {
    int r = blockIdx.x, tid = threadIdx.x;
    const float* xr = x + (size_t)r * Dn;
    float4 xv = *(const float4*)(xr + tid * 4);
    float ss = xv.x * xv.x + xv.y * xv.y + xv.z * xv.z + xv.w * xv.w;
    ss = block_sum<128>(ss);
    float n  = sqrtf(fmaxf(ss, EPSf * EPSf));
    float nc = fminf(fmaxf(n, EPSf), MAXNf);
    float ls = atanh_f(nc) / nc;
    float4 tl = make_float4(ls * xv.x, ls * xv.y, ls * xv.z, ls * xv.w);
    float st = tl.x + tl.y + tl.z + tl.w;
    st = block_sum<128>(st);
    float mu = st / (float)Dn;
    float d0 = tl.x - mu, d1 = tl.y - mu, d2 = tl.z - mu, d3 = tl.w - mu;
    float sv = d0 * d0 + d1 * d1 + d2 * d2 + d3 * d3;
    sv = block_sum<128>(sv);
    float inv = rsqrtf(sv / (float)Dn + 1e-5f);
    float4 wv = *(const float4*)(w + tid * 4);
    float4 bv = *(const float4*)(b + tid * 4);
    float4 yv = make_float4(d0 * inv * wv.x + bv.x, d1 * inv * wv.y + bv.y,
                            d2 * inv * wv.z + bv.z, d3 * inv * wv.w + bv.w);
    float sy = yv.x * yv.x + yv.y * yv.y + yv.z * yv.z + yv.w * yv.w;
    sy = block_sum<128>(sy);
    float ny = sqrtf(fmaxf(sy, EPSf * EPSf));
    float es = tanhf(ny) / ny;          // expmap scale
    float tb = tanhf(ny);               // ball norm
    float cb = fminf(fmaxf(tb, EPSf), MAXNf);
    float s2 = atanh_f(cb) / cb;        // logmap scale
    float sc = es * s2;
    store_split4(hi, lo, (size_t)r * Dn + tid * 4,
                 make_float4(sc * yv.x, sc * yv.y, sc * yv.z, sc * yv.w));
}

// GEMM-out -> expmap0 -> logmap0*ratio -> per-head expmap0 -> [B,H,S,HD]
// For V: also emit lamv (lam*v) and lm1 (lam-1) instead of vh.
template<bool ISV>
__global__ void __launch_bounds__(128)
k_post_qkv(const float* __restrict__ u, float* __restrict__ out,
           float* __restrict__ lm1, float ratio) {
    int r = blockIdx.x, tid = threadIdx.x;
    int b = r / Sn, s = r % Sn;
    float4 uv = *(const float4*)(u + (size_t)r * Dn + tid * 4);
    float ss = uv.x * uv.x + uv.y * uv.y + uv.z * uv.z + uv.w * uv.w;
    float bs = block_sum<128>(ss);
    float n  = sqrtf(fmaxf(bs, EPSf * EPSf));
    float s1 = tanhf(n) / n;
    float t  = tanhf(n);
    float c  = fminf(fmaxf(t, EPSf), MAXNf);
    float s2 = atanh_f(c) / c;
    float sc = s1 * s2 * ratio;
    float4 th = make_float4(sc * uv.x, sc * uv.y, sc * uv.z, sc * uv.w);
    // per-head: head h = tid/16, 16 threads each
    float hs = sc * sc * ss;
    hs = group16_sum(hs);
    float nh = sqrtf(fmaxf(hs, EPSf * EPSf));
    float es = tanhf(nh) / nh;
    int h = tid >> 4;
    size_t dst = ((size_t)(b * Hn + h) * Sn + s) * HDn + (tid & 15) * 4;
    if (!ISV) {
        *(float4*)(out + dst) = make_float4(es * th.x, es * th.y, es * th.z, es * th.w);
    } else {
        float vsq = es * es * hs;   // ||v||^2
        float lam = 2.f / fmaxf(1.f - vsq, EPSf);
        float ls2 = lam * es;
        *(float4*)(out + dst) = make_float4(ls2 * th.x, ls2 * th.y, ls2 * th.z, ls2 * th.w);
        if ((tid & 15) == 0) lm1[(size_t)(b * Hn + h) * Sn + s] = lam - 1.f;
    }
}

// fused attention: scores + softmax(no-max) + gyromidpoint + scalar-mul/project
__global__ void __launch_bounds__(256)
k_attn(const float* __restrict__ qh, const float* __restrict__ kh,
       const float* __restrict__ lamv, const float* __restrict__ lm1,
       const float* __restrict__ tau, const float* __restrict__ gam, int l,
       float* __restrict__ mid) {
    int it = blockIdx.x, bh = blockIdx.y;
    extern __shared__ float sma[];
    float* Qs  = sma;                 // [64][68] Qs[d*68+i]
    float* Ks  = Qs + 64 * 68;        // [64][68] Ks[d*68+j]
    float* Ps  = Ks + 64 * 68;        // [64][68] P[i*68+j]
    float* Lv  = Ps + 64 * 68;        // [64][68] Lv[j*68+d]
    float* q2  = Lv + 64 * 68;
    float* k2  = q2 + 64;
    float* lms = k2 + 64;
    int tid = threadIdx.x, tx = tid & 15, ty = tid >> 4;

    const float* Q = qh + ((size_t)bh * Sn + it * 64) * HDn;
    for (int f = tid; f < 1024; f += 256) {
        int row = f >> 4, c = (f & 15) * 4;
        float4 v = *(const float4*)(Q + row * HDn + c);
        Qs[(c + 0) * 68 + row] = v.x; Qs[(c + 1) * 68 + row] = v.y;
        Qs[(c + 2) * 68 + row] = v.z; Qs[(c + 3) * 68 + row] = v.w;
    }
    __syncthreads();
    if (tid < 64) {
        float s = 0.f;
        for (int d = 0; d < HDn; d++) { float a = Qs[d * 68 + tid]; s += a * a; }
        q2[tid] = s;
    }
    float tv = tau[l], gv = gam[l];
    float acc[4][4] = {};
    float dac[4] = {};
    float ssum[4] = {};

    for (int jt = 0; jt <= it; jt++) {
        __syncthreads();   // prev PV done (Ps/Lv/lms free); q2 visible at jt=0
        const float* K  = kh   + ((size_t)bh * Sn + jt * 64) * HDn;
        const float* Lg = lamv + ((size_t)bh * Sn + jt * 64) * HDn;
        for (int f = tid; f < 1024; f += 256) {
            int row = f >> 4, c = (f & 15) * 4;
            float4 u = *(const float4*)(K + row * HDn + c);
            Ks[(c + 0) * 68 + row] = u.x; Ks[(c + 1) * 68 + row] = u.y;
            Ks[(c + 2) * 68 + row] = u.z; Ks[(c + 3) * 68 + row] = u.w;
            float4 w = *(const float4*)(Lg + row * HDn + c);
            *(float4*)&Lv[row * 68 + c] = w;
        }
        if (tid < 64) lms[tid] = lm1[(size_t)bh * Sn + jt * 64 + tid];
        __syncthreads();
        if (tid < 64) {
            float s = 0.f;
            for (int d = 0; d < HDn; d++) { float a = Ks[d * 68 + tid]; s += a * a; }
            k2[tid] = s;
        }
        __syncthreads();

        float sacc[4][4] = {};
#pragma unroll 8
        for (int d = 0; d < HDn; d++) {
            float4 av = *(const float4*)&Qs[d * 68 + ty * 4];
            float4 bv = *(const float4*)&Ks[d * 68 + tx * 4];
            float a[4] = {av.x, av.y, av.z, av.w};
            float b[4] = {bv.x, bv.y, bv.z, bv.w};
#pragma unroll
            for (int i = 0; i < 4; i++)
#pragma unroll
                for (int j = 0; j < 4; j++) sacc[i][j] += a[i] * b[j];
        }
        bool diag = (jt == it);
#pragma unroll
        for (int ii = 0; ii < 4; ii++) {
            int i = ty * 4 + ii;
            float qq = q2[i];
#pragma unroll
            for (int jj = 0; jj < 4; jj++) {
                int j = tx * 4 + jj;
                float e;
                if (diag && j > i) e = 0.f;
                else {
                    float kk = k2[j];
                    float d2 = fmaxf(qq + kk - 2.f * sacc[ii][jj], 0.f);
                    float dn = fmaxf((1.f - qq) * (1.f - kk), EPSf);
                    float uu = fmaxf(2.f * d2 / dn, 1.1920929e-7f);
                    float dist = log1pf(uu + sqrtf(uu * (uu + 2.f)));
                    e = expf(-tv * dist - gv);
                }
                Ps[i * 68 + j] = e;
                ssum[ii] += e;
            }
        }
        __syncthreads();
#pragma unroll 4
        for (int j = 0; j < 64; j++) {
            float a0 = Ps[(ty * 4 + 0) * 68 + j];
            float a1 = Ps[(ty * 4 + 1) * 68 + j];
            float a2 = Ps[(ty * 4 + 2) * 68 + j];
            float a3 = Ps[(ty * 4 + 3) * 68 + j];
            float4 lv = *(const float4*)&Lv[j * 68 + tx * 4];
            acc[0][0] += a0 * lv.x; acc[0][1] += a0 * lv.y; acc[0][2] += a0 * lv.z; acc[0][3] += a0 * lv.w;
            acc[1][0] += a1 * lv.x; acc[1][1] += a1 * lv.y; acc[1][2] += a1 * lv.z; acc[1][3] += a1 * lv.w;
            acc[2][0] += a2 * lv.x; acc[2][1] += a2 * lv.y; acc[2][2] += a2 * lv.z; acc[2][3] += a2 * lv.w;
            acc[3][0] += a3 * lv.x; acc[3][1] += a3 * lv.y; acc[3][2] += a3 * lv.z; acc[3][3] += a3 * lv.w;
            float lm = lms[j];
            dac[0] += a0 * lm; dac[1] += a1 * lm; dac[2] += a2 * lm; dac[3] += a3 * lm;
        }
    }

    // epilogue: mid = num/max(den, EPS*sum); mobius_scalar_mul(0.5) + project
#pragma unroll
    for (int ii = 0; ii < 4; ii++) {
        float rs = ssum[ii];
#pragma unroll
        for (int o = 8; o > 0; o >>= 1) rs += __shfl_xor_sync(0xffffffffu, rs, o);
        float dn = fmaxf(dac[ii], EPSf * rs);
        float inv = 1.f / dn;
        float m0 = acc[ii][0] * inv, m1 = acc[ii][1] * inv;
        float m2 = acc[ii][2] * inv, m3 = acc[ii][3] * inv;
        float ss2 = m0 * m0 + m1 * m1 + m2 * m2 + m3 * m3;
#pragma unroll
        for (int o = 8; o > 0; o >>= 1) ss2 += __shfl_xor_sync(0xffffffffu, ss2, o);
        float n  = sqrtf(fmaxf(ss2, EPSf * EPSf));
        float nc = fminf(fmaxf(n, EPSf), MAXNf);
        float tt = tanhf(0.5f * atanh_f(nc));
        float s1 = tt / nc;
        float ny = sqrtf(fmaxf(s1 * s1 * ss2, EPSf * EPSf));
        float s2 = fminf(1.f, MAXNf / ny);
        float sc = s1 * s2;
        size_t dst = ((size_t)bh * Sn + it * 64 + ty * 4 + ii) * HDn + tx * 4;
        *(float4*)(mid + dst) = make_float4(m0 * sc, m1 * sc, m2 * sc, m3 * sc);
    }
}

// concat heads -> expmap0 -> logmap0 -> bf16 hi/lo
__global__ void __launch_bounds__(128)
k_concat2bf(const float* __restrict__ mh, __nv_bfloat16* __restrict__ hi,
            __nv_bfloat16* __restrict__ lo, float ratio) {
    int r = blockIdx.x, tid = threadIdx.x;
    int b = r / Sn, s = r % Sn;
    __shared__ float row[Dn];
    int warp = tid >> 5, lane = tid & 31;
#pragma unroll
    for (int hh = 0; hh < 2; hh++) {
        int h = warp * 2 + hh;
        const float* src = mh + ((size_t)((b * Hn + h) * Sn + s)) * HDn;
        float v0 = src[lane], v1 = src[lane + 32];
        float ss = warp_sum(v0 * v0 + v1 * v1);
        float n  = sqrtf(fmaxf(ss, EPSf * EPSf));
        float nc = fminf(fmaxf(n, EPSf), MAXNf);
        float sc = atanh_f(nc) / nc * ratio;
        row[h * HDn + lane]      = sc * v0;
        row[h * HDn + lane + 32] = sc * v1;
    }
    __syncthreads();
    float4 vl = *(const float4*)&row[tid * 4];
    float ss = vl.x * vl.x + vl.y * vl.y + vl.z * vl.z + vl.w * vl.w;
    ss = block_sum<128>(ss);
    float n  = sqrtf(fmaxf(ss, EPSf * EPSf));
    float es = tanhf(n) / n;
    float tb = tanhf(n);
    float cb = fminf(fmaxf(tb, EPSf), MAXNf);
    float s2 = atanh_f(cb) / cb;
    float sc = es * s2;
    store_split4(hi, lo, (size_t)r * Dn + tid * 4,
                 make_float4(sc * vl.x, sc * vl.y, sc * vl.z, sc * vl.w));
}

// x = project(mobius_add(x, expmap0(g)))
__global__ void __launch_bounds__(128)
k_exp_madd(const float* __restrict__ g, float* __restrict__ x) {
    int r = blockIdx.x, tid = threadIdx.x;
    float4 gv = *(const float4*)(g + (size_t)r * Dn + tid * 4);
    float4 xv = *(const float4*)(x + (size_t)r * Dn + tid * 4);
    float lg = gv.x * gv.x + gv.y * gv.y + gv.z * gv.z + gv.w * gv.w;
    float lx = xv.x * xv.x + xv.y * xv.y + xv.z * xv.z + xv.w * xv.w;
    float lxg = xv.x * gv.x + xv.y * gv.y + xv.z * gv.z + xv.w * gv.w;
    float g2 = block_sum<128>(lg);
    float x2 = block_sum<128>(lx);
    float xg = block_sum<128>(lxg);
    float ng = sqrtf(fmaxf(g2, EPSf * EPSf));
    float s  = tanhf(ng) / ng;
    float y2 = s * s * g2;
    float xy = s * xg;
    float den = fmaxf(1.f + 2.f * xy + x2 * y2, EPSf);
    float ca = (1.f + 2.f * xy + y2) / den;
    float cb = (1.f - x2) / den * s;
    float4 zv = make_float4(ca * xv.x + cb * gv.x, ca * xv.y + cb * gv.y,
                            ca * xv.z + cb * gv.z, ca * xv.w + cb * gv.w);
    float n2 = zv.x * zv.x + zv.y * zv.y + zv.z * zv.z + zv.w * zv.w;
    n2 = block_sum<128>(n2);
    float n = sqrtf(fmaxf(n2, EPSf * EPSf));
    float sc = fminf(1.f, MAXNf / n);
    *(float4*)(x + (size_t)r * Dn + tid * 4) =
        make_float4(sc * zv.x, sc * zv.y, sc * zv.z, sc * zv.w);
}

// FFN mid: expmap0 -> relu in tangent -> expmap0 -> logmap0 -> bf16 hi/lo (FF dim)
__global__ void __launch_bounds__(256)
k_ffnmid2bf(const float* __restrict__ u, __nv_bfloat16* __restrict__ hi,
            __nv_bfloat16* __restrict__ lo) {
    int r = blockIdx.x, tid = threadIdx.x;
    const float* ur = u + (size_t)r * FFn;
    float4 u0 = *(const float4*)(ur + tid * 4);
    float4 u1 = *(const float4*)(ur + 1024 + tid * 4);
    float ss = u0.x * u0.x + u0.y * u0.y + u0.z * u0.z + u0.w * u0.w
             + u1.x * u1.x + u1.y * u1.y + u1.z * u1.z + u1.w * u1.w;
    ss = block_sum<256>(ss);
    float n0 = sqrtf(fmaxf(ss, EPSf * EPSf));
    float t0 = tanhf(n0);
    float s1 = t0 / n0;
    float c0 = fminf(fmaxf(t0, EPSf), MAXNf);
    float a0 = atanh_f(c0) / c0;
    float w  = a0 * s1;
    float4 r0 = make_float4(fmaxf(w * u0.x, 0.f), fmaxf(w * u0.y, 0.f),
                            fmaxf(w * u0.z, 0.f), fmaxf(w * u0.w, 0.f));
    float4 r1 = make_float4(fmaxf(w * u1.x, 0.f), fmaxf(w * u1.y, 0.f),
                            fmaxf(w * u1.z, 0.f), fmaxf(w * u1.w, 0.f));
    float st = r0.x * r0.x + r0.y * r0.y + r0.z * r0.z + r0.w * r0.w
             + r1.x * r1.x + r1.y * r1.y + r1.z * r1.z + r1.w * r1.w;
    st = block_sum<256>(st);
    float n1 = sqrtf(fmaxf(st, EPSf * EPSf));
    float e1 = tanhf(n1) / n1;
    float t1 = tanhf(n1);
    float c1 = fminf(fmaxf(t1, EPSf), MAXNf);
    float a1 = atanh_f(c1) / c1;
    float sc = a1 * e1;
    store_split4(hi, lo, (size_t)r * FFn + tid * 4,
                 make_float4(sc * r0.x, sc * r0.y, sc * r0.z, sc * r0.w));
    store_split4(hi, lo, (size_t)r * FFn + 1024 + tid * 4,
                 make_float4(sc * r1.x, sc * r1.y, sc * r1.z, sc * r1.w));
}

// logmap0 -> bf16 hi/lo (final head input)
__global__ void __launch_bounds__(128)
k_log2bf(const float* __restrict__ x, __nv_bfloat16* __restrict__ hi,
         __nv_bfloat16* __restrict__ lo) {
    int r = blockIdx.x, tid = threadIdx.x;
    float4 xv = *(const float4*)(x + (size_t)r * Dn + tid * 4);
    float ss = xv.x * xv.x + xv.y * xv.y + xv.z * xv.z + xv.w * xv.w;
    ss = block_sum<128>(ss);
    float n  = sqrtf(fmaxf(ss, EPSf * EPSf));
    float nc = fminf(fmaxf(n, EPSf), MAXNf);
    float s  = atanh_f(nc) / nc;
    store_split4(hi, lo, (size_t)r * Dn + tid * 4,
                 make_float4(s * xv.x, s * xv.y, s * xv.z, s * xv.w));
}

// expmap0 (final output, float)
__global__ void __launch_bounds__(128)
k_expmap_out(const float* __restrict__ x, float* __restrict__ out) {
    int r = blockIdx.x, tid = threadIdx.x;
    float4 xv = *(const float4*)(x + (size_t)r * Dn + tid * 4);
    float ss = xv.x * xv.x + xv.y * xv.y + xv.z * xv.z + xv.w * xv.w;
    ss = block_sum<128>(ss);
    float n = sqrtf(fmaxf(ss, EPSf * EPSf));
    float s = tanhf(n) / n;
    *(float4*)(out + (size_t)r * Dn + tid * 4) =
        make_float4(s * xv.x, s * xv.y, s * xv.z, s * xv.w);
}

// ---------------- host orchestration ----------------
extern "C" void kernel_launch(void* const* d_in, const int* in_sizes, int n_in,
                              void* d_out, int out_size) {
    (void)in_sizes; (void)n_in; (void)out_size;
    const float* x    = (const float*)d_in[0];
    const float* pos  = (const float*)d_in[1];
    const float* ln1w = (const float*)d_in[2];
    const float* ln1b = (const float*)d_in[3];
    const float* ln2w = (const float*)d_in[4];
    const float* ln2b = (const float*)d_in[5];
    const float* Wq   = (const float*)d_in[6];
    const float* bq   = (const float*)d_in[7];
    const float* Wk   = (const float*)d_in[8];
    const float* bk   = (const float*)d_in[9];
    const float* Wv   = (const float*)d_in[10];
    const float* bv   = (const float*)d_in[11];
    const float* Wo   = (const float*)d_in[12];
    const float* bo   = (const float*)d_in[13];
    const float* W1   = (const float*)d_in[14];
    const float* b1   = (const float*)d_in[15];
    const float* W2   = (const float*)d_in[16];
    const float* b2   = (const float*)d_in[17];
    const float* tau  = (const float*)d_in[18];
    const float* gam  = (const float*)d_in[19];
    const float* Wout = (const float*)d_in[20];
    const float* bout = (const float*)d_in[21];
    float* outp = (float*)d_out;

    float *px, *pu, *pq, *pk, *plv, *plm, *pm;
    __nv_bfloat16 *pahi, *palo, *pwhi, *pwlo;
    cudaGetSymbolAddress((void**)&px,  g_x);
    cudaGetSymbolAddress((void**)&pu,  g_u);
    cudaGetSymbolAddress((void**)&pq,  g_qh);
    cudaGetSymbolAddress((void**)&pk,  g_kh);
    cudaGetSymbolAddress((void**)&plv, g_lamv);
    cudaGetSymbolAddress((void**)&plm, g_lm1);
    cudaGetSymbolAddress((void**)&pm,  g_mid);
    cudaGetSymbolAddress((void**)&pahi, g_ahi);
    cudaGetSymbolAddress((void**)&palo, g_alo);
    cudaGetSymbolAddress((void**)&pwhi, g_Whi);
    cudaGetSymbolAddress((void**)&pwlo, g_Wlo);

    cudaFuncSetAttribute((const void*)k_gemm_mma,
                         cudaFuncAttributeMaxDynamicSharedMemorySize, GEMM_SMEM);
    constexpr int ATTN_SMEM = (4 * 64 * 68 + 3 * 64) * 4;
    cudaFuncSetAttribute((const void*)k_attn,
                         cudaFuncAttributeMaxDynamicSharedMemorySize, ATTN_SMEM);

    double betaD  = std::exp(std::lgamma(Dn / 2.0)  + std::lgamma(0.5) - std::lgamma(Dn / 2.0 + 0.5));
    double betaHD = std::exp(std::lgamma(HDn / 2.0) + std::lgamma(0.5) - std::lgamma(HDn / 2.0 + 0.5));
    float ratio_split = (float)(betaHD / betaD);
    float ratio_cat   = (float)(betaD / betaHD);

    // ---- convert all weights once ----
    constexpr int DD = Dn * Dn, FD = FFn * Dn;
    WCvtArgs wa;
    int idx = 0;
    auto add = [&](const float* s, long long off, int n) {
        wa.src[idx] = s; wa.off[idx] = off; wa.n4[idx] = n / 4; idx++;
    };
    for (int l = 0; l < Ln; l++) {
        long long base = l * WLL;
        add(Wq + (size_t)l * DD, base,              DD);
        add(Wk + (size_t)l * DD, base + DD,         DD);
        add(Wv + (size_t)l * DD, base + 2 * DD,     DD);
        add(Wo + (size_t)l * DD, base + 3 * DD,     DD);
        add(W1 + (size_t)l * FD, base + 4 * DD,     FD);
        add(W2 + (size_t)l * FD, base + 4 * DD + FD, FD);
    }
    add(Wout, 4 * WLL, DD);
    k_wcvt<<<dim3(1024, 25), 256>>>(wa, pwhi, pwlo);

    auto gemm = [&](long long woff, const float* bias, float* Cout, int Ni, int Ki) {
        k_gemm_mma<<<dim3(Ni / 64, Mn / 64), 128, GEMM_SMEM>>>(
            pahi, palo, pwhi + woff, pwlo + woff, bias, Cout, Ni, Ki);
    };

    k_mobius_add<128><<<Mn, 128>>>(x, pos, px, Sn);

    for (int l = 0; l < Ln; l++) {
        long long base = l * WLL;
        // ---- attention ----
        k_pln2bf<<<Mn, 128>>>(px, ln1w + l * Dn, ln1b + l * Dn, pahi, palo);
        gemm(base,          bq + l * Dn, pu, Dn, Dn);
        k_post_qkv<false><<<Mn, 128>>>(pu, pq, nullptr, ratio_split);
        gemm(base + DD,     bk + l * Dn, pu, Dn, Dn);
        k_post_qkv<false><<<Mn, 128>>>(pu, pk, nullptr, ratio_split);
        gemm(base + 2 * DD, bv + l * Dn, pu, Dn, Dn);
        k_post_qkv<true><<<Mn, 128>>>(pu, plv, plm, ratio_split);

        k_attn<<<dim3(Sn / 64, BHn), 256, ATTN_SMEM>>>(pq, pk, plv, plm, tau, gam, l, pm);

        k_concat2bf<<<Mn, 128>>>(pm, pahi, palo, ratio_cat);
        gemm(base + 3 * DD, bo + l * Dn, pu, Dn, Dn);
        k_exp_madd<<<Mn, 128>>>(pu, px);

        // ---- FFN ----
        k_pln2bf<<<Mn, 128>>>(px, ln2w + l * Dn, ln2b + l * Dn, pahi, palo);
        gemm(base + 4 * DD, b1 + l * FFn, pu, FFn, Dn);
        k_ffnmid2bf<<<Mn, 256>>>(pu, pahi, palo);
        gemm(base + 4 * DD + FD, b2 + l * Dn, pu, Dn, FFn);
        k_exp_madd<<<Mn, 128>>>(pu, px);
    }

    // ---- head ----
    k_log2bf<<<Mn, 128>>>(px, pahi, palo);
    gemm(4 * WLL, bout, pu, Dn, Dn);
    k_expmap_out<<<Mn, 128>>>(pu, outp);
}

// round 5
// speedup vs baseline: 1.9817x; 1.0182x over previous
#include <cuda_runtime.h>
#include <cuda_bf16.h>
#include <cstdint>
#include <cmath>

// ---------------- problem constants ----------------
constexpr int Bn  = 2;
constexpr int Sn  = 1024;
constexpr int Dn  = 512;
constexpr int Hn  = 8;
constexpr int HDn = 64;
constexpr int FFn = 2048;
constexpr int Ln  = 4;
constexpr int Mn  = Bn * Sn;   // 2048
constexpr int BHn = Bn * Hn;   // 16
constexpr long long WLL = 4LL * Dn * Dn + 2LL * FFn * Dn;  // per-layer weight elems

#define EPSf   1e-7f
#define MAXNf  (1.0f - 1e-3f)

// ---------------- scratch ----------------
__device__ float g_x   [Mn * Dn];
__device__ float g_u   [Mn * FFn];
__device__ float g_qh  [Mn * Dn];
__device__ float g_kh  [Mn * Dn];
__device__ float g_lamv[Mn * Dn];
__device__ float g_lm1 [BHn * Sn];
__device__ float g_mid [Mn * Dn];
__device__ float g_bqkv[Ln * 3 * Dn];
__device__ __nv_bfloat16 g_ahi[Mn * FFn];
__device__ __nv_bfloat16 g_alo[Mn * FFn];
__device__ __nv_bfloat16 g_Whi[4 * WLL + Dn * Dn];
__device__ __nv_bfloat16 g_Wlo[4 * WLL + Dn * Dn];

// ---------------- PTX helpers ----------------
static __device__ __forceinline__ uint32_t smem_u32(const void* p) {
    return (uint32_t)__cvta_generic_to_shared(p);
}
static __device__ __forceinline__ void cp16(uint32_t dst, const void* src) {
    asm volatile("cp.async.cg.shared.global [%0], [%1], 16;" :: "r"(dst), "l"(src));
}
static __device__ __forceinline__ void cp_commit() {
    asm volatile("cp.async.commit_group;" ::: "memory");
}
template<int N>
static __device__ __forceinline__ void cp_wait() {
    asm volatile("cp.async.wait_group %0;" :: "n"(N) : "memory");
}
static __device__ __forceinline__ void ldm4(uint32_t* r, uint32_t addr) {
    asm volatile("ldmatrix.sync.aligned.m8n8.x4.shared.b16 {%0,%1,%2,%3}, [%4];"
                 : "=r"(r[0]), "=r"(r[1]), "=r"(r[2]), "=r"(r[3]) : "r"(addr));
}
static __device__ __forceinline__ void mma16816(float* d, const uint32_t* a, const uint32_t* b) {
    asm volatile("mma.sync.aligned.m16n8k16.row.col.f32.bf16.bf16.f32 "
                 "{%0,%1,%2,%3}, {%4,%5,%6,%7}, {%8,%9}, {%0,%1,%2,%3};"
                 : "+f"(d[0]), "+f"(d[1]), "+f"(d[2]), "+f"(d[3])
                 : "r"(a[0]), "r"(a[1]), "r"(a[2]), "r"(a[3]), "r"(b[0]), "r"(b[1]));
}

// ---------------- math helpers ----------------
static __device__ __forceinline__ float atanh_f(float x) {
    return 0.5f * (log1pf(x) - log1pf(-x));
}
template<int NT>
__device__ __forceinline__ float block_sum(float v) {
    __shared__ float sh[NT / 32];
#pragma unroll
    for (int o = 16; o > 0; o >>= 1) v += __shfl_xor_sync(0xffffffffu, v, o);
    int w = threadIdx.x >> 5;
    if ((threadIdx.x & 31) == 0) sh[w] = v;
    __syncthreads();
    float r = sh[0];
#pragma unroll
    for (int i = 1; i < NT / 32; i++) r += sh[i];
    __syncthreads();
    return r;
}
__device__ __forceinline__ float warp_sum(float v) {
#pragma unroll
    for (int o = 16; o > 0; o >>= 1) v += __shfl_xor_sync(0xffffffffu, v, o);
    return v;
}
__device__ __forceinline__ float group16_sum(float v) {
#pragma unroll
    for (int o = 8; o > 0; o >>= 1) v += __shfl_xor_sync(0xffffffffu, v, o);
    return v;
}
static __device__ __forceinline__ void store_split4(__nv_bfloat16* hi, __nv_bfloat16* lo,
                                                    size_t idx, float4 v) {
    __nv_bfloat16 h0 = __float2bfloat16(v.x), h1 = __float2bfloat16(v.y);
    __nv_bfloat16 h2 = __float2bfloat16(v.z), h3 = __float2bfloat16(v.w);
    __nv_bfloat16 l0 = __float2bfloat16(v.x - __bfloat162float(h0));
    __nv_bfloat16 l1 = __float2bfloat16(v.y - __bfloat162float(h1));
    __nv_bfloat16 l2 = __float2bfloat16(v.z - __bfloat162float(h2));
    __nv_bfloat16 l3 = __float2bfloat16(v.w - __bfloat162float(h3));
    ((__nv_bfloat162*)(hi + idx))[0] = __halves2bfloat162(h0, h1);
    ((__nv_bfloat162*)(hi + idx))[1] = __halves2bfloat162(h2, h3);
    ((__nv_bfloat162*)(lo + idx))[0] = __halves2bfloat162(l0, l1);
    ((__nv_bfloat162*)(lo + idx))[1] = __halves2bfloat162(l2, l3);
}

// ---------------- weight conversion (all tensors, one launch) ----------------
struct WCvtArgs {
    const float* src[25];
    long long    off[25];
    int          n4[25];
};
__global__ void k_wcvt(WCvtArgs a, __nv_bfloat16* __restrict__ hi, __nv_bfloat16* __restrict__ lo) {
    int t = blockIdx.y;
    int i = blockIdx.x * blockDim.x + threadIdx.x;
    if (i >= a.n4[t]) return;
    float4 v = ((const float4*)a.src[t])[i];
    store_split4(hi, lo, (size_t)a.off[t] + 4 * (size_t)i, v);
}

// fill fused QKV bias table: g_bqkv[l][0:512]=bq, [512:1024]=bk, [1024:1536]=bv
__global__ void k_bfill(const float* __restrict__ bq, const float* __restrict__ bk,
                        const float* __restrict__ bv, float* __restrict__ out) {
    int l = blockIdx.y;
    int i = blockIdx.x * blockDim.x + threadIdx.x;   // 0..1535
    float v;
    if (i < Dn)            v = bq[l * Dn + i];
    else if (i < 2 * Dn)   v = bk[l * Dn + i - Dn];
    else                   v = bv[l * Dn + i - 2 * Dn];
    out[l * 3 * Dn + i] = v;
}

// ---------------- HMMA GEMM (3-pass split-bf16, 3-stage pipeline) ----------------
constexpr int LDS = 72;
constexpr int STAGE_E = 4 * 64 * LDS;            // elems per stage (Ahi,Alo,Bhi,Blo)
constexpr int GEMM_SMEM = 3 * STAGE_E * 2;       // 110592 B

__global__ void __launch_bounds__(128)
k_gemm_mma(const __nv_bfloat16* __restrict__ Ahi, const __nv_bfloat16* __restrict__ Alo,
           const __nv_bfloat16* __restrict__ Whi, const __nv_bfloat16* __restrict__ Wlo,
           const float* __restrict__ bias, float* __restrict__ C, int Ni, int Ki)
{
    extern __shared__ __nv_bfloat16 sm[];
    const int tid = threadIdx.x, wid = tid >> 5, lane = tid & 31;
    const int bm = blockIdx.y * 64, bn = blockIdx.x * 64;
    const int wm = (wid >> 1) * 32, wn = (wid & 1) * 32;
    const uint32_t sbase = smem_u32(sm);

    float acc[2][4][4];
#pragma unroll
    for (int a = 0; a < 2; a++)
#pragma unroll
        for (int b = 0; b < 4; b++)
#pragma unroll
            for (int c = 0; c < 4; c++) acc[a][b][c] = 0.f;

    const int NC = Ki >> 6;

    auto load_stage = [&](int c) {
        const int s = c % 3;
        const uint32_t sb = sbase + (uint32_t)s * STAGE_E * 2;
        const size_t k0 = (size_t)c * 64;
#pragma unroll
        for (int i = tid; i < 512; i += 128) {
            int row = i >> 3, seg = i & 7;
            const size_t gA = (size_t)(bm + row) * Ki + k0 + seg * 8;
            const size_t gB = (size_t)(bn + row) * Ki + k0 + seg * 8;
            uint32_t ro = (uint32_t)(row * LDS + seg * 8) * 2;
            cp16(sb + ro,                    Ahi + gA);
            cp16(sb + 64 * LDS * 2 + ro,     Alo + gA);
            cp16(sb + 128 * LDS * 2 + ro,    Whi + gB);
            cp16(sb + 192 * LDS * 2 + ro,    Wlo + gB);
        }
        cp_commit();
    };

    // fragment load for one kk from stage base sb into buffer bf
    uint32_t ah[2][2][4], al[2][2][4], bh[2][4][2], bl[2][4][2];
    auto ldfrag = [&](uint32_t sb, int kk, int bf) {
        uint32_t koff = (uint32_t)(kk * 16) * 2 + (lane >> 4) * 16;
#pragma unroll
        for (int mt = 0; mt < 2; mt++) {
            uint32_t rA = (uint32_t)(wm + mt * 16 + (lane & 15));
            ldm4(ah[bf][mt], sb + rA * (LDS * 2) + koff);
            ldm4(al[bf][mt], sb + (64 + rA) * (LDS * 2) + koff);
        }
#pragma unroll
        for (int nt2 = 0; nt2 < 2; nt2++) {
            uint32_t rB = (uint32_t)(128 + wn + nt2 * 16 + (lane & 15));
            uint32_t t[4];
            ldm4(t, sb + rB * (LDS * 2) + koff);
            bh[bf][nt2 * 2][0] = t[0]; bh[bf][nt2 * 2 + 1][0] = t[1];
            bh[bf][nt2 * 2][1] = t[2]; bh[bf][nt2 * 2 + 1][1] = t[3];
            ldm4(t, sb + (64 + rB) * (LDS * 2) + koff);
            bl[bf][nt2 * 2][0] = t[0]; bl[bf][nt2 * 2 + 1][0] = t[1];
            bl[bf][nt2 * 2][1] = t[2]; bl[bf][nt2 * 2 + 1][1] = t[3];
        }
    };

    load_stage(0);
    if (NC > 1) load_stage(1); else cp_commit();

    for (int c = 0; c < NC; c++) {
        const uint32_t sb = sbase + (uint32_t)(c % 3) * STAGE_E * 2;
        if (c + 2 < NC) load_stage(c + 2); else cp_commit();
        cp_wait<2>();
        __syncthreads();

        ldfrag(sb, 0, 0);
#pragma unroll
        for (int kk = 0; kk < 4; kk++) {
            const int cur = kk & 1, nxt = cur ^ 1;
            if (kk < 3) ldfrag(sb, kk + 1, nxt);
            // pass-major order: 8 independent accumulators between D reuses
#pragma unroll
            for (int mt = 0; mt < 2; mt++)
#pragma unroll
                for (int nt = 0; nt < 4; nt++)
                    mma16816(acc[mt][nt], ah[cur][mt], bh[cur][nt]);
#pragma unroll
            for (int mt = 0; mt < 2; mt++)
#pragma unroll
                for (int nt = 0; nt < 4; nt++)
                    mma16816(acc[mt][nt], ah[cur][mt], bl[cur][nt]);
#pragma unroll
            for (int mt = 0; mt < 2; mt++)
#pragma unroll
                for (int nt = 0; nt < 4; nt++)
                    mma16816(acc[mt][nt], al[cur][mt], bh[cur][nt]);
        }
        __syncthreads();
    }

    // epilogue: direct float2 stores (+bias)
#pragma unroll
    for (int mt = 0; mt < 2; mt++) {
        int r0 = bm + wm + mt * 16 + (lane >> 2);
#pragma unroll
        for (int nt = 0; nt < 4; nt++) {
            int col = bn + wn + nt * 8 + 2 * (lane & 3);
            float b0 = bias[col], b1 = bias[col + 1];
            float2 v0 = make_float2(acc[mt][nt][0] + b0, acc[mt][nt][1] + b1);
            float2 v1 = make_float2(acc[mt][nt][2] + b0, acc[mt][nt][3] + b1);
            *(float2*)(C + (size_t)r0 * Ni + col) = v0;
            *(float2*)(C + (size_t)(r0 + 8) * Ni + col) = v1;
        }
    }
}

// ---------------- fused elementwise kernels ----------------

template<int NT>
__global__ void k_mobius_add(const float* __restrict__ x, const float* __restrict__ y,
                             float* __restrict__ out, int ymod) {
    constexpr int P = Dn / NT;
    int r = blockIdx.x;
    const float* xr = x + (size_t)r * Dn;
    const float* yr = y + (size_t)(r % ymod) * Dn;
    float xl[P], yl[P];
    float x2 = 0.f, y2 = 0.f, xy = 0.f;
#pragma unroll
    for (int i = 0; i < P; i++) {
        int j = threadIdx.x + i * NT;
        xl[i] = xr[j]; yl[i] = yr[j];
        x2 += xl[i] * xl[i]; y2 += yl[i] * yl[i]; xy += xl[i] * yl[i];
    }
    x2 = block_sum<NT>(x2);
    y2 = block_sum<NT>(y2);
    xy = block_sum<NT>(xy);
    float den = fmaxf(1.f + 2.f * xy + x2 * y2, EPSf);
    float ca = (1.f + 2.f * xy + y2) / den;
    float cb = (1.f - x2) / den;
    float zl[P]; float n2 = 0.f;
#pragma unroll
    for (int i = 0; i < P; i++) { zl[i] = ca * xl[i] + cb * yl[i]; n2 += zl[i] * zl[i]; }
    n2 = block_sum<NT>(n2);
    float n = sqrtf(fmaxf(n2, EPSf * EPSf));
    float sc = fminf(1.f, MAXNf / n);
#pragma unroll
    for (int i = 0; i < P; i++) out[(size_t)r * Dn + threadIdx.x + i * NT] = zl[i] * sc;
}

__global__ void __launch_bounds__(128)
k_pln2bf(const float* __restrict__ x, const float* __restrict__ w, const float* __restrict__ b,
         __nv_bfloat16* __restrict__ hi, __nv_bfloat16* __restrict__ lo) {
    int r = blockIdx.x, tid = threadIdx.x;
    const float* xr = x + (size_t)r * Dn;
    float4 xv = *(const float4*)(xr + tid * 4);
    float ss = xv.x * xv.x + xv.y * xv.y + xv.z * xv.z + xv.w * xv.w;
    ss = block_sum<128>(ss);
    float n  = sqrtf(fmaxf(ss, EPSf * EPSf));
    float nc = fminf(fmaxf(n, EPSf), MAXNf);
    float ls = atanh_f(nc) / nc;
    float4 tl = make_float4(ls * xv.x, ls * xv.y, ls * xv.z, ls * xv.w);
    float st = tl.x + tl.y + tl.z + tl.w;
    st = block_sum<128>(st);
    float mu = st / (float)Dn;
    float d0 = tl.x - mu, d1 = tl.y - mu, d2 = tl.z - mu, d3 = tl.w - mu;
    float sv = d0 * d0 + d1 * d1 + d2 * d2 + d3 * d3;
    sv = block_sum<128>(sv);
    float inv = rsqrtf(sv / (float)Dn + 1e-5f);
    float4 wv = *(const float4*)(w + tid * 4);
    float4 bv = *(const float4*)(b + tid * 4);
    float4 yv = make_float4(d0 * inv * wv.x + bv.x, d1 * inv * wv.y + bv.y,
                            d2 * inv * wv.z + bv.z, d3 * inv * wv.w + bv.w);
    float sy = yv.x * yv.x + yv.y * yv.y + yv.z * yv.z + yv.w * yv.w;
    sy = block_sum<128>(sy);
    float ny = sqrtf(fmaxf(sy, EPSf * EPSf));
    float es = tanhf(ny) / ny;
    float tb = tanhf(ny);
    float cb = fminf(fmaxf(tb, EPSf), MAXNf);
    float s2 = atanh_f(cb) / cb;
    float sc = es * s2;
    store_split4(hi, lo, (size_t)r * Dn + tid * 4,
                 make_float4(sc * yv.x, sc * yv.y, sc * yv.z, sc * yv.w));
}

// fused-QKV post: blockIdx.y = 0(Q) / 1(K) / 2(V); reads u[M,1536]
__global__ void __launch_bounds__(128)
k_post_qkv3(const float* __restrict__ u, float* __restrict__ q, float* __restrict__ k,
            float* __restrict__ lamv, float* __restrict__ lm1, float ratio) {
    int which = blockIdx.y;
    int r = blockIdx.x, tid = threadIdx.x;
    int b = r / Sn, s = r % Sn;
    float4 uv = *(const float4*)(u + (size_t)r * (3 * Dn) + which * Dn + tid * 4);
    float ss = uv.x * uv.x + uv.y * uv.y + uv.z * uv.z + uv.w * uv.w;
    float bs = block_sum<128>(ss);
    float n  = sqrtf(fmaxf(bs, EPSf * EPSf));
    float s1 = tanhf(n) / n;
    float t  = tanhf(n);
    float c  = fminf(fmaxf(t, EPSf), MAXNf);
    float s2 = atanh_f(c) / c;
    float sc = s1 * s2 * ratio;
    float4 th = make_float4(sc * uv.x, sc * uv.y, sc * uv.z, sc * uv.w);
    float hs = sc * sc * ss;
    hs = group16_sum(hs);
    float nh = sqrtf(fmaxf(hs, EPSf * EPSf));
    float es = tanhf(nh) / nh;
    int h = tid >> 4;
    size_t dst = ((size_t)(b * Hn + h) * Sn + s) * HDn + (tid & 15) * 4;
    if (which == 0) {
        *(float4*)(q + dst) = make_float4(es * th.x, es * th.y, es * th.z, es * th.w);
    } else if (which == 1) {
        *(float4*)(k + dst) = make_float4(es * th.x, es * th.y, es * th.z, es * th.w);
    } else {
        float vsq = es * es * hs;
        float lam = 2.f / fmaxf(1.f - vsq, EPSf);
        float ls2 = lam * es;
        *(float4*)(lamv + dst) = make_float4(ls2 * th.x, ls2 * th.y, ls2 * th.z, ls2 * th.w);
        if ((tid & 15) == 0) lm1[(size_t)(b * Hn + h) * Sn + s] = lam - 1.f;
    }
}

// fused attention: scores + softmax(no-max) + gyromidpoint + scalar-mul/project
__global__ void __launch_bounds__(256)
k_attn(const float* __restrict__ qh, const float* __restrict__ kh,
       const float* __restrict__ lamv, const float* __restrict__ lm1,
       const float* __restrict__ tau, const float* __restrict__ gam, int l,
       float* __restrict__ mid) {
    int it = blockIdx.x, bh = blockIdx.y;
    extern __shared__ float sma[];
    float* Qs  = sma;
    float* Ks  = Qs + 64 * 68;
    float* Ps  = Ks + 64 * 68;
    float* Lv  = Ps + 64 * 68;
    float* q2  = Lv + 64 * 68;
    float* k2  = q2 + 64;
    float* lms = k2 + 64;
    int tid = threadIdx.x, tx = tid & 15, ty = tid >> 4;

    const float* Q = qh + ((size_t)bh * Sn + it * 64) * HDn;
    for (int f = tid; f < 1024; f += 256) {
        int row = f >> 4, c = (f & 15) * 4;
        float4 v = *(const float4*)(Q + row * HDn + c);
        Qs[(c + 0) * 68 + row] = v.x; Qs[(c + 1) * 68 + row] = v.y;
        Qs[(c + 2) * 68 + row] = v.z; Qs[(c + 3) * 68 + row] = v.w;
    }
    __syncthreads();
    if (tid < 64) {
        float s = 0.f;
        for (int d = 0; d < HDn; d++) { float a = Qs[d * 68 + tid]; s += a * a; }
        q2[tid] = s;
    }
    float tv = tau[l], gv = gam[l];
    float acc[4][4] = {};
    float dac[4] = {};
    float ssum[4] = {};

    for (int jt = 0; jt <= it; jt++) {
        __syncthreads();
        const float* K  = kh   + ((size_t)bh * Sn + jt * 64) * HDn;
        const float* Lg = lamv + ((size_t)bh * Sn + jt * 64) * HDn;
        for (int f = tid; f < 1024; f += 256) {
            int row = f >> 4, c = (f & 15) * 4;
            float4 u = *(const float4*)(K + row * HDn + c);
            Ks[(c + 0) * 68 + row] = u.x; Ks[(c + 1) * 68 + row] = u.y;
            Ks[(c + 2) * 68 + row] = u.z; Ks[(c + 3) * 68 + row] = u.w;
            float4 w = *(const float4*)(Lg + row * HDn + c);
            *(float4*)&Lv[row * 68 + c] = w;
        }
        if (tid < 64) lms[tid] = lm1[(size_t)bh * Sn + jt * 64 + tid];
        __syncthreads();
        if (tid < 64) {
            float s = 0.f;
            for (int d = 0; d < HDn; d++) { float a = Ks[d * 68 + tid]; s += a * a; }
            k2[tid] = s;
        }
        __syncthreads();

        float sacc[4][4] = {};
#pragma unroll 8
        for (int d = 0; d < HDn; d++) {
            float4 av = *(const float4*)&Qs[d * 68 + ty * 4];
            float4 bv = *(const float4*)&Ks[d * 68 + tx * 4];
            float a[4] = {av.x, av.y, av.z, av.w};
            float b[4] = {bv.x, bv.y, bv.z, bv.w};
#pragma unroll
            for (int i = 0; i < 4; i++)
#pragma unroll
                for (int j = 0; j < 4; j++) sacc[i][j] += a[i] * b[j];
        }
        bool diag = (jt == it);
#pragma unroll
        for (int ii = 0; ii < 4; ii++) {
            int i = ty * 4 + ii;
            float qq = q2[i];
#pragma unroll
            for (int jj = 0; jj < 4; jj++) {
                int j = tx * 4 + jj;
                float e;
                if (diag && j > i) e = 0.f;
                else {
                    float kk = k2[j];
                    float d2 = fmaxf(qq + kk - 2.f * sacc[ii][jj], 0.f);
                    float dn = fmaxf((1.f - qq) * (1.f - kk), EPSf);
                    float uu = fmaxf(2.f * d2 / dn, 1.1920929e-7f);
                    float dist = log1pf(uu + sqrtf(uu * (uu + 2.f)));
                    e = expf(-tv * dist - gv);
                }
                Ps[i * 68 + j] = e;
                ssum[ii] += e;
            }
        }
        __syncthreads();
#pragma unroll 4
        for (int j = 0; j < 64; j++) {
            float a0 = Ps[(ty * 4 + 0) * 68 + j];
            float a1 = Ps[(ty * 4 + 1) * 68 + j];
            float a2 = Ps[(ty * 4 + 2) * 68 + j];
            float a3 = Ps[(ty * 4 + 3) * 68 + j];
            float4 lv = *(const float4*)&Lv[j * 68 + tx * 4];
            acc[0][0] += a0 * lv.x; acc[0][1] += a0 * lv.y; acc[0][2] += a0 * lv.z; acc[0][3] += a0 * lv.w;
            acc[1][0] += a1 * lv.x; acc[1][1] += a1 * lv.y; acc[1][2] += a1 * lv.z; acc[1][3] += a1 * lv.w;
            acc[2][0] += a2 * lv.x; acc[2][1] += a2 * lv.y; acc[2][2] += a2 * lv.z; acc[2][3] += a2 * lv.w;
            acc[3][0] += a3 * lv.x; acc[3][1] += a3 * lv.y; acc[3][2] += a3 * lv.z; acc[3][3] += a3 * lv.w;
            float lm = lms[j];
            dac[0] += a0 * lm; dac[1] += a1 * lm; dac[2] += a2 * lm; dac[3] += a3 * lm;
        }
    }

#pragma unroll
    for (int ii = 0; ii < 4; ii++) {
        float rs = ssum[ii];
#pragma unroll
        for (int o = 8; o > 0; o >>= 1) rs += __shfl_xor_sync(0xffffffffu, rs, o);
        float dn = fmaxf(dac[ii], EPSf * rs);
        float inv = 1.f / dn;
        float m0 = acc[ii][0] * inv, m1 = acc[ii][1] * inv;
        float m2 = acc[ii][2] * inv, m3 = acc[ii][3] * inv;
        float ss2 = m0 * m0 + m1 * m1 + m2 * m2 + m3 * m3;
#pragma unroll
        for (int o = 8; o > 0; o >>= 1) ss2 += __shfl_xor_sync(0xffffffffu, ss2, o);
        float n  = sqrtf(fmaxf(ss2, EPSf * EPSf));
        float nc = fminf(fmaxf(n, EPSf), MAXNf);
        float tt = tanhf(0.5f * atanh_f(nc));
        float s1 = tt / nc;
        float ny = sqrtf(fmaxf(s1 * s1 * ss2, EPSf * EPSf));
        float s2 = fminf(1.f, MAXNf / ny);
        float sc = s1 * s2;
        size_t dst = ((size_t)bh * Sn + it * 64 + ty * 4 + ii) * HDn + tx * 4;
        *(float4*)(mid + dst) = make_float4(m0 * sc, m1 * sc, m2 * sc, m3 * sc);
    }
}

__global__ void __launch_bounds__(128)
k_concat2bf(const float* __restrict__ mh, __nv_bfloat16* __restrict__ hi,
            __nv_bfloat16* __restrict__ lo, float ratio) {
    int r = blockIdx.x, tid = threadIdx.x;
    int b = r / Sn, s = r % Sn;
    __shared__ float row[Dn];
    int warp = tid >> 5, lane = tid & 31;
#pragma unroll
    for (int hh = 0; hh < 2; hh++) {
        int h = warp * 2 + hh;
        const float* src = mh + ((size_t)((b * Hn + h) * Sn + s)) * HDn;
        float v0 = src[lane], v1 = src[lane + 32];
        float ss = warp_sum(v0 * v0 + v1 * v1);
        float n  = sqrtf(fmaxf(ss, EPSf * EPSf));
        float nc = fminf(fmaxf(n, EPSf), MAXNf);
        float sc = atanh_f(nc) / nc * ratio;
        row[h * HDn + lane]      = sc * v0;
        row[h * HDn + lane + 32] = sc * v1;
    }
    __syncthreads();
    float4 vl = *(const float4*)&row[tid * 4];
    float ss = vl.x * vl.x + vl.y * vl.y + vl.z * vl.z + vl.w * vl.w;
    ss = block_sum<128>(ss);
    float n  = sqrtf(fmaxf(ss, EPSf * EPSf));
    float es = tanhf(n) / n;
    float tb = tanhf(n);
    float cb = fminf(fmaxf(tb, EPSf), MAXNf);
    float s2 = atanh_f(cb) / cb;
    float sc = es * s2;
    store_split4(hi, lo, (size_t)r * Dn + tid * 4,
                 make_float4(sc * vl.x, sc * vl.y, sc * vl.z, sc * vl.w));
}

__global__ void __launch_bounds__(128)
k_exp_madd(const float* __restrict__ g, float* __restrict__ x) {
    int r = blockIdx.x, tid = threadIdx.x;
    float4 gv = *(const float4*)(g + (size_t)r * Dn + tid * 4);
    float4 xv = *(const float4*)(x + (size_t)r * Dn + tid * 4);
    float lg = gv.x * gv.x + gv.y * gv.y + gv.z * gv.z + gv.w * gv.w;
    float lx = xv.x * xv.x + xv.y * xv.y + xv.z * xv.z + xv.w * xv.w;
    float lxg = xv.x * gv.x + xv.y * gv.y + xv.z * gv.z + xv.w * gv.w;
    float g2 = block_sum<128>(lg);
    float x2 = block_sum<128>(lx);
    float xg = block_sum<128>(lxg);
    float ng = sqrtf(fmaxf(g2, EPSf * EPSf));
    float s  = tanhf(ng) / ng;
    float y2 = s * s * g2;
    float xy = s * xg;
    float den = fmaxf(1.f + 2.f * xy + x2 * y2, EPSf);
    float ca = (1.f + 2.f * xy + y2) / den;
    float cb = (1.f - x2) / den * s;
    float4 zv = make_float4(ca * xv.x + cb * gv.x, ca * xv.y + cb * gv.y,
                            ca * xv.z + cb * gv.z, ca * xv.w + cb * gv.w);
    float n2 = zv.x * zv.x + zv.y * zv.y + zv.z * zv.z + zv.w * zv.w;
    n2 = block_sum<128>(n2);
    float n = sqrtf(fmaxf(n2, EPSf * EPSf));
    float sc = fminf(1.f, MAXNf / n);
    *(float4*)(x + (size_t)r * Dn + tid * 4) =
        make_float4(sc * zv.x, sc * zv.y, sc * zv.z, sc * zv.w);
}

__global__ void __launch_bounds__(256)
k_ffnmid2bf(const float* __restrict__ u, __nv_bfloat16* __restrict__ hi,
            __nv_bfloat16* __restrict__ lo) {
    int r = blockIdx.x, tid = threadIdx.x;
    const float* ur = u + (size_t)r * FFn;
    float4 u0 = *(const float4*)(ur + tid * 4);
    float4 u1 = *(const float4*)(ur + 1024 + tid * 4);
    float ss = u0.x * u0.x + u0.y * u0.y + u0.z * u0.z + u0.w * u0.w
             + u1.x * u1.x + u1.y * u1.y + u1.z * u1.z + u1.w * u1.w;
    ss = block_sum<256>(ss);
    float n0 = sqrtf(fmaxf(ss, EPSf * EPSf));
    float t0 = tanhf(n0);
    float s1 = t0 / n0;
    float c0 = fminf(fmaxf(t0, EPSf), MAXNf);
    float a0 = atanh_f(c0) / c0;
    float w  = a0 * s1;
    float4 r0 = make_float4(fmaxf(w * u0.x, 0.f), fmaxf(w * u0.y, 0.f),
                            fmaxf(w * u0.z, 0.f), fmaxf(w * u0.w, 0.f));
    float4 r1 = make_float4(fmaxf(w * u1.x, 0.f), fmaxf(w * u1.y, 0.f),
                            fmaxf(w * u1.z, 0.f), fmaxf(w * u1.w, 0.f));
    float st = r0.x * r0.x + r0.y * r0.y + r0.z * r0.z + r0.w * r0.w
             + r1.x * r1.x + r1.y * r1.y + r1.z * r1.z + r1.w * r1.w;
    st = block_sum<256>(st);
    float n1 = sqrtf(fmaxf(st, EPSf * EPSf));
    float e1 = tanhf(n1) / n1;
    float t1 = tanhf(n1);
    float c1 = fminf(fmaxf(t1, EPSf), MAXNf);
    float a1 = atanh_f(c1) / c1;
    float sc = a1 * e1;
    store_split4(hi, lo, (size_t)r * FFn + tid * 4,
                 make_float4(sc * r0.x, sc * r0.y, sc * r0.z, sc * r0.w));
    store_split4(hi, lo, (size_t)r * FFn + 1024 + tid * 4,
                 make_float4(sc * r1.x, sc * r1.y, sc * r1.z, sc * r1.w));
}

__global__ void __launch_bounds__(128)
k_log2bf(const float* __restrict__ x, __nv_bfloat16* __restrict__ hi,
         __nv_bfloat16* __restrict__ lo) {
    int r = blockIdx.x, tid = threadIdx.x;
    float4 xv = *(const float4*)(x + (size_t)r * Dn + tid * 4);
    float ss = xv.x * xv.x + xv.y * xv.y + xv.z * xv.z + xv.w * xv.w;
    ss = block_sum<128>(ss);
    float n  = sqrtf(fmaxf(ss, EPSf * EPSf));
    float nc = fminf(fmaxf(n, EPSf), MAXNf);
    float s  = atanh_f(nc) / nc;
    store_split4(hi, lo, (size_t)r * Dn + tid * 4,
                 make_float4(s * xv.x, s * xv.y, s * xv.z, s * xv.w));
}

__global__ void __launch_bounds__(128)
k_expmap_out(const float* __restrict__ x, float* __restrict__ out) {
    int r = blockIdx.x, tid = threadIdx.x;
    float4 xv = *(const float4*)(x + (size_t)r * Dn + tid * 4);
    float ss = xv.x * xv.x + xv.y * xv.y + xv.z * xv.z + xv.w * xv.w;
    ss = block_sum<128>(ss);
    float n = sqrtf(fmaxf(ss, EPSf * EPSf));
    float s = tanhf(n) / n;
    *(float4*)(out + (size_t)r * Dn + tid * 4) =
        make_float4(s * xv.x, s * xv.y, s * xv.z, s * xv.w);
}

// ---------------- host orchestration ----------------
extern "C" void kernel_launch(void* const* d_in, const int* in_sizes, int n_in,
                              void* d_out, int out_size) {
    (void)in_sizes; (void)n_in; (void)out_size;
    const float* x    = (const float*)d_in[0];
    const float* pos  = (const float*)d_in[1];
    const float* ln1w = (const float*)d_in[2];
    const float* ln1b = (const float*)d_in[3];
    const float* ln2w = (const float*)d_in[4];
    const float* ln2b = (const float*)d_in[5];
    const float* Wq   = (const float*)d_in[6];
    const float* bq   = (const float*)d_in[7];
    const float* Wk   = (const float*)d_in[8];
    const float* bk   = (const float*)d_in[9];
    const float* Wv   = (const float*)d_in[10];
    const float* bv   = (const float*)d_in[11];
    const float* Wo   = (const float*)d_in[12];
    const float* bo   = (const float*)d_in[13];
    const float* W1   = (const float*)d_in[14];
    const float* b1   = (const float*)d_in[15];
    const float* W2   = (const float*)d_in[16];
    const float* b2   = (const float*)d_in[17];
    const float* tau  = (const float*)d_in[18];
    const float* gam  = (const float*)d_in[19];
    const float* Wout = (const float*)d_in[20];
    const float* bout = (const float*)d_in[21];
    float* outp = (float*)d_out;

    float *px, *pu, *pq, *pk, *plv, *plm, *pm, *pbq;
    __nv_bfloat16 *pahi, *palo, *pwhi, *pwlo;
    cudaGetSymbolAddress((void**)&px,  g_x);
    cudaGetSymbolAddress((void**)&pu,  g_u);
    cudaGetSymbolAddress((void**)&pq,  g_qh);
    cudaGetSymbolAddress((void**)&pk,  g_kh);
    cudaGetSymbolAddress((void**)&plv, g_lamv);
    cudaGetSymbolAddress((void**)&plm, g_lm1);
    cudaGetSymbolAddress((void**)&pm,  g_mid);
    cudaGetSymbolAddress((void**)&pbq, g_bqkv);
    cudaGetSymbolAddress((void**)&pahi, g_ahi);
    cudaGetSymbolAddress((void**)&palo, g_alo);
    cudaGetSymbolAddress((void**)&pwhi, g_Whi);
    cudaGetSymbolAddress((void**)&pwlo, g_Wlo);

    cudaFuncSetAttribute((const void*)k_gemm_mma,
                         cudaFuncAttributeMaxDynamicSharedMemorySize, GEMM_SMEM);
    constexpr int ATTN_SMEM = (4 * 64 * 68 + 3 * 64) * 4;
    cudaFuncSetAttribute((const void*)k_attn,
                         cudaFuncAttributeMaxDynamicSharedMemorySize, ATTN_SMEM);

    double betaD  = std::exp(std::lgamma(Dn / 2.0)  + std::lgamma(0.5) - std::lgamma(Dn / 2.0 + 0.5));
    double betaHD = std::exp(std::lgamma(HDn / 2.0) + std::lgamma(0.5) - std::lgamma(HDn / 2.0 + 0.5));
    float ratio_split = (float)(betaHD / betaD);
    float ratio_cat   = (float)(betaD / betaHD);

    // ---- convert all weights + fused biases once ----
    constexpr int DD = Dn * Dn, FD = FFn * Dn;
    WCvtArgs wa;
    int idx = 0;
    auto add = [&](const float* s, long long off, int n) {
        wa.src[idx] = s; wa.off[idx] = off; wa.n4[idx] = n / 4; idx++;
    };
    for (int l = 0; l < Ln; l++) {
        long long base = l * WLL;
        add(Wq + (size_t)l * DD, base,              DD);
        add(Wk + (size_t)l * DD, base + DD,         DD);
        add(Wv + (size_t)l * DD, base + 2 * DD,     DD);
        add(Wo + (size_t)l * DD, base + 3 * DD,     DD);
        add(W1 + (size_t)l * FD, base + 4 * DD,     FD);
        add(W2 + (size_t)l * FD, base + 4 * DD + FD, FD);
    }
    add(Wout, 4 * WLL, DD);
    k_wcvt<<<dim3(1024, 25), 256>>>(wa, pwhi, pwlo);
    k_bfill<<<dim3(6, Ln), 256>>>(bq, bk, bv, pbq);

    auto gemm = [&](long long woff, const float* bias, float* Cout, int Ni, int Ki) {
        k_gemm_mma<<<dim3(Ni / 64, Mn / 64), 128, GEMM_SMEM>>>(
            pahi, palo, pwhi + woff, pwlo + woff, bias, Cout, Ni, Ki);
    };

    k_mobius_add<128><<<Mn, 128>>>(x, pos, px, Sn);

    for (int l = 0; l < Ln; l++) {
        long long base = l * WLL;
        // ---- attention ----
        k_pln2bf<<<Mn, 128>>>(px, ln1w + l * Dn, ln1b + l * Dn, pahi, palo);
        gemm(base, pbq + l * 3 * Dn, pu, 3 * Dn, Dn);   // fused QKV
        k_post_qkv3<<<dim3(Mn, 3), 128>>>(pu, pq, pk, plv, plm, ratio_split);

        k_attn<<<dim3(Sn / 64, BHn), 256, ATTN_SMEM>>>(pq, pk, plv, plm, tau, gam, l, pm);

        k_concat2bf<<<Mn, 128>>>(pm, pahi, palo, ratio_cat);
        gemm(base + 3 * DD, bo + l * Dn, pu, Dn, Dn);
        k_exp_madd<<<Mn, 128>>>(pu, px);

        // ---- FFN ----
        k_pln2bf<<<Mn, 128>>>(px, ln2w + l * Dn, ln2b + l * Dn, pahi, palo);
        gemm(base + 4 * DD, b1 + l * FFn, pu, FFn, Dn);
        k_ffnmid2bf<<<Mn, 256>>>(pu, pahi, palo);
        gemm(base + 4 * DD + FD, b2 + l * Dn, pu, Dn, FFn);
        k_exp_madd<<<Mn, 128>>>(pu, px);
    }

    // ---- head ----
    k_log2bf<<<Mn, 128>>>(px, pahi, palo);
    gemm(4 * WLL, bout, pu, Dn, Dn);
    k_expmap_out<<<Mn, 128>>>(pu, outp);
}

// round 6
// speedup vs baseline: 1.9821x; 1.0002x over previous
#include <cuda_runtime.h>
#include <cuda_bf16.h>
#include <cstdint>
#include <cmath>

// ---------------- problem constants ----------------
constexpr int Bn  = 2;
constexpr int Sn  = 1024;
constexpr int Dn  = 512;
constexpr int Hn  = 8;
constexpr int HDn = 64;
constexpr int FFn = 2048;
constexpr int Ln  = 4;
constexpr int Mn  = Bn * Sn;   // 2048
constexpr int BHn = Bn * Hn;   // 16
constexpr long long WLL = 4LL * Dn * Dn + 2LL * FFn * Dn;  // per-layer weight elems

#define EPSf   1e-7f
#define MAXNf  (1.0f - 1e-3f)

// ---------------- scratch ----------------
__device__ float g_x   [Mn * Dn];
__device__ float g_u   [Mn * FFn];
__device__ float g_qh  [Mn * Dn];
__device__ float g_kh  [Mn * Dn];
__device__ float g_lamv[Mn * Dn];
__device__ float g_lm1 [BHn * Sn];
__device__ float g_mid [Mn * Dn];
__device__ float g_bqkv[Ln * 3 * Dn];
__device__ __nv_bfloat16 g_ahi[Mn * FFn];
__device__ __nv_bfloat16 g_alo[Mn * FFn];
__device__ __nv_bfloat16 g_Whi[4 * WLL + Dn * Dn];
__device__ __nv_bfloat16 g_Wlo[4 * WLL + Dn * Dn];

// ---------------- PTX helpers ----------------
static __device__ __forceinline__ uint32_t smem_u32(const void* p) {
    return (uint32_t)__cvta_generic_to_shared(p);
}
static __device__ __forceinline__ void cp16(uint32_t dst, const void* src) {
    asm volatile("cp.async.cg.shared.global [%0], [%1], 16;" :: "r"(dst), "l"(src));
}
static __device__ __forceinline__ void cp_commit() {
    asm volatile("cp.async.commit_group;" ::: "memory");
}
template<int N>
static __device__ __forceinline__ void cp_wait() {
    asm volatile("cp.async.wait_group %0;" :: "n"(N) : "memory");
}
static __device__ __forceinline__ void ldm4(uint32_t* r, uint32_t addr) {
    asm volatile("ldmatrix.sync.aligned.m8n8.x4.shared.b16 {%0,%1,%2,%3}, [%4];"
                 : "=r"(r[0]), "=r"(r[1]), "=r"(r[2]), "=r"(r[3]) : "r"(addr));
}
static __device__ __forceinline__ void mma16816(float* d, const uint32_t* a, const uint32_t* b) {
    asm volatile("mma.sync.aligned.m16n8k16.row.col.f32.bf16.bf16.f32 "
                 "{%0,%1,%2,%3}, {%4,%5,%6,%7}, {%8,%9}, {%0,%1,%2,%3};"
                 : "+f"(d[0]), "+f"(d[1]), "+f"(d[2]), "+f"(d[3])
                 : "r"(a[0]), "r"(a[1]), "r"(a[2]), "r"(a[3]), "r"(b[0]), "r"(b[1]));
}

// ---------------- math helpers ----------------
static __device__ __forceinline__ float atanh_f(float x) {
    return 0.5f * (log1pf(x) - log1pf(-x));
}
template<int NT>
__device__ __forceinline__ float block_sum(float v) {
    __shared__ float sh[NT / 32];
#pragma unroll
    for (int o = 16; o > 0; o >>= 1) v += __shfl_xor_sync(0xffffffffu, v, o);
    int w = threadIdx.x >> 5;
    if ((threadIdx.x & 31) == 0) sh[w] = v;
    __syncthreads();
    float r = sh[0];
#pragma unroll
    for (int i = 1; i < NT / 32; i++) r += sh[i];
    __syncthreads();
    return r;
}
__device__ __forceinline__ float warp_sum(float v) {
#pragma unroll
    for (int o = 16; o > 0; o >>= 1) v += __shfl_xor_sync(0xffffffffu, v, o);
    return v;
}
__device__ __forceinline__ float group16_sum(float v) {
#pragma unroll
    for (int o = 8; o > 0; o >>= 1) v += __shfl_xor_sync(0xffffffffu, v, o);
    return v;
}
static __device__ __forceinline__ void store_split4(__nv_bfloat16* hi, __nv_bfloat16* lo,
                                                    size_t idx, float4 v) {
    __nv_bfloat16 h0 = __float2bfloat16(v.x), h1 = __float2bfloat16(v.y);
    __nv_bfloat16 h2 = __float2bfloat16(v.z), h3 = __float2bfloat16(v.w);
    __nv_bfloat16 l0 = __float2bfloat16(v.x - __bfloat162float(h0));
    __nv_bfloat16 l1 = __float2bfloat16(v.y - __bfloat162float(h1));
    __nv_bfloat16 l2 = __float2bfloat16(v.z - __bfloat162float(h2));
    __nv_bfloat16 l3 = __float2bfloat16(v.w - __bfloat162float(h3));
    ((__nv_bfloat162*)(hi + idx))[0] = __halves2bfloat162(h0, h1);
    ((__nv_bfloat162*)(hi + idx))[1] = __halves2bfloat162(h2, h3);
    ((__nv_bfloat162*)(lo + idx))[0] = __halves2bfloat162(l0, l1);
    ((__nv_bfloat162*)(lo + idx))[1] = __halves2bfloat162(l2, l3);
}

// ---------------- weight conversion (all tensors, one launch) ----------------
struct WCvtArgs {
    const float* src[25];
    long long    off[25];
    int          n4[25];
};
__global__ void k_wcvt(WCvtArgs a, __nv_bfloat16* __restrict__ hi, __nv_bfloat16* __restrict__ lo) {
    int t = blockIdx.y;
    int i = blockIdx.x * blockDim.x + threadIdx.x;
    if (i >= a.n4[t]) return;
    float4 v = ((const float4*)a.src[t])[i];
    store_split4(hi, lo, (size_t)a.off[t] + 4 * (size_t)i, v);
}

// fill fused QKV bias table: g_bqkv[l][0:512]=bq, [512:1024]=bk, [1024:1536]=bv
__global__ void k_bfill(const float* __restrict__ bq, const float* __restrict__ bk,
                        const float* __restrict__ bv, float* __restrict__ out) {
    int l = blockIdx.y;
    int i = blockIdx.x * blockDim.x + threadIdx.x;   // 0..1535
    float v;
    if (i < Dn)            v = bq[l * Dn + i];
    else if (i < 2 * Dn)   v = bk[l * Dn + i - Dn];
    else                   v = bv[l * Dn + i - 2 * Dn];
    out[l * 3 * Dn + i] = v;
}

// ---------------- HMMA GEMM (3-pass split-bf16, 3-stage pipeline) ----------------
constexpr int LDS = 72;
constexpr int STAGE_E = 4 * 64 * LDS;            // elems per stage (Ahi,Alo,Bhi,Blo)
constexpr int GEMM_SMEM = 3 * STAGE_E * 2;       // 110592 B

__global__ void __launch_bounds__(128)
k_gemm_mma(const __nv_bfloat16* __restrict__ Ahi, const __nv_bfloat16* __restrict__ Alo,
           const __nv_bfloat16* __restrict__ Whi, const __nv_bfloat16* __restrict__ Wlo,
           const float* __restrict__ bias, float* __restrict__ C, int Ni, int Ki)
{
    extern __shared__ __nv_bfloat16 sm[];
    const int tid = threadIdx.x, wid = tid >> 5, lane = tid & 31;
    const int bm = blockIdx.y * 64, bn = blockIdx.x * 64;
    const int wm = (wid >> 1) * 32, wn = (wid & 1) * 32;
    const uint32_t sbase = smem_u32(sm);

    float acc[2][4][4];
#pragma unroll
    for (int a = 0; a < 2; a++)
#pragma unroll
        for (int b = 0; b < 4; b++)
#pragma unroll
            for (int c = 0; c < 4; c++) acc[a][b][c] = 0.f;

    const int NC = Ki >> 6;

    auto load_stage = [&](int c) {
        const int s = c % 3;
        const uint32_t sb = sbase + (uint32_t)s * STAGE_E * 2;
        const size_t k0 = (size_t)c * 64;
#pragma unroll
        for (int i = tid; i < 512; i += 128) {
            int row = i >> 3, seg = i & 7;
            const size_t gA = (size_t)(bm + row) * Ki + k0 + seg * 8;
            const size_t gB = (size_t)(bn + row) * Ki + k0 + seg * 8;
            uint32_t ro = (uint32_t)(row * LDS + seg * 8) * 2;
            cp16(sb + ro,                    Ahi + gA);
            cp16(sb + 64 * LDS * 2 + ro,     Alo + gA);
            cp16(sb + 128 * LDS * 2 + ro,    Whi + gB);
            cp16(sb + 192 * LDS * 2 + ro,    Wlo + gB);
        }
        cp_commit();
    };

    // fragment load for one kk from stage base sb into buffer bf
    uint32_t ah[2][2][4], al[2][2][4], bh[2][4][2], bl[2][4][2];
    auto ldfrag = [&](uint32_t sb, int kk, int bf) {
        uint32_t koff = (uint32_t)(kk * 16) * 2 + (lane >> 4) * 16;
#pragma unroll
        for (int mt = 0; mt < 2; mt++) {
            uint32_t rA = (uint32_t)(wm + mt * 16 + (lane & 15));
            ldm4(ah[bf][mt], sb + rA * (LDS * 2) + koff);
            ldm4(al[bf][mt], sb + (64 + rA) * (LDS * 2) + koff);
        }
#pragma unroll
        for (int nt2 = 0; nt2 < 2; nt2++) {
            uint32_t rB = (uint32_t)(128 + wn + nt2 * 16 + (lane & 15));
            uint32_t t[4];
            ldm4(t, sb + rB * (LDS * 2) + koff);
            bh[bf][nt2 * 2][0] = t[0]; bh[bf][nt2 * 2 + 1][0] = t[1];
            bh[bf][nt2 * 2][1] = t[2]; bh[bf][nt2 * 2 + 1][1] = t[3];
            ldm4(t, sb + (64 + rB) * (LDS * 2) + koff);
            bl[bf][nt2 * 2][0] = t[0]; bl[bf][nt2 * 2 + 1][0] = t[1];
            bl[bf][nt2 * 2][1] = t[2]; bl[bf][nt2 * 2 + 1][1] = t[3];
        }
    };

    load_stage(0);
    if (NC > 1) load_stage(1); else cp_commit();

    for (int c = 0; c < NC; c++) {
        const uint32_t sb = sbase + (uint32_t)(c % 3) * STAGE_E * 2;
        if (c + 2 < NC) load_stage(c + 2); else cp_commit();
        cp_wait<2>();
        __syncthreads();

        ldfrag(sb, 0, 0);
#pragma unroll
        for (int kk = 0; kk < 4; kk++) {
            const int cur = kk & 1, nxt = cur ^ 1;
            if (kk < 3) ldfrag(sb, kk + 1, nxt);
            // pass-major order: 8 independent accumulators between D reuses
#pragma unroll
            for (int mt = 0; mt < 2; mt++)
#pragma unroll
                for (int nt = 0; nt < 4; nt++)
                    mma16816(acc[mt][nt], ah[cur][mt], bh[cur][nt]);
#pragma unroll
            for (int mt = 0; mt < 2; mt++)
#pragma unroll
                for (int nt = 0; nt < 4; nt++)
                    mma16816(acc[mt][nt], ah[cur][mt], bl[cur][nt]);
#pragma unroll
            for (int mt = 0; mt < 2; mt++)
#pragma unroll
                for (int nt = 0; nt < 4; nt++)
                    mma16816(acc[mt][nt], al[cur][mt], bh[cur][nt]);
        }
        __syncthreads();
    }

    // epilogue: direct float2 stores (+bias)
#pragma unroll
    for (int mt = 0; mt < 2; mt++) {
        int r0 = bm + wm + mt * 16 + (lane >> 2);
#pragma unroll
        for (int nt = 0; nt < 4; nt++) {
            int col = bn + wn + nt * 8 + 2 * (lane & 3);
            float b0 = bias[col], b1 = bias[col + 1];
            float2 v0 = make_float2(acc[mt][nt][0] + b0, acc[mt][nt][1] + b1);
            float2 v1 = make_float2(acc[mt][nt][2] + b0, acc[mt][nt][3] + b1);
            *(float2*)(C + (size_t)r0 * Ni + col) = v0;
            *(float2*)(C + (size_t)(r0 + 8) * Ni + col) = v1;
        }
    }
}

// ---------------- fused elementwise kernels ----------------

template<int NT>
__global__ void k_mobius_add(const float* __restrict__ x, const float* __restrict__ y,
                             float* __restrict__ out, int ymod) {
    constexpr int P = Dn / NT;
    int r = blockIdx.x;
    const float* xr = x + (size_t)r * Dn;
    const float* yr = y + (size_t)(r % ymod) * Dn;
    float xl[P], yl[P];
    float x2 = 0.f, y2 = 0.f, xy = 0.f;
#pragma unroll
    for (int i = 0; i < P; i++) {
        int j = threadIdx.x + i * NT;
        xl[i] = xr[j]; yl[i] = yr[j];
        x2 += xl[i] * xl[i]; y2 += yl[i] * yl[i]; xy += xl[i] * yl[i];
    }
    x2 = block_sum<NT>(x2);
    y2 = block_sum<NT>(y2);
    xy = block_sum<NT>(xy);
    float den = fmaxf(1.f + 2.f * xy + x2 * y2, EPSf);
    float ca = (1.f + 2.f * xy + y2) / den;
    float cb = (1.f - x2) / den;
    float zl[P]; float n2 = 0.f;
#pragma unroll
    for (int i = 0; i < P; i++) { zl[i] = ca * xl[i] + cb * yl[i]; n2 += zl[i] * zl[i]; }
    n2 = block_sum<NT>(n2);
    float n = sqrtf(fmaxf(n2, EPSf * EPSf));
    float sc = fminf(1.f, MAXNf / n);
#pragma unroll
    for (int i = 0; i < P; i++) out[(size_t)r * Dn + threadIdx.x + i * NT] = zl[i] * sc;
}

__global__ void __launch_bounds__(128)
k_pln2bf(const float* __restrict__ x, const float* __restrict__ w, const float* __restrict__ b,
         __nv_bfloat16* __restrict__ hi, __nv_bfloat16* __restrict__ lo) {
    int r = blockIdx.x, tid = threadIdx.x;
    const float* xr = x + (size_t)r * Dn;
    float4 xv = *(const float4*)(xr + tid * 4);
    float ss = xv.x * xv.x + xv.y * xv.y + xv.z * xv.z + xv.w * xv.w;
    ss = block_sum<128>(ss);
    float n  = sqrtf(fmaxf(ss, EPSf * EPSf));
    float nc = fminf(fmaxf(n, EPSf), MAXNf);
    float ls = atanh_f(nc) / nc;
    float4 tl = make_float4(ls * xv.x, ls * xv.y, ls * xv.z, ls * xv.w);
    float st = tl.x + tl.y + tl.z + tl.w;
    st = block_sum<128>(st);
    float mu = st / (float)Dn;
    float d0 = tl.x - mu, d1 = tl.y - mu, d2 = tl.z - mu, d3 = tl.w - mu;
    float sv = d0 * d0 + d1 * d1 + d2 * d2 + d3 * d3;
    sv = block_sum<128>(sv);
    float inv = rsqrtf(sv / (float)Dn + 1e-5f);
    float4 wv = *(const float4*)(w + tid * 4);
    float4 bv = *(const float4*)(b + tid * 4);
    float4 yv = make_float4(d0 * inv * wv.x + bv.x, d1 * inv * wv.y + bv.y,
                            d2 * inv * wv.z + bv.z, d3 * inv * wv.w + bv.w);
    float sy = yv.x * yv.x + yv.y * yv.y + yv.z * yv.z + yv.w * yv.w;
    sy = block_sum<128>(sy);
    float ny = sqrtf(fmaxf(sy, EPSf * EPSf));
    float es = tanhf(ny) / ny;
    float tb = tanhf(ny);
    float cb = fminf(fmaxf(tb, EPSf), MAXNf);
    float s2 = atanh_f(cb) / cb;
    float sc = es * s2;
    store_split4(hi, lo, (size_t)r * Dn + tid * 4,
                 make_float4(sc * yv.x, sc * yv.y, sc * yv.z, sc * yv.w));
}

// fused-QKV post: blockIdx.y = 0(Q) / 1(K) / 2(V); reads u[M,1536]
__global__ void __launch_bounds__(128)
k_post_qkv3(const float* __restrict__ u, float* __restrict__ q, float* __restrict__ k,
            float* __restrict__ lamv, float* __restrict__ lm1, float ratio) {
    int which = blockIdx.y;
    int r = blockIdx.x, tid = threadIdx.x;
    int b = r / Sn, s = r % Sn;
    float4 uv = *(const float4*)(u + (size_t)r * (3 * Dn) + which * Dn + tid * 4);
    float ss = uv.x * uv.x + uv.y * uv.y + uv.z * uv.z + uv.w * uv.w;
    float bs = block_sum<128>(ss);
    float n  = sqrtf(fmaxf(bs, EPSf * EPSf));
    float s1 = tanhf(n) / n;
    float t  = tanhf(n);
    float c  = fminf(fmaxf(t, EPSf), MAXNf);
    float s2 = atanh_f(c) / c;
    float sc = s1 * s2 * ratio;
    float4 th = make_float4(sc * uv.x, sc * uv.y, sc * uv.z, sc * uv.w);
    float hs = sc * sc * ss;
    hs = group16_sum(hs);
    float nh = sqrtf(fmaxf(hs, EPSf * EPSf));
    float es = tanhf(nh) / nh;
    int h = tid >> 4;
    size_t dst = ((size_t)(b * Hn + h) * Sn + s) * HDn + (tid & 15) * 4;
    if (which == 0) {
        *(float4*)(q + dst) = make_float4(es * th.x, es * th.y, es * th.z, es * th.w);
    } else if (which == 1) {
        *(float4*)(k + dst) = make_float4(es * th.x, es * th.y, es * th.z, es * th.w);
    } else {
        float vsq = es * es * hs;
        float lam = 2.f / fmaxf(1.f - vsq, EPSf);
        float ls2 = lam * es;
        *(float4*)(lamv + dst) = make_float4(ls2 * th.x, ls2 * th.y, ls2 * th.z, ls2 * th.w);
        if ((tid & 15) == 0) lm1[(size_t)(b * Hn + h) * Sn + s] = lam - 1.f;
    }
}

// fused attention: scores + softmax(no-max) + gyromidpoint + scalar-mul/project
__global__ void __launch_bounds__(256)
k_attn(const float* __restrict__ qh, const float* __restrict__ kh,
       const float* __restrict__ lamv, const float* __restrict__ lm1,
       const float* __restrict__ tau, const float* __restrict__ gam, int l,
       float* __restrict__ mid) {
    int it = blockIdx.x, bh = blockIdx.y;
    extern __shared__ float sma[];
    float* Qs  = sma;
    float* Ks  = Qs + 64 * 68;
    float* Ps  = Ks + 64 * 68;
    float* Lv  = Ps + 64 * 68;
    float* q2  = Lv + 64 * 68;
    float* k2  = q2 + 64;
    float* lms = k2 + 64;
    int tid = threadIdx.x, tx = tid & 15, ty = tid >> 4;

    const float* Q = qh + ((size_t)bh * Sn + it * 64) * HDn;
    for (int f = tid; f < 1024; f += 256) {
        int row = f >> 4, c = (f & 15) * 4;
        float4 v = *(const float4*)(Q + row * HDn + c);
        Qs[(c + 0) * 68 + row] = v.x; Qs[(c + 1) * 68 + row] = v.y;
        Qs[(c + 2) * 68 + row] = v.z; Qs[(c + 3) * 68 + row] = v.w;
    }
    __syncthreads();
    if (tid < 64) {
        float s = 0.f;
        for (int d = 0; d < HDn; d++) { float a = Qs[d * 68 + tid]; s += a * a; }
        q2[tid] = s;
    }
    float tv = tau[l], gv = gam[l];
    float acc[4][4] = {};
    float dac[4] = {};
    float ssum[4] = {};

    for (int jt = 0; jt <= it; jt++) {
        __syncthreads();
        const float* K  = kh   + ((size_t)bh * Sn + jt * 64) * HDn;
        const float* Lg = lamv + ((size_t)bh * Sn + jt * 64) * HDn;
        for (int f = tid; f < 1024; f += 256) {
            int row = f >> 4, c = (f & 15) * 4;
            float4 u = *(const float4*)(K + row * HDn + c);
            Ks[(c + 0) * 68 + row] = u.x; Ks[(c + 1) * 68 + row] = u.y;
            Ks[(c + 2) * 68 + row] = u.z; Ks[(c + 3) * 68 + row] = u.w;
            float4 w = *(const float4*)(Lg + row * HDn + c);
            *(float4*)&Lv[row * 68 + c] = w;
        }
        if (tid < 64) lms[tid] = lm1[(size_t)bh * Sn + jt * 64 + tid];
        __syncthreads();
        if (tid < 64) {
            float s = 0.f;
            for (int d = 0; d < HDn; d++) { float a = Ks[d * 68 + tid]; s += a * a; }
            k2[tid] = s;
        }
        __syncthreads();

        float sacc[4][4] = {};
#pragma unroll 8
        for (int d = 0; d < HDn; d++) {
            float4 av = *(const float4*)&Qs[d * 68 + ty * 4];
            float4 bv = *(const float4*)&Ks[d * 68 + tx * 4];
            float a[4] = {av.x, av.y, av.z, av.w};
            float b[4] = {bv.x, bv.y, bv.z, bv.w};
#pragma unroll
            for (int i = 0; i < 4; i++)
#pragma unroll
                for (int j = 0; j < 4; j++) sacc[i][j] += a[i] * b[j];
        }
        bool diag = (jt == it);
#pragma unroll
        for (int ii = 0; ii < 4; ii++) {
            int i = ty * 4 + ii;
            float qq = q2[i];
#pragma unroll
            for (int jj = 0; jj < 4; jj++) {
                int j = tx * 4 + jj;
                float e;
                if (diag && j > i) e = 0.f;
                else {
                    float kk = k2[j];
                    float d2 = fmaxf(qq + kk - 2.f * sacc[ii][jj], 0.f);
                    float dn = fmaxf((1.f - qq) * (1.f - kk), EPSf);
                    float uu = fmaxf(2.f * d2 / dn, 1.1920929e-7f);
                    float dist = log1pf(uu + sqrtf(uu * (uu + 2.f)));
                    e = expf(-tv * dist - gv);
                }
                Ps[i * 68 + j] = e;
                ssum[ii] += e;
            }
        }
        __syncthreads();
#pragma unroll 4
        for (int j = 0; j < 64; j++) {
            float a0 = Ps[(ty * 4 + 0) * 68 + j];
            float a1 = Ps[(ty * 4 + 1) * 68 + j];
            float a2 = Ps[(ty * 4 + 2) * 68 + j];
            float a3 = Ps[(ty * 4 + 3) * 68 + j];
            float4 lv = *(const float4*)&Lv[j * 68 + tx * 4];
            acc[0][0] += a0 * lv.x; acc[0][1] += a0 * lv.y; acc[0][2] += a0 * lv.z; acc[0][3] += a0 * lv.w;
            acc[1][0] += a1 * lv.x; acc[1][1] += a1 * lv.y; acc[1][2] += a1 * lv.z; acc[1][3] += a1 * lv.w;
            acc[2][0] += a2 * lv.x; acc[2][1] += a2 * lv.y; acc[2][2] += a2 * lv.z; acc[2][3] += a2 * lv.w;
            acc[3][0] += a3 * lv.x; acc[3][1] += a3 * lv.y; acc[3][2] += a3 * lv.z; acc[3][3] += a3 * lv.w;
            float lm = lms[j];
            dac[0] += a0 * lm; dac[1] += a1 * lm; dac[2] += a2 * lm; dac[3] += a3 * lm;
        }
    }

#pragma unroll
    for (int ii = 0; ii < 4; ii++) {
        float rs = ssum[ii];
#pragma unroll
        for (int o = 8; o > 0; o >>= 1) rs += __shfl_xor_sync(0xffffffffu, rs, o);
        float dn = fmaxf(dac[ii], EPSf * rs);
        float inv = 1.f / dn;
        float m0 = acc[ii][0] * inv, m1 = acc[ii][1] * inv;
        float m2 = acc[ii][2] * inv, m3 = acc[ii][3] * inv;
        float ss2 = m0 * m0 + m1 * m1 + m2 * m2 + m3 * m3;
#pragma unroll
        for (int o = 8; o > 0; o >>= 1) ss2 += __shfl_xor_sync(0xffffffffu, ss2, o);
        float n  = sqrtf(fmaxf(ss2, EPSf * EPSf));
        float nc = fminf(fmaxf(n, EPSf), MAXNf);
        float tt = tanhf(0.5f * atanh_f(nc));
        float s1 = tt / nc;
        float ny = sqrtf(fmaxf(s1 * s1 * ss2, EPSf * EPSf));
        float s2 = fminf(1.f, MAXNf / ny);
        float sc = s1 * s2;
        size_t dst = ((size_t)bh * Sn + it * 64 + ty * 4 + ii) * HDn + tx * 4;
        *(float4*)(mid + dst) = make_float4(m0 * sc, m1 * sc, m2 * sc, m3 * sc);
    }
}

__global__ void __launch_bounds__(128)
k_concat2bf(const float* __restrict__ mh, __nv_bfloat16* __restrict__ hi,
            __nv_bfloat16* __restrict__ lo, float ratio) {
    int r = blockIdx.x, tid = threadIdx.x;
    int b = r / Sn, s = r % Sn;
    __shared__ float row[Dn];
    int warp = tid >> 5, lane = tid & 31;
#pragma unroll
    for (int hh = 0; hh < 2; hh++) {
        int h = warp * 2 + hh;
        const float* src = mh + ((size_t)((b * Hn + h) * Sn + s)) * HDn;
        float v0 = src[lane], v1 = src[lane + 32];
        float ss = warp_sum(v0 * v0 + v1 * v1);
        float n  = sqrtf(fmaxf(ss, EPSf * EPSf));
        float nc = fminf(fmaxf(n, EPSf), MAXNf);
        float sc = atanh_f(nc) / nc * ratio;
        row[h * HDn + lane]      = sc * v0;
        row[h * HDn + lane + 32] = sc * v1;
    }
    __syncthreads();
    float4 vl = *(const float4*)&row[tid * 4];
    float ss = vl.x * vl.x + vl.y * vl.y + vl.z * vl.z + vl.w * vl.w;
    ss = block_sum<128>(ss);
    float n  = sqrtf(fmaxf(ss, EPSf * EPSf));
    float es = tanhf(n) / n;
    float tb = tanhf(n);
    float cb = fminf(fmaxf(tb, EPSf), MAXNf);
    float s2 = atanh_f(cb) / cb;
    float sc = es * s2;
    store_split4(hi, lo, (size_t)r * Dn + tid * 4,
                 make_float4(sc * vl.x, sc * vl.y, sc * vl.z, sc * vl.w));
}

__global__ void __launch_bounds__(128)
k_exp_madd(const float* __restrict__ g, float* __restrict__ x) {
    int r = blockIdx.x, tid = threadIdx.x;
    float4 gv = *(const float4*)(g + (size_t)r * Dn + tid * 4);
    float4 xv = *(const float4*)(x + (size_t)r * Dn + tid * 4);
    float lg = gv.x * gv.x + gv.y * gv.y + gv.z * gv.z + gv.w * gv.w;
    float lx = xv.x * xv.x + xv.y * xv.y + xv.z * xv.z + xv.w * xv.w;
    float lxg = xv.x * gv.x + xv.y * gv.y + xv.z * gv.z + xv.w * gv.w;
    float g2 = block_sum<128>(lg);
    float x2 = block_sum<128>(lx);
    float xg = block_sum<128>(lxg);
    float ng = sqrtf(fmaxf(g2, EPSf * EPSf));
    float s  = tanhf(ng) / ng;
    float y2 = s * s * g2;
    float xy = s * xg;
    float den = fmaxf(1.f + 2.f * xy + x2 * y2, EPSf);
    float ca = (1.f + 2.f * xy + y2) / den;
    float cb = (1.f - x2) / den * s;
    float4 zv = make_float4(ca * xv.x + cb * gv.x, ca * xv.y + cb * gv.y,
                            ca * xv.z + cb * gv.z, ca * xv.w + cb * gv.w);
    float n2 = zv.x * zv.x + zv.y * zv.y + zv.z * zv.z + zv.w * zv.w;
    n2 = block_sum<128>(n2);
    float n = sqrtf(fmaxf(n2, EPSf * EPSf));
    float sc = fminf(1.f, MAXNf / n);
    *(float4*)(x + (size_t)r * Dn + tid * 4) =
        make_float4(sc * zv.x, sc * zv.y, sc * zv.z, sc * zv.w);
}

__global__ void __launch_bounds__(256)
k_ffnmid2bf(const float* __restrict__ u, __nv_bfloat16* __restrict__ hi,
            __nv_bfloat16* __restrict__ lo) {
    int r = blockIdx.x, tid = threadIdx.x;
    const float* ur = u + (size_t)r * FFn;
    float4 u0 = *(const float4*)(ur + tid * 4);
    float4 u1 = *(const float4*)(ur + 1024 + tid * 4);
    float ss = u0.x * u0.x + u0.y * u0.y + u0.z * u0.z + u0.w * u0.w
             + u1.x * u1.x + u1.y * u1.y + u1.z * u1.z + u1.w * u1.w;
    ss = block_sum<256>(ss);
    float n0 = sqrtf(fmaxf(ss, EPSf * EPSf));
    float t0 = tanhf(n0);
    float s1 = t0 / n0;
    float c0 = fminf(fmaxf(t0, EPSf), MAXNf);
    float a0 = atanh_f(c0) / c0;
    float w  = a0 * s1;
    float4 r0 = make_float4(fmaxf(w * u0.x, 0.f), fmaxf(w * u0.y, 0.f),
                            fmaxf(w * u0.z, 0.f), fmaxf(w * u0.w, 0.f));
    float4 r1 = make_float4(fmaxf(w * u1.x, 0.f), fmaxf(w * u1.y, 0.f),
                            fmaxf(w * u1.z, 0.f), fmaxf(w * u1.w, 0.f));
    float st = r0.x * r0.x + r0.y * r0.y + r0.z * r0.z + r0.w * r0.w
             + r1.x * r1.x + r1.y * r1.y + r1.z * r1.z + r1.w * r1.w;
    st = block_sum<256>(st);
    float n1 = sqrtf(fmaxf(st, EPSf * EPSf));
    float e1 = tanhf(n1) / n1;
    float t1 = tanhf(n1);
    float c1 = fminf(fmaxf(t1, EPSf), MAXNf);
    float a1 = atanh_f(c1) / c1;
    float sc = a1 * e1;
    store_split4(hi, lo, (size_t)r * FFn + tid * 4,
                 make_float4(sc * r0.x, sc * r0.y, sc * r0.z, sc * r0.w));
    store_split4(hi, lo, (size_t)r * FFn + 1024 + tid * 4,
                 make_float4(sc * r1.x, sc * r1.y, sc * r1.z, sc * r1.w));
}

__global__ void __launch_bounds__(128)
k_log2bf(const float* __restrict__ x, __nv_bfloat16* __restrict__ hi,
         __nv_bfloat16* __restrict__ lo) {
    int r = blockIdx.x, tid = threadIdx.x;
    float4 xv = *(const float4*)(x + (size_t)r * Dn + tid * 4);
    float ss = xv.x * xv.x + xv.y * xv.y + xv.z * xv.z + xv.w * xv.w;
    ss = block_sum<128>(ss);
    float n  = sqrtf(fmaxf(ss, EPSf * EPSf));
    float nc = fminf(fmaxf(n, EPSf), MAXNf);
    float s  = atanh_f(nc) / nc;
    store_split4(hi, lo, (size_t)r * Dn + tid * 4,
                 make_float4(s * xv.x, s * xv.y, s * xv.z, s * xv.w));
}

__global__ void __launch_bounds__(128)
k_expmap_out(const float* __restrict__ x, float* __restrict__ out) {
    int r = blockIdx.x, tid = threadIdx.x;
    float4 xv = *(const float4*)(x + (size_t)r * Dn + tid * 4);
    float ss = xv.x * xv.x + xv.y * xv.y + xv.z * xv.z + xv.w * xv.w;
    ss = block_sum<128>(ss);
    float n = sqrtf(fmaxf(ss, EPSf * EPSf));
    float s = tanhf(n) / n;
    *(float4*)(out + (size_t)r * Dn + tid * 4) =
        make_float4(s * xv.x, s * xv.y, s * xv.z, s * xv.w);
}

// ---------------- host orchestration ----------------
extern "C" void kernel_launch(void* const* d_in, const int* in_sizes, int n_in,
                              void* d_out, int out_size) {
    (void)in_sizes; (void)n_in; (void)out_size;
    const float* x    = (const float*)d_in[0];
    const float* pos  = (const float*)d_in[1];
    const float* ln1w = (const float*)d_in[2];
    const float* ln1b = (const float*)d_in[3];
    const float* ln2w = (const float*)d_in[4];
    const float* ln2b = (const float*)d_in[5];
    const float* Wq   = (const float*)d_in[6];
    const float* bq   = (const float*)d_in[7];
    const float* Wk   = (const float*)d_in[8];
    const float* bk   = (const float*)d_in[9];
    const float* Wv   = (const float*)d_in[10];
    const float* bv   = (const float*)d_in[11];
    const float* Wo   = (const float*)d_in[12];
    const float* bo   = (const float*)d_in[13];
    const float* W1   = (const float*)d_in[14];
    const float* b1   = (const float*)d_in[15];
    const float* W2   = (const float*)d_in[16];
    const float* b2   = (const float*)d_in[17];
    const float* tau  = (const float*)d_in[18];
    const float* gam  = (const float*)d_in[19];
    const float* Wout = (const float*)d_in[20];
    const float* bout = (const float*)d_in[21];
    float* outp = (float*)d_out;

    float *px, *pu, *pq, *pk, *plv, *plm, *pm, *pbq;
    __nv_bfloat16 *pahi, *palo, *pwhi, *pwlo;
    cudaGetSymbolAddress((void**)&px,  g_x);
    cudaGetSymbolAddress((void**)&pu,  g_u);
    cudaGetSymbolAddress((void**)&pq,  g_qh);
    cudaGetSymbolAddress((void**)&pk,  g_kh);
    cudaGetSymbolAddress((void**)&plv, g_lamv);
    cudaGetSymbolAddress((void**)&plm, g_lm1);
    cudaGetSymbolAddress((void**)&pm,  g_mid);
    cudaGetSymbolAddress((void**)&pbq, g_bqkv);
    cudaGetSymbolAddress((void**)&pahi, g_ahi);
    cudaGetSymbolAddress((void**)&palo, g_alo);
    cudaGetSymbolAddress((void**)&pwhi, g_Whi);
    cudaGetSymbolAddress((void**)&pwlo, g_Wlo);

    cudaFuncSetAttribute((const void*)k_gemm_mma,
                         cudaFuncAttributeMaxDynamicSharedMemorySize, GEMM_SMEM);
    constexpr int ATTN_SMEM = (4 * 64 * 68 + 3 * 64) * 4;
    cudaFuncSetAttribute((const void*)k_attn,
                         cudaFuncAttributeMaxDynamicSharedMemorySize, ATTN_SMEM);

    double betaD  = std::exp(std::lgamma(Dn / 2.0)  + std::lgamma(0.5) - std::lgamma(Dn / 2.0 + 0.5));
    double betaHD = std::exp(std::lgamma(HDn / 2.0) + std::lgamma(0.5) - std::lgamma(HDn / 2.0 + 0.5));
    float ratio_split = (float)(betaHD / betaD);
    float ratio_cat   = (float)(betaD / betaHD);

    // ---- convert all weights + fused biases once ----
    constexpr int DD = Dn * Dn, FD = FFn * Dn;
    WCvtArgs wa;
    int idx = 0;
    auto add = [&](const float* s, long long off, int n) {
        wa.src[idx] = s; wa.off[idx] = off; wa.n4[idx] = n / 4; idx++;
    };
    for (int l = 0; l < Ln; l++) {
        long long base = l * WLL;
        add(Wq + (size_t)l * DD, base,              DD);
        add(Wk + (size_t)l * DD, base + DD,         DD);
        add(Wv + (size_t)l * DD, base + 2 * DD,     DD);
        add(Wo + (size_t)l * DD, base + 3 * DD,     DD);
        add(W1 + (size_t)l * FD, base + 4 * DD,     FD);
        add(W2 + (size_t)l * FD, base + 4 * DD + FD, FD);
    }
    add(Wout, 4 * WLL, DD);
    k_wcvt<<<dim3(1024, 25), 256>>>(wa, pwhi, pwlo);
    k_bfill<<<dim3(6, Ln), 256>>>(bq, bk, bv, pbq);

    auto gemm = [&](long long woff, const float* bias, float* Cout, int Ni, int Ki) {
        k_gemm_mma<<<dim3(Ni / 64, Mn / 64), 128, GEMM_SMEM>>>(
            pahi, palo, pwhi + woff, pwlo + woff, bias, Cout, Ni, Ki);
    };

    k_mobius_add<128><<<Mn, 128>>>(x, pos, px, Sn);

    for (int l = 0; l < Ln; l++) {
        long long base = l * WLL;
        // ---- attention ----
        k_pln2bf<<<Mn, 128>>>(px, ln1w + l * Dn, ln1b + l * Dn, pahi, palo);
        gemm(base, pbq + l * 3 * Dn, pu, 3 * Dn, Dn);   // fused QKV
        k_post_qkv3<<<dim3(Mn, 3), 128>>>(pu, pq, pk, plv, plm, ratio_split);

        k_attn<<<dim3(Sn / 64, BHn), 256, ATTN_SMEM>>>(pq, pk, plv, plm, tau, gam, l, pm);

        k_concat2bf<<<Mn, 128>>>(pm, pahi, palo, ratio_cat);
        gemm(base + 3 * DD, bo + l * Dn, pu, Dn, Dn);
        k_exp_madd<<<Mn, 128>>>(pu, px);

        // ---- FFN ----
        k_pln2bf<<<Mn, 128>>>(px, ln2w + l * Dn, ln2b + l * Dn, pahi, palo);
        gemm(base + 4 * DD, b1 + l * FFn, pu, FFn, Dn);
        k_ffnmid2bf<<<Mn, 256>>>(pu, pahi, palo);
        gemm(base + 4 * DD + FD, b2 + l * Dn, pu, Dn, FFn);
        k_exp_madd<<<Mn, 128>>>(pu, px);
    }

    // ---- head ----
    k_log2bf<<<Mn, 128>>>(px, pahi, palo);
    gemm(4 * WLL, bout, pu, Dn, Dn);
    k_expmap_out<<<Mn, 128>>>(pu, outp);
}

// round 9
// speedup vs baseline: 2.5097x; 1.2662x over previous
#include <cuda_runtime.h>
#include <cuda_bf16.h>
#include <cstdint>
#include <cmath>

// ---------------- problem constants ----------------
constexpr int Bn  = 2;
constexpr int Sn  = 1024;
constexpr int Dn  = 512;
constexpr int Hn  = 8;
constexpr int HDn = 64;
constexpr int FFn = 2048;
constexpr int Ln  = 4;
constexpr int Mn  = Bn * Sn;   // 2048
constexpr int BHn = Bn * Hn;   // 16
constexpr long long WLL = 4LL * Dn * Dn + 2LL * FFn * Dn;

#define EPSf   1e-7f
#define MAXNf  (1.0f - 1e-3f)

// ---------------- scratch ----------------
__device__ float g_x   [Mn * Dn];
__device__ float g_u   [Mn * FFn];
__device__ float g_mid [Mn * Dn];
__device__ float g_qf  [Mn * Dn];
__device__ float g_kf  [Mn * Dn];
__device__ float g_bqkv[Ln * 3 * Dn];
__device__ float g_q2  [BHn * Sn];
__device__ float g_k2  [BHn * Sn];
__device__ float g_lm1 [BHn * Sn];
__device__ __nv_bfloat16 g_lvh[Mn * Dn];
__device__ __nv_bfloat16 g_lvl[Mn * Dn];
__device__ __nv_bfloat16 g_ahi[Mn * FFn];
__device__ __nv_bfloat16 g_alo[Mn * FFn];
__device__ __nv_bfloat16 g_Whi[4 * WLL + Dn * Dn];
__device__ __nv_bfloat16 g_Wlo[4 * WLL + Dn * Dn];

// ---------------- PTX helpers ----------------
static __device__ __forceinline__ uint32_t smem_u32(const void* p) {
    return (uint32_t)__cvta_generic_to_shared(p);
}
static __device__ __forceinline__ void cp16(uint32_t dst, const void* src) {
    asm volatile("cp.async.cg.shared.global [%0], [%1], 16;" :: "r"(dst), "l"(src));
}
static __device__ __forceinline__ void cp_commit() {
    asm volatile("cp.async.commit_group;" ::: "memory");
}
template<int N>
static __device__ __forceinline__ void cp_wait() {
    asm volatile("cp.async.wait_group %0;" :: "n"(N) : "memory");
}
static __device__ __forceinline__ void ldm4(uint32_t* r, uint32_t addr) {
    asm volatile("ldmatrix.sync.aligned.m8n8.x4.shared.b16 {%0,%1,%2,%3}, [%4];"
                 : "=r"(r[0]), "=r"(r[1]), "=r"(r[2]), "=r"(r[3]) : "r"(addr));
}
static __device__ __forceinline__ void ldm4t(uint32_t* r, uint32_t addr) {
    asm volatile("ldmatrix.sync.aligned.m8n8.x4.trans.shared.b16 {%0,%1,%2,%3}, [%4];"
                 : "=r"(r[0]), "=r"(r[1]), "=r"(r[2]), "=r"(r[3]) : "r"(addr));
}
static __device__ __forceinline__ void mma16816(float* d, const uint32_t* a, const uint32_t* b) {
    asm volatile("mma.sync.aligned.m16n8k16.row.col.f32.bf16.bf16.f32 "
                 "{%0,%1,%2,%3}, {%4,%5,%6,%7}, {%8,%9}, {%0,%1,%2,%3};"
                 : "+f"(d[0]), "+f"(d[1]), "+f"(d[2]), "+f"(d[3])
                 : "r"(a[0]), "r"(a[1]), "r"(a[2]), "r"(a[3]), "r"(b[0]), "r"(b[1]));
}

// ---------------- math helpers ----------------
static __device__ __forceinline__ float atanh_f(float x) {
    return 0.5f * (log1pf(x) - log1pf(-x));
}
template<int NT>
__device__ __forceinline__ float block_sum(float v) {
    __shared__ float sh[NT / 32];
#pragma unroll
    for (int o = 16; o > 0; o >>= 1) v += __shfl_xor_sync(0xffffffffu, v, o);
    int w = threadIdx.x >> 5;
    if ((threadIdx.x & 31) == 0) sh[w] = v;
    __syncthreads();
    float r = sh[0];
#pragma unroll
    for (int i = 1; i < NT / 32; i++) r += sh[i];
    __syncthreads();
    return r;
}
__device__ __forceinline__ float warp_sum(float v) {
#pragma unroll
    for (int o = 16; o > 0; o >>= 1) v += __shfl_xor_sync(0xffffffffu, v, o);
    return v;
}
__device__ __forceinline__ float group16_sum(float v) {
#pragma unroll
    for (int o = 8; o > 0; o >>= 1) v += __shfl_xor_sync(0xffffffffu, v, o);
    return v;
}
static __device__ __forceinline__ void store_split4(__nv_bfloat16* hi, __nv_bfloat16* lo,
                                                    size_t idx, float4 v) {
    __nv_bfloat16 h0 = __float2bfloat16(v.x), h1 = __float2bfloat16(v.y);
    __nv_bfloat16 h2 = __float2bfloat16(v.z), h3 = __float2bfloat16(v.w);
    __nv_bfloat16 l0 = __float2bfloat16(v.x - __bfloat162float(h0));
    __nv_bfloat16 l1 = __float2bfloat16(v.y - __bfloat162float(h1));
    __nv_bfloat16 l2 = __float2bfloat16(v.z - __bfloat162float(h2));
    __nv_bfloat16 l3 = __float2bfloat16(v.w - __bfloat162float(h3));
    ((__nv_bfloat162*)(hi + idx))[0] = __halves2bfloat162(h0, h1);
    ((__nv_bfloat162*)(hi + idx))[1] = __halves2bfloat162(h2, h3);
    ((__nv_bfloat162*)(lo + idx))[0] = __halves2bfloat162(l0, l1);
    ((__nv_bfloat162*)(lo + idx))[1] = __halves2bfloat162(l2, l3);
}

// ---------------- weight conversion ----------------
struct WCvtArgs {
    const float* src[25];
    long long    off[25];
    int          n4[25];
};
__global__ void k_wcvt(WCvtArgs a, __nv_bfloat16* __restrict__ hi, __nv_bfloat16* __restrict__ lo) {
    int t = blockIdx.y;
    int i = blockIdx.x * blockDim.x + threadIdx.x;
    if (i >= a.n4[t]) return;
    float4 v = ((const float4*)a.src[t])[i];
    store_split4(hi, lo, (size_t)a.off[t] + 4 * (size_t)i, v);
}
__global__ void k_bfill(const float* __restrict__ bq, const float* __restrict__ bk,
                        const float* __restrict__ bv, float* __restrict__ out) {
    int l = blockIdx.y;
    int i = blockIdx.x * blockDim.x + threadIdx.x;
    float v;
    if (i < Dn)            v = bq[l * Dn + i];
    else if (i < 2 * Dn)   v = bk[l * Dn + i - Dn];
    else                   v = bv[l * Dn + i - 2 * Dn];
    out[l * 3 * Dn + i] = v;
}

// ---------------- HMMA GEMM (3-pass split-bf16, 2-stage, 2 CTA/SM) ----------------
constexpr int LDS = 72;
constexpr int STAGE_E = 4 * 64 * LDS;
constexpr int GEMM_SMEM = 2 * STAGE_E * 2;   // 73728 B

__global__ void __launch_bounds__(128, 2)
k_gemm_mma(const __nv_bfloat16* __restrict__ Ahi, const __nv_bfloat16* __restrict__ Alo,
           const __nv_bfloat16* __restrict__ Whi, const __nv_bfloat16* __restrict__ Wlo,
           const float* __restrict__ bias, float* __restrict__ C, int Ni, int Ki)
{
    extern __shared__ __nv_bfloat16 sm[];
    const int tid = threadIdx.x, wid = tid >> 5, lane = tid & 31;
    const int bm = blockIdx.y * 64, bn = blockIdx.x * 64;
    const int wm = (wid >> 1) * 32, wn = (wid & 1) * 32;
    const uint32_t sbase = smem_u32(sm);

    float acc[2][4][4];
#pragma unroll
    for (int a = 0; a < 2; a++)
#pragma unroll
        for (int b = 0; b < 4; b++)
#pragma unroll
            for (int c = 0; c < 4; c++) acc[a][b][c] = 0.f;

    const int NC = Ki >> 6;

    auto load_stage = [&](int c) {
        const uint32_t sb = sbase + (uint32_t)(c & 1) * STAGE_E * 2;
        const size_t k0 = (size_t)c * 64;
#pragma unroll
        for (int i = tid; i < 512; i += 128) {
            int row = i >> 3, seg = i & 7;
            const size_t gA = (size_t)(bm + row) * Ki + k0 + seg * 8;
            const size_t gB = (size_t)(bn + row) * Ki + k0 + seg * 8;
            uint32_t ro = (uint32_t)(row * LDS + seg * 8) * 2;
            cp16(sb + ro,                 Ahi + gA);
            cp16(sb + 64 * LDS * 2 + ro,  Alo + gA);
            cp16(sb + 128 * LDS * 2 + ro, Whi + gB);
            cp16(sb + 192 * LDS * 2 + ro, Wlo + gB);
        }
        cp_commit();
    };

    uint32_t ah[2][2][4], al[2][2][4], bh[2][4][2], bl[2][4][2];
    auto ldfrag = [&](uint32_t sb, int kk, int bf) {
        uint32_t koff = (uint32_t)(kk * 16) * 2 + (lane >> 4) * 16;
#pragma unroll
        for (int mt = 0; mt < 2; mt++) {
            uint32_t rA = (uint32_t)(wm + mt * 16 + (lane & 15));
            ldm4(ah[bf][mt], sb + rA * (LDS * 2) + koff);
            ldm4(al[bf][mt], sb + (64 + rA) * (LDS * 2) + koff);
        }
#pragma unroll
        for (int nt2 = 0; nt2 < 2; nt2++) {
            uint32_t rB = (uint32_t)(128 + wn + nt2 * 16 + (lane & 15));
            uint32_t t[4];
            ldm4(t, sb + rB * (LDS * 2) + koff);
            bh[bf][nt2 * 2][0] = t[0]; bh[bf][nt2 * 2 + 1][0] = t[1];
            bh[bf][nt2 * 2][1] = t[2]; bh[bf][nt2 * 2 + 1][1] = t[3];
            ldm4(t, sb + (64 + rB) * (LDS * 2) + koff);
            bl[bf][nt2 * 2][0] = t[0]; bl[bf][nt2 * 2 + 1][0] = t[1];
            bl[bf][nt2 * 2][1] = t[2]; bl[bf][nt2 * 2 + 1][1] = t[3];
        }
    };

    load_stage(0);
    if (NC > 1) load_stage(1);

    for (int c = 0; c < NC; c++) {
        const uint32_t sb = sbase + (uint32_t)(c & 1) * STAGE_E * 2;
        cp_wait<1>();
        __syncthreads();

        ldfrag(sb, 0, 0);
#pragma unroll
        for (int kk = 0; kk < 4; kk++) {
            const int cur = kk & 1, nxt = cur ^ 1;
            if (kk < 3) ldfrag(sb, kk + 1, nxt);
#pragma unroll
            for (int mt = 0; mt < 2; mt++)
#pragma unroll
                for (int nt = 0; nt < 4; nt++)
                    mma16816(acc[mt][nt], ah[cur][mt], bh[cur][nt]);
#pragma unroll
            for (int mt = 0; mt < 2; mt++)
#pragma unroll
                for (int nt = 0; nt < 4; nt++)
                    mma16816(acc[mt][nt], ah[cur][mt], bl[cur][nt]);
#pragma unroll
            for (int mt = 0; mt < 2; mt++)
#pragma unroll
                for (int nt = 0; nt < 4; nt++)
                    mma16816(acc[mt][nt], al[cur][mt], bh[cur][nt]);
        }
        __syncthreads();
        if (c + 2 < NC) load_stage(c + 2);
    }

#pragma unroll
    for (int mt = 0; mt < 2; mt++) {
        int r0 = bm + wm + mt * 16 + (lane >> 2);
#pragma unroll
        for (int nt = 0; nt < 4; nt++) {
            int col = bn + wn + nt * 8 + 2 * (lane & 3);
            float b0 = bias[col], b1 = bias[col + 1];
            float2 v0 = make_float2(acc[mt][nt][0] + b0, acc[mt][nt][1] + b1);
            float2 v1 = make_float2(acc[mt][nt][2] + b0, acc[mt][nt][3] + b1);
            *(float2*)(C + (size_t)r0 * Ni + col) = v0;
            *(float2*)(C + (size_t)(r0 + 8) * Ni + col) = v1;
        }
    }
}

// ---------------- fused elementwise kernels ----------------

template<int NT>
__global__ void k_mobius_add(const float* __restrict__ x, const float* __restrict__ y,
                             float* __restrict__ out, int ymod) {
    constexpr int P = Dn / NT;
    int r = blockIdx.x;
    const float* xr = x + (size_t)r * Dn;
    const float* yr = y + (size_t)(r % ymod) * Dn;
    float xl[P], yl[P];
    float x2 = 0.f, y2 = 0.f, xy = 0.f;
#pragma unroll
    for (int i = 0; i < P; i++) {
        int j = threadIdx.x + i * NT;
        xl[i] = xr[j]; yl[i] = yr[j];
        x2 += xl[i] * xl[i]; y2 += yl[i] * yl[i]; xy += xl[i] * yl[i];
    }
    x2 = block_sum<NT>(x2);
    y2 = block_sum<NT>(y2);
    xy = block_sum<NT>(xy);
    float den = fmaxf(1.f + 2.f * xy + x2 * y2, EPSf);
    float ca = (1.f + 2.f * xy + y2) / den;
    float cb = (1.f - x2) / den;
    float zl[P]; float n2 = 0.f;
#pragma unroll
    for (int i = 0; i < P; i++) { zl[i] = ca * xl[i] + cb * yl[i]; n2 += zl[i] * zl[i]; }
    n2 = block_sum<NT>(n2);
    float n = sqrtf(fmaxf(n2, EPSf * EPSf));
    float sc = fminf(1.f, MAXNf / n);
#pragma unroll
    for (int i = 0; i < P; i++) out[(size_t)r * Dn + threadIdx.x + i * NT] = zl[i] * sc;
}

__global__ void __launch_bounds__(128)
k_pln2bf(const float* __restrict__ x, const float* __restrict__ w, const float* __restrict__ b,
         __nv_bfloat16* __restrict__ hi, __nv_bfloat16* __restrict__ lo) {
    int r = blockIdx.x, tid = threadIdx.x;
    const float* xr = x + (size_t)r * Dn;
    float4 xv = *(const float4*)(xr + tid * 4);
    float ss = xv.x * xv.x + xv.y * xv.y + xv.z * xv.z + xv.w * xv.w;
    ss = block_sum<128>(ss);
    float n  = sqrtf(fmaxf(ss, EPSf * EPSf));
    float nc = fminf(fmaxf(n, EPSf), MAXNf);
    float ls = atanh_f(nc) / nc;
    float4 tl = make_float4(ls * xv.x, ls * xv.y, ls * xv.z, ls * xv.w);
    float st = tl.x + tl.y + tl.z + tl.w;
    st = block_sum<128>(st);
    float mu = st / (float)Dn;
    float d0 = tl.x - mu, d1 = tl.y - mu, d2 = tl.z - mu, d3 = tl.w - mu;
    float sv = d0 * d0 + d1 * d1 + d2 * d2 + d3 * d3;
    sv = block_sum<128>(sv);
    float inv = rsqrtf(sv / (float)Dn + 1e-5f);
    float4 wv = *(const float4*)(w + tid * 4);
    float4 bv = *(const float4*)(b + tid * 4);
    float4 yv = make_float4(d0 * inv * wv.x + bv.x, d1 * inv * wv.y + bv.y,
                            d2 * inv * wv.z + bv.z, d3 * inv * wv.w + bv.w);
    float sy = yv.x * yv.x + yv.y * yv.y + yv.z * yv.z + yv.w * yv.w;
    sy = block_sum<128>(sy);
    float ny = sqrtf(fmaxf(sy, EPSf * EPSf));
    float es = tanhf(ny) / ny;
    float tb = tanhf(ny);
    float cb = fminf(fmaxf(tb, EPSf), MAXNf);
    float s2 = atanh_f(cb) / cb;
    float sc = es * s2;
    store_split4(hi, lo, (size_t)r * Dn + tid * 4,
                 make_float4(sc * yv.x, sc * yv.y, sc * yv.z, sc * yv.w));
}

// fused-QKV post: Q/K -> fp32 (+q2/k2), V -> lamv bf16 hi/lo (+lm1)
__global__ void __launch_bounds__(128)
k_post_qkv3(const float* __restrict__ u,
            float* __restrict__ qf, float* __restrict__ kf,
            __nv_bfloat16* __restrict__ lvh, __nv_bfloat16* __restrict__ lvl,
            float* __restrict__ q2g, float* __restrict__ k2g, float* __restrict__ lmg,
            float ratio) {
    int which = blockIdx.y;
    int r = blockIdx.x, tid = threadIdx.x;
    int b = r / Sn, s = r % Sn;
    float4 uv = *(const float4*)(u + (size_t)r * (3 * Dn) + which * Dn + tid * 4);
    float ss = uv.x * uv.x + uv.y * uv.y + uv.z * uv.z + uv.w * uv.w;
    float bs = block_sum<128>(ss);
    float n  = sqrtf(fmaxf(bs, EPSf * EPSf));
    float s1 = tanhf(n) / n;
    float t  = tanhf(n);
    float c  = fminf(fmaxf(t, EPSf), MAXNf);
    float s2 = atanh_f(c) / c;
    float sc = s1 * s2 * ratio;
    float4 th = make_float4(sc * uv.x, sc * uv.y, sc * uv.z, sc * uv.w);
    float hs = sc * sc * ss;
    hs = group16_sum(hs);
    float nh = sqrtf(fmaxf(hs, EPSf * EPSf));
    float es = tanhf(nh) / nh;
    int h = tid >> 4;
    size_t row = (size_t)(b * Hn + h) * Sn + s;
    size_t dst = row * HDn + (tid & 15) * 4;
    if (which == 0) {
        *(float4*)(qf + dst) = make_float4(es * th.x, es * th.y, es * th.z, es * th.w);
        if ((tid & 15) == 0) q2g[row] = es * es * hs;
    } else if (which == 1) {
        *(float4*)(kf + dst) = make_float4(es * th.x, es * th.y, es * th.z, es * th.w);
        if ((tid & 15) == 0) k2g[row] = es * es * hs;
    } else {
        float vsq = es * es * hs;
        float lam = 2.f / fmaxf(1.f - vsq, EPSf);
        float ls2 = lam * es;
        store_split4(lvh, lvl, dst, make_float4(ls2 * th.x, ls2 * th.y, ls2 * th.z, ls2 * th.w));
        if ((tid & 15) == 0) lmg[row] = lam - 1.f;
    }
}

// ---------------- fused attention: fp32 SIMT scores + HMMA PV ----------------
constexpr int ALD = 72;   // bf16 row stride (144 B)
constexpr int O_QS  = 0;           // fp32 [64][68]
constexpr int O_KS  = 17408;       // fp32 [64][68] (aliased as NUM post-loop)
constexpr int O_LVH = 34816;       // bf16 [64][72]
constexpr int O_LVL = 44032;
constexpr int O_PHI = 53248;
constexpr int O_PLO = 62464;
constexpr int O_Q2  = 71680;
constexpr int O_K2  = 71936;
constexpr int O_LMS = 72192;
constexpr int O_RS  = 72448;
constexpr int O_DS  = 72704;
constexpr int O_INV = 72960;
constexpr int ATT2_SMEM = 73216;

__global__ void __launch_bounds__(256)
k_attn2(const float* __restrict__ qf, const float* __restrict__ kf,
        const __nv_bfloat16* __restrict__ lvh, const __nv_bfloat16* __restrict__ lvl,
        const float* __restrict__ q2g, const float* __restrict__ k2g,
        const float* __restrict__ lmg,
        const float* __restrict__ tau, const float* __restrict__ gam, int l,
        float* __restrict__ mid)
{
    extern __shared__ char smb[];
    float* smf = (float*)smb;
    const uint32_t sb = smem_u32(smb);
    const int tid = threadIdx.x, wid = tid >> 5, lane = tid & 31;
    const int tx = tid & 15, ty = tid >> 4;
    const int bh = blockIdx.y;
    const int wm = (wid >> 1) * 16, wn = (wid & 1) * 32;
    const float tv = tau[l], gv = gam[l];

    for (int p = 0; p < 2; p++) {
        const int it = p ? (15 - (int)blockIdx.x) : (int)blockIdx.x;

        {   // Q -> transposed fp32 smem [d][i], q2
            const float* Q = qf + ((size_t)bh * Sn + it * 64) * HDn;
#pragma unroll
            for (int f = tid; f < 1024; f += 256) {
                int row = f >> 4, c = (f & 15) * 4;
                float4 v = *(const float4*)(Q + row * HDn + c);
                smf[(c + 0) * 68 + row] = v.x; smf[(c + 1) * 68 + row] = v.y;
                smf[(c + 2) * 68 + row] = v.z; smf[(c + 3) * 68 + row] = v.w;
            }
            if (tid < 64) smf[O_Q2 / 4 + tid] = q2g[(size_t)bh * Sn + it * 64 + tid];
        }
        float acc2[4][4];
#pragma unroll
        for (int a = 0; a < 4; a++)
#pragma unroll
            for (int c = 0; c < 4; c++) acc2[a][c] = 0.f;
        float ssum[4] = {0.f, 0.f, 0.f, 0.f};
        float dac[4]  = {0.f, 0.f, 0.f, 0.f};
        __syncthreads();

        for (int jt = 0; jt <= it; jt++) {
            {   // K -> transposed fp32 smem [d][j]; lamv bf16 hi/lo; k2/lms
                const float* K = kf + ((size_t)bh * Sn + jt * 64) * HDn;
#pragma unroll
                for (int f = tid; f < 1024; f += 256) {
                    int row = f >> 4, c = (f & 15) * 4;
                    float4 v = *(const float4*)(K + row * HDn + c);
                    smf[O_KS / 4 + (c + 0) * 68 + row] = v.x;
                    smf[O_KS / 4 + (c + 1) * 68 + row] = v.y;
                    smf[O_KS / 4 + (c + 2) * 68 + row] = v.z;
                    smf[O_KS / 4 + (c + 3) * 68 + row] = v.w;
                }
                const size_t rb = ((size_t)bh * Sn + jt * 64) * HDn;
#pragma unroll
                for (int i = tid; i < 512; i += 256) {
                    int row = i >> 3, seg = i & 7;
                    uint32_t ro = (uint32_t)(row * ALD + seg * 8) * 2;
                    cp16(sb + O_LVH + ro, lvh + rb + row * HDn + seg * 8);
                    cp16(sb + O_LVL + ro, lvl + rb + row * HDn + seg * 8);
                }
                cp_commit();
                if (tid < 64) {
                    smf[O_K2 / 4 + tid]  = k2g[(size_t)bh * Sn + jt * 64 + tid];
                    smf[O_LMS / 4 + tid] = lmg[(size_t)bh * Sn + jt * 64 + tid];
                }
            }
            cp_wait<0>();
            __syncthreads();

            // ---- SIMT fp32 QK^T ----
            float sacc[4][4] = {};
#pragma unroll 8
            for (int d = 0; d < HDn; d++) {
                float4 av = *(const float4*)&smf[d * 68 + ty * 4];
                float4 bv = *(const float4*)&smf[O_KS / 4 + d * 68 + tx * 4];
                float a[4] = {av.x, av.y, av.z, av.w};
                float b[4] = {bv.x, bv.y, bv.z, bv.w};
#pragma unroll
                for (int i = 0; i < 4; i++)
#pragma unroll
                    for (int j = 0; j < 4; j++) sacc[i][j] += a[i] * b[j];
            }

            // ---- exact fp32 score transform + bf16-split P + row partials ----
            const bool diag = (jt == it);
#pragma unroll
            for (int ii = 0; ii < 4; ii++) {
                int i = ty * 4 + ii;
                float qq = smf[O_Q2 / 4 + i];
                float e[4];
#pragma unroll
                for (int jj = 0; jj < 4; jj++) {
                    int j = tx * 4 + jj;
                    if (diag && j > i) { e[jj] = 0.f; continue; }
                    float kk = smf[O_K2 / 4 + j];
                    float d2 = fmaxf(qq + kk - 2.f * sacc[ii][jj], 0.f);
                    float dn = fmaxf((1.f - qq) * (1.f - kk), EPSf);
                    float uu = fmaxf(2.f * d2 / dn, 1.1920929e-7f);
                    float dist = log1pf(uu + sqrtf(uu * (uu + 2.f)));
                    e[jj] = expf(-tv * dist - gv);
                    ssum[ii] += e[jj];
                    dac[ii]  += e[jj] * smf[O_LMS / 4 + j];
                }
                __nv_bfloat16 h0 = __float2bfloat16(e[0]), h1 = __float2bfloat16(e[1]);
                __nv_bfloat16 h2 = __float2bfloat16(e[2]), h3 = __float2bfloat16(e[3]);
                uint32_t po = (uint32_t)(i * ALD + tx * 4) * 2;
                *(__nv_bfloat162*)(smb + O_PHI + po)     = __halves2bfloat162(h0, h1);
                *(__nv_bfloat162*)(smb + O_PHI + po + 4) = __halves2bfloat162(h2, h3);
                *(__nv_bfloat162*)(smb + O_PLO + po)     = __halves2bfloat162(
                    __float2bfloat16(e[0] - __bfloat162float(h0)),
                    __float2bfloat16(e[1] - __bfloat162float(h1)));
                *(__nv_bfloat162*)(smb + O_PLO + po + 4) = __halves2bfloat162(
                    __float2bfloat16(e[2] - __bfloat162float(h2)),
                    __float2bfloat16(e[3] - __bfloat162float(h3)));
            }
            __syncthreads();

            // ---- HMMA PV: acc2 += P · λv (3-pass split) ----
#pragma unroll
            for (int kk = 0; kk < 4; kk++) {
                uint32_t koff = (uint32_t)(kk * 16) * 2 + (lane >> 4) * 16;
                uint32_t ph[4], pl[4], vh_[4][2], vl_[4][2];
                uint32_t rA = (uint32_t)(wm + (lane & 15));
                ldm4(ph, sb + O_PHI + rA * (ALD * 2) + koff);
                ldm4(pl, sb + O_PLO + rA * (ALD * 2) + koff);
#pragma unroll
                for (int q = 0; q < 2; q++) {
                    uint32_t row = (uint32_t)(kk * 16 + (lane & 15));
                    uint32_t col = (uint32_t)(wn + q * 16 + ((lane >> 4) << 3));
                    uint32_t t[4];
                    ldm4t(t, sb + O_LVH + (row * ALD + col) * 2);
                    vh_[q * 2][0] = t[0]; vh_[q * 2][1] = t[1];
                    vh_[q * 2 + 1][0] = t[2]; vh_[q * 2 + 1][1] = t[3];
                    ldm4t(t, sb + O_LVL + (row * ALD + col) * 2);
                    vl_[q * 2][0] = t[0]; vl_[q * 2][1] = t[1];
                    vl_[q * 2 + 1][0] = t[2]; vl_[q * 2 + 1][1] = t[3];
                }
#pragma unroll
                for (int nt = 0; nt < 4; nt++) mma16816(acc2[nt], ph, vh_[nt]);
#pragma unroll
                for (int nt = 0; nt < 4; nt++) mma16816(acc2[nt], ph, vl_[nt]);
#pragma unroll
                for (int nt = 0; nt < 4; nt++) mma16816(acc2[nt], pl, vh_[nt]);
            }
            __syncthreads();
        }

        // ---- row sums (reduce across tx within half-warp) ----
#pragma unroll
        for (int ii = 0; ii < 4; ii++) {
            float v = ssum[ii], w = dac[ii];
#pragma unroll
            for (int o = 8; o > 0; o >>= 1) {
                v += __shfl_xor_sync(0xffffffffu, v, o);
                w += __shfl_xor_sync(0xffffffffu, w, o);
            }
            if (tx == 0) {
                smf[O_RS / 4 + ty * 4 + ii] = v;
                smf[O_DS / 4 + ty * 4 + ii] = w;
            }
        }
        __syncthreads();
        if (tid < 64)
            smf[O_INV / 4 + tid] = __fdividef(
                1.f, fmaxf(smf[O_DS / 4 + tid], EPSf * smf[O_RS / 4 + tid]));
        __syncthreads();

        // ---- num = acc2 * inv -> NUM smem (alias Ks region) ----
        {
            int r0 = wm + (lane >> 2);
            float i0 = smf[O_INV / 4 + r0], i1 = smf[O_INV / 4 + r0 + 8];
#pragma unroll
            for (int nt = 0; nt < 4; nt++) {
                int c0 = wn + nt * 8 + 2 * (lane & 3);
                smf[O_KS / 4 + r0 * 68 + c0]           = acc2[nt][0] * i0;
                smf[O_KS / 4 + r0 * 68 + c0 + 1]       = acc2[nt][1] * i0;
                smf[O_KS / 4 + (r0 + 8) * 68 + c0]     = acc2[nt][2] * i1;
                smf[O_KS / 4 + (r0 + 8) * 68 + c0 + 1] = acc2[nt][3] * i1;
            }
        }
        __syncthreads();

        // ---- mobius_scalar_mul(0.5) + project, write mid ----
        {
            int r = tid >> 2, cg = (tid & 3) * 16;
            const float* nr = smf + O_KS / 4 + r * 68 + cg;
            float ss2 = 0.f;
#pragma unroll
            for (int c = 0; c < 16; c++) { float m = nr[c]; ss2 += m * m; }
            ss2 += __shfl_xor_sync(0xffffffffu, ss2, 1);
            ss2 += __shfl_xor_sync(0xffffffffu, ss2, 2);
            float n  = sqrtf(fmaxf(ss2, EPSf * EPSf));
            float nc = fminf(fmaxf(n, EPSf), MAXNf);
            float tt = tanhf(0.5f * atanh_f(nc));
            float s1 = tt / nc;
            float ny = sqrtf(fmaxf(s1 * s1 * ss2, EPSf * EPSf));
            float s2 = fminf(1.f, MAXNf / ny);
            float sc = s1 * s2;
            float* dst = mid + ((size_t)bh * Sn + it * 64 + r) * HDn + cg;
#pragma unroll
            for (int c = 0; c < 16; c += 4)
                *(float4*)(dst + c) = make_float4(sc * nr[c], sc * nr[c + 1],
                                                  sc * nr[c + 2], sc * nr[c + 3]);
        }
        __syncthreads();
    }
}

__global__ void __launch_bounds__(128)
k_concat2bf(const float* __restrict__ mh, __nv_bfloat16* __restrict__ hi,
            __nv_bfloat16* __restrict__ lo, float ratio) {
    int r = blockIdx.x, tid = threadIdx.x;
    int b = r / Sn, s = r % Sn;
    __shared__ float row[Dn];
    int warp = tid >> 5, lane = tid & 31;
#pragma unroll
    for (int hh = 0; hh < 2; hh++) {
        int h = warp * 2 + hh;
        const float* src = mh + ((size_t)((b * Hn + h) * Sn + s)) * HDn;
        float v0 = src[lane], v1 = src[lane + 32];
        float ss = warp_sum(v0 * v0 + v1 * v1);
        float n  = sqrtf(fmaxf(ss, EPSf * EPSf));
        float nc = fminf(fmaxf(n, EPSf), MAXNf);
        float sc = atanh_f(nc) / nc * ratio;
        row[h * HDn + lane]      = sc * v0;
        row[h * HDn + lane + 32] = sc * v1;
    }
    __syncthreads();
    float4 vl = *(const float4*)&row[tid * 4];
    float ss = vl.x * vl.x + vl.y * vl.y + vl.z * vl.z + vl.w * vl.w;
    ss = block_sum<128>(ss);
    float n  = sqrtf(fmaxf(ss, EPSf * EPSf));
    float es = tanhf(n) / n;
    float tb = tanhf(n);
    float cb = fminf(fmaxf(tb, EPSf), MAXNf);
    float s2 = atanh_f(cb) / cb;
    float sc = es * s2;
    store_split4(hi, lo, (size_t)r * Dn + tid * 4,
                 make_float4(sc * vl.x, sc * vl.y, sc * vl.z, sc * vl.w));
}

__global__ void __launch_bounds__(128)
k_exp_madd(const float* __restrict__ g, float* __restrict__ x) {
    int r = blockIdx.x, tid = threadIdx.x;
    float4 gv = *(const float4*)(g + (size_t)r * Dn + tid * 4);
    float4 xv = *(const float4*)(x + (size_t)r * Dn + tid * 4);
    float lg = gv.x * gv.x + gv.y * gv.y + gv.z * gv.z + gv.w * gv.w;
    float lx = xv.x * xv.x + xv.y * xv.y + xv.z * xv.z + xv.w * xv.w;
    float lxg = xv.x * gv.x + xv.y * gv.y + xv.z * gv.z + xv.w * gv.w;
    float g2 = block_sum<128>(lg);
    float x2 = block_sum<128>(lx);
    float xg = block_sum<128>(lxg);
    float ng = sqrtf(fmaxf(g2, EPSf * EPSf));
    float s  = tanhf(ng) / ng;
    float y2 = s * s * g2;
    float xy = s * xg;
    float den = fmaxf(1.f + 2.f * xy + x2 * y2, EPSf);
    float ca = (1.f + 2.f * xy + y2) / den;
    float cb = (1.f - x2) / den * s;
    float4 zv = make_float4(ca * xv.x + cb * gv.x, ca * xv.y + cb * gv.y,
                            ca * xv.z + cb * gv.z, ca * xv.w + cb * gv.w);
    float n2 = zv.x * zv.x + zv.y * zv.y + zv.z * zv.z + zv.w * zv.w;
    n2 = block_sum<128>(n2);
    float n = sqrtf(fmaxf(n2, EPSf * EPSf));
    float sc = fminf(1.f, MAXNf / n);
    *(float4*)(x + (size_t)r * Dn + tid * 4) =
        make_float4(sc * zv.x, sc * zv.y, sc * zv.z, sc * zv.w);
}

__global__ void __launch_bounds__(256)
k_ffnmid2bf(const float* __restrict__ u, __nv_bfloat16* __restrict__ hi,
            __nv_bfloat16* __restrict__ lo) {
    int r = blockIdx.x, tid = threadIdx.x;
    const float* ur = u + (size_t)r * FFn;
    float4 u0 = *(const float4*)(ur + tid * 4);
    float4 u1 = *(const float4*)(ur + 1024 + tid * 4);
    float ss = u0.x * u0.x + u0.y * u0.y + u0.z * u0.z + u0.w * u0.w
             + u1.x * u1.x + u1.y * u1.y + u1.z * u1.z + u1.w * u1.w;
    ss = block_sum<256>(ss);
    float n0 = sqrtf(fmaxf(ss, EPSf * EPSf));
    float t0 = tanhf(n0);
    float s1 = t0 / n0;
    float c0 = fminf(fmaxf(t0, EPSf), MAXNf);
    float a0 = atanh_f(c0) / c0;
    float w  = a0 * s1;
    float4 r0 = make_float4(fmaxf(w * u0.x, 0.f), fmaxf(w * u0.y, 0.f),
                            fmaxf(w * u0.z, 0.f), fmaxf(w * u0.w, 0.f));
    float4 r1 = make_float4(fmaxf(w * u1.x, 0.f), fmaxf(w * u1.y, 0.f),
                            fmaxf(w * u1.z, 0.f), fmaxf(w * u1.w, 0.f));
    float st = r0.x * r0.x + r0.y * r0.y + r0.z * r0.z + r0.w * r0.w
             + r1.x * r1.x + r1.y * r1.y + r1.z * r1.z + r1.w * r1.w;
    st = block_sum<256>(st);
    float n1 = sqrtf(fmaxf(st, EPSf * EPSf));
    float e1 = tanhf(n1) / n1;
    float t1 = tanhf(n1);
    float c1 = fminf(fmaxf(t1, EPSf), MAXNf);
    float a1 = atanh_f(c1) / c1;
    float sc = a1 * e1;
    store_split4(hi, lo, (size_t)r * FFn + tid * 4,
                 make_float4(sc * r0.x, sc * r0.y, sc * r0.z, sc * r0.w));
    store_split4(hi, lo, (size_t)r * FFn + 1024 + tid * 4,
                 make_float4(sc * r1.x, sc * r1.y, sc * r1.z, sc * r1.w));
}

__global__ void __launch_bounds__(128)
k_log2bf(const float* __restrict__ x, __nv_bfloat16* __restrict__ hi,
         __nv_bfloat16* __restrict__ lo) {
    int r = blockIdx.x, tid = threadIdx.x;
    float4 xv = *(const float4*)(x + (size_t)r * Dn + tid * 4);
    float ss = xv.x * xv.x + xv.y * xv.y + xv.z * xv.z + xv.w * xv.w;
    ss = block_sum<128>(ss);
    float n  = sqrtf(fmaxf(ss, EPSf * EPSf));
    float nc = fminf(fmaxf(n, EPSf), MAXNf);
    float s  = atanh_f(nc) / nc;
    store_split4(hi, lo, (size_t)r * Dn + tid * 4,
                 make_float4(s * xv.x, s * xv.y, s * xv.z, s * xv.w));
}

__global__ void __launch_bounds__(128)
k_expmap_out(const float* __restrict__ x, float* __restrict__ out) {
    int r = blockIdx.x, tid = threadIdx.x;
    float4 xv = *(const float4*)(x + (size_t)r * Dn + tid * 4);
    float ss = xv.x * xv.x + xv.y * xv.y + xv.z * xv.z + xv.w * xv.w;
    ss = block_sum<128>(ss);
    float n = sqrtf(fmaxf(ss, EPSf * EPSf));
    float s = tanhf(n) / n;
    *(float4*)(out + (size_t)r * Dn + tid * 4) =
        make_float4(s * xv.x, s * xv.y, s * xv.z, s * xv.w);
}

// ---------------- host orchestration ----------------
extern "C" void kernel_launch(void* const* d_in, const int* in_sizes, int n_in,
                              void* d_out, int out_size) {
    (void)in_sizes; (void)n_in; (void)out_size;
    const float* x    = (const float*)d_in[0];
    const float* pos  = (const float*)d_in[1];
    const float* ln1w = (const float*)d_in[2];
    const float* ln1b = (const float*)d_in[3];
    const float* ln2w = (const float*)d_in[4];
    const float* ln2b = (const float*)d_in[5];
    const float* Wq   = (const float*)d_in[6];
    const float* bq   = (const float*)d_in[7];
    const float* Wk   = (const float*)d_in[8];
    const float* bk   = (const float*)d_in[9];
    const float* Wv   = (const float*)d_in[10];
    const float* bv   = (const float*)d_in[11];
    const float* Wo   = (const float*)d_in[12];
    const float* bo   = (const float*)d_in[13];
    const float* W1   = (const float*)d_in[14];
    const float* b1   = (const float*)d_in[15];
    const float* W2   = (const float*)d_in[16];
    const float* b2   = (const float*)d_in[17];
    const float* tau  = (const float*)d_in[18];
    const float* gam  = (const float*)d_in[19];
    const float* Wout = (const float*)d_in[20];
    const float* bout = (const float*)d_in[21];
    float* outp = (float*)d_out;

    float *px, *pu, *pm, *pqf, *pkf, *pbq, *pq2, *pk2, *plm;
    __nv_bfloat16 *pahi, *palo, *pwhi, *pwlo, *plh, *pll;
    cudaGetSymbolAddress((void**)&px,  g_x);
    cudaGetSymbolAddress((void**)&pu,  g_u);
    cudaGetSymbolAddress((void**)&pm,  g_mid);
    cudaGetSymbolAddress((void**)&pqf, g_qf);
    cudaGetSymbolAddress((void**)&pkf, g_kf);
    cudaGetSymbolAddress((void**)&pbq, g_bqkv);
    cudaGetSymbolAddress((void**)&pq2, g_q2);
    cudaGetSymbolAddress((void**)&pk2, g_k2);
    cudaGetSymbolAddress((void**)&plm, g_lm1);
    cudaGetSymbolAddress((void**)&plh, g_lvh);
    cudaGetSymbolAddress((void**)&pll, g_lvl);
    cudaGetSymbolAddress((void**)&pahi, g_ahi);
    cudaGetSymbolAddress((void**)&palo, g_alo);
    cudaGetSymbolAddress((void**)&pwhi, g_Whi);
    cudaGetSymbolAddress((void**)&pwlo, g_Wlo);

    cudaFuncSetAttribute((const void*)k_gemm_mma,
                         cudaFuncAttributeMaxDynamicSharedMemorySize, GEMM_SMEM);
    cudaFuncSetAttribute((const void*)k_gemm_mma,
                         cudaFuncAttributePreferredSharedMemoryCarveout, 100);
    cudaFuncSetAttribute((const void*)k_attn2,
                         cudaFuncAttributeMaxDynamicSharedMemorySize, ATT2_SMEM);
    cudaFuncSetAttribute((const void*)k_attn2,
                         cudaFuncAttributePreferredSharedMemoryCarveout, 100);

    double betaD  = std::exp(std::lgamma(Dn / 2.0)  + std::lgamma(0.5) - std::lgamma(Dn / 2.0 + 0.5));
    double betaHD = std::exp(std::lgamma(HDn / 2.0) + std::lgamma(0.5) - std::lgamma(HDn / 2.0 + 0.5));
    float ratio_split = (float)(betaHD / betaD);
    float ratio_cat   = (float)(betaD / betaHD);

    constexpr int DD = Dn * Dn, FD = FFn * Dn;
    WCvtArgs wa;
    int idx = 0;
    auto add = [&](const float* s, long long off, int n) {
        wa.src[idx] = s; wa.off[idx] = off; wa.n4[idx] = n / 4; idx++;
    };
    for (int l = 0; l < Ln; l++) {
        long long base = l * WLL;
        add(Wq + (size_t)l * DD, base,               DD);
        add(Wk + (size_t)l * DD, base + DD,          DD);
        add(Wv + (size_t)l * DD, base + 2 * DD,      DD);
        add(Wo + (size_t)l * DD, base + 3 * DD,      DD);
        add(W1 + (size_t)l * FD, base + 4 * DD,      FD);
        add(W2 + (size_t)l * FD, base + 4 * DD + FD, FD);
    }
    add(Wout, 4 * WLL, DD);
    k_wcvt<<<dim3(1024, 25), 256>>>(wa, pwhi, pwlo);
    k_bfill<<<dim3(6, Ln), 256>>>(bq, bk, bv, pbq);

    auto gemm = [&](long long woff, const float* bias, float* Cout, int Ni, int Ki) {
        k_gemm_mma<<<dim3(Ni / 64, Mn / 64), 128, GEMM_SMEM>>>(
            pahi, palo, pwhi + woff, pwlo + woff, bias, Cout, Ni, Ki);
    };

    k_mobius_add<128><<<Mn, 128>>>(x, pos, px, Sn);

    for (int l = 0; l < Ln; l++) {
        long long base = l * WLL;
        // ---- attention ----
        k_pln2bf<<<Mn, 128>>>(px, ln1w + l * Dn, ln1b + l * Dn, pahi, palo);
        gemm(base, pbq + l * 3 * Dn, pu, 3 * Dn, Dn);   // fused QKV
        k_post_qkv3<<<dim3(Mn, 3), 128>>>(pu, pqf, pkf, plh, pll,
                                          pq2, pk2, plm, ratio_split);
        k_attn2<<<dim3(Sn / 128, BHn), 256, ATT2_SMEM>>>(
            pqf, pkf, plh, pll, pq2, pk2, plm, tau, gam, l, pm);

        k_concat2bf<<<Mn, 128>>>(pm, pahi, palo, ratio_cat);
        gemm(base + 3 * DD, bo + l * Dn, pu, Dn, Dn);
        k_exp_madd<<<Mn, 128>>>(pu, px);

        // ---- FFN ----
        k_pln2bf<<<Mn, 128>>>(px, ln2w + l * Dn, ln2b + l * Dn, pahi, palo);
        gemm(base + 4 * DD, b1 + l * FFn, pu, FFn, Dn);
        k_ffnmid2bf<<<Mn, 256>>>(pu, pahi, palo);
        gemm(base + 4 * DD + FD, b2 + l * Dn, pu, Dn, FFn);
        k_exp_madd<<<Mn, 128>>>(pu, px);
    }

    // ---- head ----
    k_log2bf<<<Mn, 128>>>(px, pahi, palo);
    gemm(4 * WLL, bout, pu, Dn, Dn);
    k_expmap_out<<<Mn, 128>>>(pu, outp);
}

// round 10
// speedup vs baseline: 3.0738x; 1.2247x over previous
#include <cuda_runtime.h>
#include <cuda_bf16.h>
#include <cstdint>
#include <cmath>

// ---------------- problem constants ----------------
constexpr int Bn  = 2;
constexpr int Sn  = 1024;
constexpr int Dn  = 512;
constexpr int Hn  = 8;
constexpr int HDn = 64;
constexpr int FFn = 2048;
constexpr int Ln  = 4;
constexpr int Mn  = Bn * Sn;   // 2048
constexpr int BHn = Bn * Hn;   // 16
constexpr long long WLL = 4LL * Dn * Dn + 2LL * FFn * Dn;

#define EPSf   1e-7f
#define MAXNf  (1.0f - 1e-3f)

// ---------------- scratch ----------------
__device__ float g_x   [Mn * Dn];
__device__ float g_u   [Mn * FFn];
__device__ float g_mid [Mn * Dn];
__device__ float g_qf  [Mn * Dn];
__device__ float g_kf  [Mn * Dn];
__device__ float g_bqkv[Ln * 3 * Dn];
__device__ float g_q2  [BHn * Sn];
__device__ float g_k2  [BHn * Sn];
__device__ float g_lm1 [BHn * Sn];
__device__ __nv_bfloat16 g_lvh[Mn * Dn];
__device__ __nv_bfloat16 g_lvl[Mn * Dn];
__device__ __nv_bfloat16 g_ahi[Mn * FFn];
__device__ __nv_bfloat16 g_alo[Mn * FFn];
__device__ __nv_bfloat16 g_Whi[4 * WLL + Dn * Dn];
__device__ __nv_bfloat16 g_Wlo[4 * WLL + Dn * Dn];

// ---------------- PTX helpers ----------------
static __device__ __forceinline__ uint32_t smem_u32(const void* p) {
    return (uint32_t)__cvta_generic_to_shared(p);
}
static __device__ __forceinline__ void cp16(uint32_t dst, const void* src) {
    asm volatile("cp.async.cg.shared.global [%0], [%1], 16;" :: "r"(dst), "l"(src));
}
static __device__ __forceinline__ void cp_commit() {
    asm volatile("cp.async.commit_group;" ::: "memory");
}
template<int N>
static __device__ __forceinline__ void cp_wait() {
    asm volatile("cp.async.wait_group %0;" :: "n"(N) : "memory");
}
static __device__ __forceinline__ void ldm4(uint32_t* r, uint32_t addr) {
    asm volatile("ldmatrix.sync.aligned.m8n8.x4.shared.b16 {%0,%1,%2,%3}, [%4];"
                 : "=r"(r[0]), "=r"(r[1]), "=r"(r[2]), "=r"(r[3]) : "r"(addr));
}
static __device__ __forceinline__ void ldm4t(uint32_t* r, uint32_t addr) {
    asm volatile("ldmatrix.sync.aligned.m8n8.x4.trans.shared.b16 {%0,%1,%2,%3}, [%4];"
                 : "=r"(r[0]), "=r"(r[1]), "=r"(r[2]), "=r"(r[3]) : "r"(addr));
}
static __device__ __forceinline__ void mma16816(float* d, const uint32_t* a, const uint32_t* b) {
    asm volatile("mma.sync.aligned.m16n8k16.row.col.f32.bf16.bf16.f32 "
                 "{%0,%1,%2,%3}, {%4,%5,%6,%7}, {%8,%9}, {%0,%1,%2,%3};"
                 : "+f"(d[0]), "+f"(d[1]), "+f"(d[2]), "+f"(d[3])
                 : "r"(a[0]), "r"(a[1]), "r"(a[2]), "r"(a[3]), "r"(b[0]), "r"(b[1]));
}
static __device__ __forceinline__ uint32_t f2tf(float x) {
    uint32_t r; asm("cvt.rna.tf32.f32 %0, %1;" : "=r"(r) : "f"(x)); return r;
}
static __device__ __forceinline__ void mma_tf32(float* d, const uint32_t* a, const uint32_t* b) {
    asm volatile("mma.sync.aligned.m16n8k8.row.col.f32.tf32.tf32.f32 "
                 "{%0,%1,%2,%3}, {%4,%5,%6,%7}, {%8,%9}, {%0,%1,%2,%3};"
                 : "+f"(d[0]), "+f"(d[1]), "+f"(d[2]), "+f"(d[3])
                 : "r"(a[0]), "r"(a[1]), "r"(a[2]), "r"(a[3]), "r"(b[0]), "r"(b[1]));
}

// ---------------- math helpers ----------------
static __device__ __forceinline__ float atanh_f(float x) {
    return 0.5f * (log1pf(x) - log1pf(-x));
}
template<int NT>
__device__ __forceinline__ float block_sum(float v) {
    __shared__ float sh[NT / 32];
#pragma unroll
    for (int o = 16; o > 0; o >>= 1) v += __shfl_xor_sync(0xffffffffu, v, o);
    int w = threadIdx.x >> 5;
    if ((threadIdx.x & 31) == 0) sh[w] = v;
    __syncthreads();
    float r = sh[0];
#pragma unroll
    for (int i = 1; i < NT / 32; i++) r += sh[i];
    __syncthreads();
    return r;
}
__device__ __forceinline__ float warp_sum(float v) {
#pragma unroll
    for (int o = 16; o > 0; o >>= 1) v += __shfl_xor_sync(0xffffffffu, v, o);
    return v;
}
__device__ __forceinline__ float group16_sum(float v) {
#pragma unroll
    for (int o = 8; o > 0; o >>= 1) v += __shfl_xor_sync(0xffffffffu, v, o);
    return v;
}
static __device__ __forceinline__ void store_split4(__nv_bfloat16* hi, __nv_bfloat16* lo,
                                                    size_t idx, float4 v) {
    __nv_bfloat16 h0 = __float2bfloat16(v.x), h1 = __float2bfloat16(v.y);
    __nv_bfloat16 h2 = __float2bfloat16(v.z), h3 = __float2bfloat16(v.w);
    __nv_bfloat16 l0 = __float2bfloat16(v.x - __bfloat162float(h0));
    __nv_bfloat16 l1 = __float2bfloat16(v.y - __bfloat162float(h1));
    __nv_bfloat16 l2 = __float2bfloat16(v.z - __bfloat162float(h2));
    __nv_bfloat16 l3 = __float2bfloat16(v.w - __bfloat162float(h3));
    ((__nv_bfloat162*)(hi + idx))[0] = __halves2bfloat162(h0, h1);
    ((__nv_bfloat162*)(hi + idx))[1] = __halves2bfloat162(h2, h3);
    ((__nv_bfloat162*)(lo + idx))[0] = __halves2bfloat162(l0, l1);
    ((__nv_bfloat162*)(lo + idx))[1] = __halves2bfloat162(l2, l3);
}

// ---------------- weight conversion ----------------
struct WCvtArgs {
    const float* src[25];
    long long    off[25];
    int          n4[25];
};
__global__ void k_wcvt(WCvtArgs a, __nv_bfloat16* __restrict__ hi, __nv_bfloat16* __restrict__ lo) {
    int t = blockIdx.y;
    int i = blockIdx.x * blockDim.x + threadIdx.x;
    if (i >= a.n4[t]) return;
    float4 v = ((const float4*)a.src[t])[i];
    store_split4(hi, lo, (size_t)a.off[t] + 4 * (size_t)i, v);
}
__global__ void k_bfill(const float* __restrict__ bq, const float* __restrict__ bk,
                        const float* __restrict__ bv, float* __restrict__ out) {
    int l = blockIdx.y;
    int i = blockIdx.x * blockDim.x + threadIdx.x;
    float v;
    if (i < Dn)            v = bq[l * Dn + i];
    else if (i < 2 * Dn)   v = bk[l * Dn + i - Dn];
    else                   v = bv[l * Dn + i - 2 * Dn];
    out[l * 3 * Dn + i] = v;
}

// ---------------- HMMA GEMM (3-pass split-bf16, 2-stage, 2 CTA/SM) ----------------
constexpr int LDS = 72;
constexpr int STAGE_E = 4 * 64 * LDS;
constexpr int GEMM_SMEM = 2 * STAGE_E * 2;   // 73728 B

__global__ void __launch_bounds__(128, 2)
k_gemm_mma(const __nv_bfloat16* __restrict__ Ahi, const __nv_bfloat16* __restrict__ Alo,
           const __nv_bfloat16* __restrict__ Whi, const __nv_bfloat16* __restrict__ Wlo,
           const float* __restrict__ bias, float* __restrict__ C, int Ni, int Ki)
{
    extern __shared__ __nv_bfloat16 sm[];
    const int tid = threadIdx.x, wid = tid >> 5, lane = tid & 31;
    const int bm = blockIdx.y * 64, bn = blockIdx.x * 64;
    const int wm = (wid >> 1) * 32, wn = (wid & 1) * 32;
    const uint32_t sbase = smem_u32(sm);

    float acc[2][4][4];
#pragma unroll
    for (int a = 0; a < 2; a++)
#pragma unroll
        for (int b = 0; b < 4; b++)
#pragma unroll
            for (int c = 0; c < 4; c++) acc[a][b][c] = 0.f;

    const int NC = Ki >> 6;

    auto load_stage = [&](int c) {
        const uint32_t sb = sbase + (uint32_t)(c & 1) * STAGE_E * 2;
        const size_t k0 = (size_t)c * 64;
#pragma unroll
        for (int i = tid; i < 512; i += 128) {
            int row = i >> 3, seg = i & 7;
            const size_t gA = (size_t)(bm + row) * Ki + k0 + seg * 8;
            const size_t gB = (size_t)(bn + row) * Ki + k0 + seg * 8;
            uint32_t ro = (uint32_t)(row * LDS + seg * 8) * 2;
            cp16(sb + ro,                 Ahi + gA);
            cp16(sb + 64 * LDS * 2 + ro,  Alo + gA);
            cp16(sb + 128 * LDS * 2 + ro, Whi + gB);
            cp16(sb + 192 * LDS * 2 + ro, Wlo + gB);
        }
        cp_commit();
    };

    uint32_t ah[2][2][4], al[2][2][4], bh[2][4][2], bl[2][4][2];
    auto ldfrag = [&](uint32_t sb, int kk, int bf) {
        uint32_t koff = (uint32_t)(kk * 16) * 2 + (lane >> 4) * 16;
#pragma unroll
        for (int mt = 0; mt < 2; mt++) {
            uint32_t rA = (uint32_t)(wm + mt * 16 + (lane & 15));
            ldm4(ah[bf][mt], sb + rA * (LDS * 2) + koff);
            ldm4(al[bf][mt], sb + (64 + rA) * (LDS * 2) + koff);
        }
#pragma unroll
        for (int nt2 = 0; nt2 < 2; nt2++) {
            uint32_t rB = (uint32_t)(128 + wn + nt2 * 16 + (lane & 15));
            uint32_t t[4];
            ldm4(t, sb + rB * (LDS * 2) + koff);
            bh[bf][nt2 * 2][0] = t[0]; bh[bf][nt2 * 2 + 1][0] = t[1];
            bh[bf][nt2 * 2][1] = t[2]; bh[bf][nt2 * 2 + 1][1] = t[3];
            ldm4(t, sb + (64 + rB) * (LDS * 2) + koff);
            bl[bf][nt2 * 2][0] = t[0]; bl[bf][nt2 * 2 + 1][0] = t[1];
            bl[bf][nt2 * 2][1] = t[2]; bl[bf][nt2 * 2 + 1][1] = t[3];
        }
    };

    load_stage(0);
    if (NC > 1) load_stage(1);

    for (int c = 0; c < NC; c++) {
        const uint32_t sb = sbase + (uint32_t)(c & 1) * STAGE_E * 2;
        cp_wait<1>();
        __syncthreads();

        ldfrag(sb, 0, 0);
#pragma unroll
        for (int kk = 0; kk < 4; kk++) {
            const int cur = kk & 1, nxt = cur ^ 1;
            if (kk < 3) ldfrag(sb, kk + 1, nxt);
#pragma unroll
            for (int mt = 0; mt < 2; mt++)
#pragma unroll
                for (int nt = 0; nt < 4; nt++)
                    mma16816(acc[mt][nt], ah[cur][mt], bh[cur][nt]);
#pragma unroll
            for (int mt = 0; mt < 2; mt++)
#pragma unroll
                for (int nt = 0; nt < 4; nt++)
                    mma16816(acc[mt][nt], ah[cur][mt], bl[cur][nt]);
#pragma unroll
            for (int mt = 0; mt < 2; mt++)
#pragma unroll
                for (int nt = 0; nt < 4; nt++)
                    mma16816(acc[mt][nt], al[cur][mt], bh[cur][nt]);
        }
        __syncthreads();
        if (c + 2 < NC) load_stage(c + 2);
    }

#pragma unroll
    for (int mt = 0; mt < 2; mt++) {
        int r0 = bm + wm + mt * 16 + (lane >> 2);
#pragma unroll
        for (int nt = 0; nt < 4; nt++) {
            int col = bn + wn + nt * 8 + 2 * (lane & 3);
            float b0 = bias[col], b1 = bias[col + 1];
            float2 v0 = make_float2(acc[mt][nt][0] + b0, acc[mt][nt][1] + b1);
            float2 v1 = make_float2(acc[mt][nt][2] + b0, acc[mt][nt][3] + b1);
            *(float2*)(C + (size_t)r0 * Ni + col) = v0;
            *(float2*)(C + (size_t)(r0 + 8) * Ni + col) = v1;
        }
    }
}

// ---------------- fused elementwise kernels ----------------

template<int NT>
__global__ void k_mobius_add(const float* __restrict__ x, const float* __restrict__ y,
                             float* __restrict__ out, int ymod) {
    constexpr int P = Dn / NT;
    int r = blockIdx.x;
    const float* xr = x + (size_t)r * Dn;
    const float* yr = y + (size_t)(r % ymod) * Dn;
    float xl[P], yl[P];
    float x2 = 0.f, y2 = 0.f, xy = 0.f;
#pragma unroll
    for (int i = 0; i < P; i++) {
        int j = threadIdx.x + i * NT;
        xl[i] = xr[j]; yl[i] = yr[j];
        x2 += xl[i] * xl[i]; y2 += yl[i] * yl[i]; xy += xl[i] * yl[i];
    }
    x2 = block_sum<NT>(x2);
    y2 = block_sum<NT>(y2);
    xy = block_sum<NT>(xy);
    float den = fmaxf(1.f + 2.f * xy + x2 * y2, EPSf);
    float ca = (1.f + 2.f * xy + y2) / den;
    float cb = (1.f - x2) / den;
    float zl[P]; float n2 = 0.f;
#pragma unroll
    for (int i = 0; i < P; i++) { zl[i] = ca * xl[i] + cb * yl[i]; n2 += zl[i] * zl[i]; }
    n2 = block_sum<NT>(n2);
    float n = sqrtf(fmaxf(n2, EPSf * EPSf));
    float sc = fminf(1.f, MAXNf / n);
#pragma unroll
    for (int i = 0; i < P; i++) out[(size_t)r * Dn + threadIdx.x + i * NT] = zl[i] * sc;
}

__global__ void __launch_bounds__(128)
k_pln2bf(const float* __restrict__ x, const float* __restrict__ w, const float* __restrict__ b,
         __nv_bfloat16* __restrict__ hi, __nv_bfloat16* __restrict__ lo) {
    int r = blockIdx.x, tid = threadIdx.x;
    const float* xr = x + (size_t)r * Dn;
    float4 xv = *(const float4*)(xr + tid * 4);
    float ss = xv.x * xv.x + xv.y * xv.y + xv.z * xv.z + xv.w * xv.w;
    ss = block_sum<128>(ss);
    float n  = sqrtf(fmaxf(ss, EPSf * EPSf));
    float nc = fminf(fmaxf(n, EPSf), MAXNf);
    float ls = atanh_f(nc) / nc;
    float4 tl = make_float4(ls * xv.x, ls * xv.y, ls * xv.z, ls * xv.w);
    float st = tl.x + tl.y + tl.z + tl.w;
    st = block_sum<128>(st);
    float mu = st / (float)Dn;
    float d0 = tl.x - mu, d1 = tl.y - mu, d2 = tl.z - mu, d3 = tl.w - mu;
    float sv = d0 * d0 + d1 * d1 + d2 * d2 + d3 * d3;
    sv = block_sum<128>(sv);
    float inv = rsqrtf(sv / (float)Dn + 1e-5f);
    float4 wv = *(const float4*)(w + tid * 4);
    float4 bv = *(const float4*)(b + tid * 4);
    float4 yv = make_float4(d0 * inv * wv.x + bv.x, d1 * inv * wv.y + bv.y,
                            d2 * inv * wv.z + bv.z, d3 * inv * wv.w + bv.w);
    float sy = yv.x * yv.x + yv.y * yv.y + yv.z * yv.z + yv.w * yv.w;
    sy = block_sum<128>(sy);
    float ny = sqrtf(fmaxf(sy, EPSf * EPSf));
    float es = tanhf(ny) / ny;
    float tb = tanhf(ny);
    float cb = fminf(fmaxf(tb, EPSf), MAXNf);
    float s2 = atanh_f(cb) / cb;
    float sc = es * s2;
    store_split4(hi, lo, (size_t)r * Dn + tid * 4,
                 make_float4(sc * yv.x, sc * yv.y, sc * yv.z, sc * yv.w));
}

// fused: x = project(mobius_add(x, expmap0(g))); then pln(x) -> logmap0 -> bf16 hi/lo
__global__ void __launch_bounds__(128)
k_expmadd_pln(const float* __restrict__ g, float* __restrict__ x,
              const float* __restrict__ w, const float* __restrict__ b,
              __nv_bfloat16* __restrict__ hi, __nv_bfloat16* __restrict__ lo) {
    int r = blockIdx.x, tid = threadIdx.x;
    float4 gv = *(const float4*)(g + (size_t)r * Dn + tid * 4);
    float4 xv = *(const float4*)(x + (size_t)r * Dn + tid * 4);
    float lg = gv.x * gv.x + gv.y * gv.y + gv.z * gv.z + gv.w * gv.w;
    float lx = xv.x * xv.x + xv.y * xv.y + xv.z * xv.z + xv.w * xv.w;
    float lxg = xv.x * gv.x + xv.y * gv.y + xv.z * gv.z + xv.w * gv.w;
    float g2 = block_sum<128>(lg);
    float x2 = block_sum<128>(lx);
    float xg = block_sum<128>(lxg);
    float ng = sqrtf(fmaxf(g2, EPSf * EPSf));
    float s  = tanhf(ng) / ng;
    float y2 = s * s * g2;
    float xy = s * xg;
    float den = fmaxf(1.f + 2.f * xy + x2 * y2, EPSf);
    float ca = (1.f + 2.f * xy + y2) / den;
    float cb2 = (1.f - x2) / den * s;
    float4 zv = make_float4(ca * xv.x + cb2 * gv.x, ca * xv.y + cb2 * gv.y,
                            ca * xv.z + cb2 * gv.z, ca * xv.w + cb2 * gv.w);
    float n2 = zv.x * zv.x + zv.y * zv.y + zv.z * zv.z + zv.w * zv.w;
    n2 = block_sum<128>(n2);
    float n = sqrtf(fmaxf(n2, EPSf * EPSf));
    float scp = fminf(1.f, MAXNf / n);
    float4 nx = make_float4(scp * zv.x, scp * zv.y, scp * zv.z, scp * zv.w);
    *(float4*)(x + (size_t)r * Dn + tid * 4) = nx;

    // pln on nx: ss = scp^2 * n2 (exact up to rounding)
    float ss = scp * scp * n2;
    float n1  = sqrtf(fmaxf(ss, EPSf * EPSf));
    float nc1 = fminf(fmaxf(n1, EPSf), MAXNf);
    float ls = atanh_f(nc1) / nc1;
    float4 tl = make_float4(ls * nx.x, ls * nx.y, ls * nx.z, ls * nx.w);
    float st = tl.x + tl.y + tl.z + tl.w;
    st = block_sum<128>(st);
    float mu = st / (float)Dn;
    float d0 = tl.x - mu, d1 = tl.y - mu, d2 = tl.z - mu, d3 = tl.w - mu;
    float sv = d0 * d0 + d1 * d1 + d2 * d2 + d3 * d3;
    sv = block_sum<128>(sv);
    float inv = rsqrtf(sv / (float)Dn + 1e-5f);
    float4 wv = *(const float4*)(w + tid * 4);
    float4 bv = *(const float4*)(b + tid * 4);
    float4 yv = make_float4(d0 * inv * wv.x + bv.x, d1 * inv * wv.y + bv.y,
                            d2 * inv * wv.z + bv.z, d3 * inv * wv.w + bv.w);
    float sy = yv.x * yv.x + yv.y * yv.y + yv.z * yv.z + yv.w * yv.w;
    sy = block_sum<128>(sy);
    float ny = sqrtf(fmaxf(sy, EPSf * EPSf));
    float es = tanhf(ny) / ny;
    float tb = tanhf(ny);
    float cb3 = fminf(fmaxf(tb, EPSf), MAXNf);
    float s2 = atanh_f(cb3) / cb3;
    float sc = es * s2;
    store_split4(hi, lo, (size_t)r * Dn + tid * 4,
                 make_float4(sc * yv.x, sc * yv.y, sc * yv.z, sc * yv.w));
}

// fused-QKV post: Q/K -> fp32 (+q2/k2), V -> lamv bf16 hi/lo (+lm1)
__global__ void __launch_bounds__(128)
k_post_qkv3(const float* __restrict__ u,
            float* __restrict__ qf, float* __restrict__ kf,
            __nv_bfloat16* __restrict__ lvh, __nv_bfloat16* __restrict__ lvl,
            float* __restrict__ q2g, float* __restrict__ k2g, float* __restrict__ lmg,
            float ratio) {
    int which = blockIdx.y;
    int r = blockIdx.x, tid = threadIdx.x;
    int b = r / Sn, s = r % Sn;
    float4 uv = *(const float4*)(u + (size_t)r * (3 * Dn) + which * Dn + tid * 4);
    float ss = uv.x * uv.x + uv.y * uv.y + uv.z * uv.z + uv.w * uv.w;
    float bs = block_sum<128>(ss);
    float n  = sqrtf(fmaxf(bs, EPSf * EPSf));
    float s1 = tanhf(n) / n;
    float t  = tanhf(n);
    float c  = fminf(fmaxf(t, EPSf), MAXNf);
    float s2 = atanh_f(c) / c;
    float sc = s1 * s2 * ratio;
    float4 th = make_float4(sc * uv.x, sc * uv.y, sc * uv.z, sc * uv.w);
    float hs = sc * sc * ss;
    hs = group16_sum(hs);
    float nh = sqrtf(fmaxf(hs, EPSf * EPSf));
    float es = tanhf(nh) / nh;
    int h = tid >> 4;
    size_t row = (size_t)(b * Hn + h) * Sn + s;
    size_t dst = row * HDn + (tid & 15) * 4;
    if (which == 0) {
        *(float4*)(qf + dst) = make_float4(es * th.x, es * th.y, es * th.z, es * th.w);
        if ((tid & 15) == 0) q2g[row] = es * es * hs;
    } else if (which == 1) {
        *(float4*)(kf + dst) = make_float4(es * th.x, es * th.y, es * th.z, es * th.w);
        if ((tid & 15) == 0) k2g[row] = es * es * hs;
    } else {
        float vsq = es * es * hs;
        float lam = 2.f / fmaxf(1.f - vsq, EPSf);
        float ls2 = lam * es;
        store_split4(lvh, lvl, dst, make_float4(ls2 * th.x, ls2 * th.y, ls2 * th.z, ls2 * th.w));
        if ((tid & 15) == 0) lmg[row] = lam - 1.f;
    }
}

// ---------------- fused attention: 3xTF32 HMMA QK + MUFU transform + HMMA PV ----------------
constexpr int ALD = 72;   // bf16 row stride (144 B)
constexpr int O_QS  = 0;           // fp32 [64][68] row-major [i][d]
constexpr int O_KS  = 17408;       // fp32 [64][68] row-major [j][d] (aliased as NUM post-loop)
constexpr int O_LVH = 34816;       // bf16 [64][72]
constexpr int O_LVL = 44032;
constexpr int O_PHI = 53248;
constexpr int O_PLO = 62464;
constexpr int O_Q2  = 71680;
constexpr int O_K2  = 71936;
constexpr int O_LMS = 72192;
constexpr int O_RS  = 72448;       // 2x 64 floats (per n-warp half)
constexpr int O_DS  = 72960;
constexpr int O_INV = 73472;
constexpr int ATT2_SMEM = 73728;

__global__ void __launch_bounds__(256)
k_attn3(const float* __restrict__ qf, const float* __restrict__ kf,
        const __nv_bfloat16* __restrict__ lvh, const __nv_bfloat16* __restrict__ lvl,
        const float* __restrict__ q2g, const float* __restrict__ k2g,
        const float* __restrict__ lmg,
        const float* __restrict__ tau, const float* __restrict__ gam, int l,
        float* __restrict__ mid)
{
    extern __shared__ char smb[];
    float* smf = (float*)smb;
    const uint32_t sb = smem_u32(smb);
    const int tid = threadIdx.x, wid = tid >> 5, lane = tid & 31;
    const int gid = lane >> 2, tig = lane & 3;
    const int bh = blockIdx.y;
    const int wm = (wid >> 1) * 16, wn = (wid & 1) * 32;
    const float tv = tau[l], gv = gam[l];

    for (int p = 0; p < 2; p++) {
        const int it = p ? (15 - (int)blockIdx.x) : (int)blockIdx.x;

        {   // Q -> row-major fp32 smem [i][d] (stride 68), q2
            const float* Q = qf + ((size_t)bh * Sn + it * 64) * HDn;
#pragma unroll
            for (int f = tid; f < 1024; f += 256) {
                int row = f >> 4, c = (f & 15) * 4;
                *(float4*)&smf[row * 68 + c] = *(const float4*)(Q + row * HDn + c);
            }
            if (tid < 64) smf[O_Q2 / 4 + tid] = q2g[(size_t)bh * Sn + it * 64 + tid];
        }
        float acc2[4][4];
#pragma unroll
        for (int a = 0; a < 4; a++)
#pragma unroll
            for (int c = 0; c < 4; c++) acc2[a][c] = 0.f;
        float rs_t[2] = {0.f, 0.f};
        float ds_t[2] = {0.f, 0.f};
        __syncthreads();

        for (int jt = 0; jt <= it; jt++) {
            {   // K -> row-major fp32 smem [j][d]; lamv bf16 hi/lo; k2/lms
                const float* K = kf + ((size_t)bh * Sn + jt * 64) * HDn;
#pragma unroll
                for (int f = tid; f < 1024; f += 256) {
                    int row = f >> 4, c = (f & 15) * 4;
                    *(float4*)&smf[O_KS / 4 + row * 68 + c] = *(const float4*)(K + row * HDn + c);
                }
                const size_t rb = ((size_t)bh * Sn + jt * 64) * HDn;
#pragma unroll
                for (int i = tid; i < 512; i += 256) {
                    int row = i >> 3, seg = i & 7;
                    uint32_t ro = (uint32_t)(row * ALD + seg * 8) * 2;
                    cp16(sb + O_LVH + ro, lvh + rb + row * HDn + seg * 8);
                    cp16(sb + O_LVL + ro, lvl + rb + row * HDn + seg * 8);
                }
                cp_commit();
                if (tid < 64) {
                    smf[O_K2 / 4 + tid]  = k2g[(size_t)bh * Sn + jt * 64 + tid];
                    smf[O_LMS / 4 + tid] = lmg[(size_t)bh * Sn + jt * 64 + tid];
                }
            }
            cp_wait<0>();
            __syncthreads();

            // ---- QK^T via 3xTF32 mma (m16n8k8) ----
            float sacc[4][4];
#pragma unroll
            for (int a = 0; a < 4; a++)
#pragma unroll
                for (int c = 0; c < 4; c++) sacc[a][c] = 0.f;
#pragma unroll
            for (int kc = 0; kc < 8; kc++) {
                const int d0 = kc * 8 + tig;
                float a0 = smf[(wm + gid) * 68 + d0];
                float a1 = smf[(wm + gid + 8) * 68 + d0];
                float a2 = smf[(wm + gid) * 68 + d0 + 4];
                float a3 = smf[(wm + gid + 8) * 68 + d0 + 4];
                uint32_t ah[4] = {f2tf(a0), f2tf(a1), f2tf(a2), f2tf(a3)};
                uint32_t al[4] = {f2tf(a0 - __uint_as_float(ah[0])),
                                  f2tf(a1 - __uint_as_float(ah[1])),
                                  f2tf(a2 - __uint_as_float(ah[2])),
                                  f2tf(a3 - __uint_as_float(ah[3]))};
                uint32_t bhv[4][2], blv[4][2];
#pragma unroll
                for (int nt = 0; nt < 4; nt++) {
                    float b0 = smf[O_KS / 4 + (wn + nt * 8 + gid) * 68 + d0];
                    float b1 = smf[O_KS / 4 + (wn + nt * 8 + gid) * 68 + d0 + 4];
                    bhv[nt][0] = f2tf(b0); bhv[nt][1] = f2tf(b1);
                    blv[nt][0] = f2tf(b0 - __uint_as_float(bhv[nt][0]));
                    blv[nt][1] = f2tf(b1 - __uint_as_float(bhv[nt][1]));
                }
#pragma unroll
                for (int nt = 0; nt < 4; nt++) mma_tf32(sacc[nt], ah, bhv[nt]);
#pragma unroll
                for (int nt = 0; nt < 4; nt++) mma_tf32(sacc[nt], ah, blv[nt]);
#pragma unroll
                for (int nt = 0; nt < 4; nt++) mma_tf32(sacc[nt], al, bhv[nt]);
            }

            // ---- MUFU score transform + bf16-split P + row partials ----
            const bool diag = (jt == it);
            {
                const int r0 = wm + gid;
                float qq0 = smf[O_Q2 / 4 + r0], qq1 = smf[O_Q2 / 4 + r0 + 8];
                float di0 = 1.f - qq0, di1 = 1.f - qq1;
#pragma unroll
                for (int nt = 0; nt < 4; nt++) {
                    int c0 = wn + nt * 8 + 2 * tig;
                    float kk0 = smf[O_K2 / 4 + c0],  kk1 = smf[O_K2 / 4 + c0 + 1];
                    float lm0 = smf[O_LMS / 4 + c0], lm1v = smf[O_LMS / 4 + c0 + 1];
                    float dj0 = 1.f - kk0, dj1 = 1.f - kk1;
                    float e[4];
#pragma unroll
                    for (int z = 0; z < 4; z++) {
                        float qq = (z < 2) ? qq0 : qq1;
                        float di = (z < 2) ? di0 : di1;
                        float kk2 = (z & 1) ? kk1 : kk0;
                        float dj = (z & 1) ? dj1 : dj0;
                        float d2 = fmaxf(qq + kk2 - 2.f * sacc[nt][z], 0.f);
                        float dn = fmaxf(di * dj, EPSf);
                        float uu = fmaxf(__fdividef(2.f * d2, dn), 1.1920929e-7f);
                        float ar = uu * (uu + 2.f);
                        float w = 1.f + uu + ar * rsqrtf(ar);
                        e[z] = __expf(fmaf(-tv, __logf(w), -gv));
                    }
                    if (diag) {
                        if (c0 > r0)         e[0] = 0.f;
                        if (c0 + 1 > r0)     e[1] = 0.f;
                        if (c0 > r0 + 8)     e[2] = 0.f;
                        if (c0 + 1 > r0 + 8) e[3] = 0.f;
                    }
                    rs_t[0] += e[0] + e[1];
                    ds_t[0] += e[0] * lm0 + e[1] * lm1v;
                    rs_t[1] += e[2] + e[3];
                    ds_t[1] += e[2] * lm0 + e[3] * lm1v;
                    __nv_bfloat16 h00 = __float2bfloat16(e[0]), h01 = __float2bfloat16(e[1]);
                    __nv_bfloat16 h10 = __float2bfloat16(e[2]), h11 = __float2bfloat16(e[3]);
                    *(__nv_bfloat162*)(smb + O_PHI + (r0 * ALD + c0) * 2) = __halves2bfloat162(h00, h01);
                    *(__nv_bfloat162*)(smb + O_PHI + ((r0 + 8) * ALD + c0) * 2) = __halves2bfloat162(h10, h11);
                    *(__nv_bfloat162*)(smb + O_PLO + (r0 * ALD + c0) * 2) = __halves2bfloat162(
                        __float2bfloat16(e[0] - __bfloat162float(h00)),
                        __float2bfloat16(e[1] - __bfloat162float(h01)));
                    *(__nv_bfloat162*)(smb + O_PLO + ((r0 + 8) * ALD + c0) * 2) = __halves2bfloat162(
                        __float2bfloat16(e[2] - __bfloat162float(h10)),
                        __float2bfloat16(e[3] - __bfloat162float(h11)));
                }
            }
            __syncthreads();

            // ---- HMMA PV: acc2 += P · λv (3-pass bf16 split) ----
#pragma unroll
            for (int kk = 0; kk < 4; kk++) {
                uint32_t koff = (uint32_t)(kk * 16) * 2 + (lane >> 4) * 16;
                uint32_t ph[4], pl[4], vh_[4][2], vl_[4][2];
                uint32_t rA = (uint32_t)(wm + (lane & 15));
                ldm4(ph, sb + O_PHI + rA * (ALD * 2) + koff);
                ldm4(pl, sb + O_PLO + rA * (ALD * 2) + koff);
#pragma unroll
                for (int q = 0; q < 2; q++) {
                    uint32_t row = (uint32_t)(kk * 16 + (lane & 15));
                    uint32_t col = (uint32_t)(wn + q * 16 + ((lane >> 4) << 3));
                    uint32_t t[4];
                    ldm4t(t, sb + O_LVH + (row * ALD + col) * 2);
                    vh_[q * 2][0] = t[0]; vh_[q * 2][1] = t[1];
                    vh_[q * 2 + 1][0] = t[2]; vh_[q * 2 + 1][1] = t[3];
                    ldm4t(t, sb + O_LVL + (row * ALD + col) * 2);
                    vl_[q * 2][0] = t[0]; vl_[q * 2][1] = t[1];
                    vl_[q * 2 + 1][0] = t[2]; vl_[q * 2 + 1][1] = t[3];
                }
#pragma unroll
                for (int nt = 0; nt < 4; nt++) mma16816(acc2[nt], ph, vh_[nt]);
#pragma unroll
                for (int nt = 0; nt < 4; nt++) mma16816(acc2[nt], ph, vl_[nt]);
#pragma unroll
                for (int nt = 0; nt < 4; nt++) mma16816(acc2[nt], pl, vh_[nt]);
            }
            __syncthreads();
        }

        // ---- reduce row sums across tig lanes + the two n-warps ----
#pragma unroll
        for (int hf = 0; hf < 2; hf++) {
            float v = rs_t[hf];
            v += __shfl_xor_sync(0xffffffffu, v, 1);
            v += __shfl_xor_sync(0xffffffffu, v, 2);
            float w = ds_t[hf];
            w += __shfl_xor_sync(0xffffffffu, w, 1);
            w += __shfl_xor_sync(0xffffffffu, w, 2);
            if (tig == 0) {
                int r = wm + hf * 8 + gid;
                int half = (wid & 1) * 64;
                smf[O_RS / 4 + half + r] = v;
                smf[O_DS / 4 + half + r] = w;
            }
        }
        __syncthreads();
        if (tid < 64) {
            float rst = smf[O_RS / 4 + tid] + smf[O_RS / 4 + 64 + tid];
            float dst = smf[O_DS / 4 + tid] + smf[O_DS / 4 + 64 + tid];
            smf[O_INV / 4 + tid] = __fdividef(1.f, fmaxf(dst, EPSf * rst));
        }
        __syncthreads();

        // ---- num = acc2 * inv -> NUM smem (alias Ks region, stride 68) ----
        {
            int r0 = wm + gid;
            float i0 = smf[O_INV / 4 + r0], i1 = smf[O_INV / 4 + r0 + 8];
#pragma unroll
            for (int nt = 0; nt < 4; nt++) {
                int c0 = wn + nt * 8 + 2 * tig;
                smf[O_KS / 4 + r0 * 68 + c0]           = acc2[nt][0] * i0;
                smf[O_KS / 4 + r0 * 68 + c0 + 1]       = acc2[nt][1] * i0;
                smf[O_KS / 4 + (r0 + 8) * 68 + c0]     = acc2[nt][2] * i1;
                smf[O_KS / 4 + (r0 + 8) * 68 + c0 + 1] = acc2[nt][3] * i1;
            }
        }
        __syncthreads();

        // ---- mobius_scalar_mul(0.5) + project, write mid ----
        {
            int r = tid >> 2, cg = (tid & 3) * 16;
            const float* nr = smf + O_KS / 4 + r * 68 + cg;
            float ss2 = 0.f;
#pragma unroll
            for (int c = 0; c < 16; c++) { float m = nr[c]; ss2 += m * m; }
            ss2 += __shfl_xor_sync(0xffffffffu, ss2, 1);
            ss2 += __shfl_xor_sync(0xffffffffu, ss2, 2);
            float n  = sqrtf(fmaxf(ss2, EPSf * EPSf));
            float nc = fminf(fmaxf(n, EPSf), MAXNf);
            float tt = tanhf(0.5f * atanh_f(nc));
            float s1 = tt / nc;
            float ny = sqrtf(fmaxf(s1 * s1 * ss2, EPSf * EPSf));
            float s2 = fminf(1.f, MAXNf / ny);
            float sc = s1 * s2;
            float* dst = mid + ((size_t)bh * Sn + it * 64 + r) * HDn + cg;
#pragma unroll
            for (int c = 0; c < 16; c += 4)
                *(float4*)(dst + c) = make_float4(sc * nr[c], sc * nr[c + 1],
                                                  sc * nr[c + 2], sc * nr[c + 3]);
        }
        __syncthreads();
    }
}

__global__ void __launch_bounds__(128)
k_concat2bf(const float* __restrict__ mh, __nv_bfloat16* __restrict__ hi,
            __nv_bfloat16* __restrict__ lo, float ratio) {
    int r = blockIdx.x, tid = threadIdx.x;
    int b = r / Sn, s = r % Sn;
    __shared__ float row[Dn];
    int warp = tid >> 5, lane = tid & 31;
#pragma unroll
    for (int hh = 0; hh < 2; hh++) {
        int h = warp * 2 + hh;
        const float* src = mh + ((size_t)((b * Hn + h) * Sn + s)) * HDn;
        float v0 = src[lane], v1 = src[lane + 32];
        float ss = warp_sum(v0 * v0 + v1 * v1);
        float n  = sqrtf(fmaxf(ss, EPSf * EPSf));
        float nc = fminf(fmaxf(n, EPSf), MAXNf);
        float sc = atanh_f(nc) / nc * ratio;
        row[h * HDn + lane]      = sc * v0;
        row[h * HDn + lane + 32] = sc * v1;
    }
    __syncthreads();
    float4 vl = *(const float4*)&row[tid * 4];
    float ss = vl.x * vl.x + vl.y * vl.y + vl.z * vl.z + vl.w * vl.w;
    ss = block_sum<128>(ss);
    float n  = sqrtf(fmaxf(ss, EPSf * EPSf));
    float es = tanhf(n) / n;
    float tb = tanhf(n);
    float cb = fminf(fmaxf(tb, EPSf), MAXNf);
    float s2 = atanh_f(cb) / cb;
    float sc = es * s2;
    store_split4(hi, lo, (size_t)r * Dn + tid * 4,
                 make_float4(sc * vl.x, sc * vl.y, sc * vl.z, sc * vl.w));
}

__global__ void __launch_bounds__(128)
k_exp_madd(const float* __restrict__ g, float* __restrict__ x) {
    int r = blockIdx.x, tid = threadIdx.x;
    float4 gv = *(const float4*)(g + (size_t)r * Dn + tid * 4);
    float4 xv = *(const float4*)(x + (size_t)r * Dn + tid * 4);
    float lg = gv.x * gv.x + gv.y * gv.y + gv.z * gv.z + gv.w * gv.w;
    float lx = xv.x * xv.x + xv.y * xv.y + xv.z * xv.z + xv.w * xv.w;
    float lxg = xv.x * gv.x + xv.y * gv.y + xv.z * gv.z + xv.w * gv.w;
    float g2 = block_sum<128>(lg);
    float x2 = block_sum<128>(lx);
    float xg = block_sum<128>(lxg);
    float ng = sqrtf(fmaxf(g2, EPSf * EPSf));
    float s  = tanhf(ng) / ng;
    float y2 = s * s * g2;
    float xy = s * xg;
    float den = fmaxf(1.f + 2.f * xy + x2 * y2, EPSf);
    float ca = (1.f + 2.f * xy + y2) / den;
    float cb = (1.f - x2) / den * s;
    float4 zv = make_float4(ca * xv.x + cb * gv.x, ca * xv.y + cb * gv.y,
                            ca * xv.z + cb * gv.z, ca * xv.w + cb * gv.w);
    float n2 = zv.x * zv.x + zv.y * zv.y + zv.z * zv.z + zv.w * zv.w;
    n2 = block_sum<128>(n2);
    float n = sqrtf(fmaxf(n2, EPSf * EPSf));
    float sc = fminf(1.f, MAXNf / n);
    *(float4*)(x + (size_t)r * Dn + tid * 4) =
        make_float4(sc * zv.x, sc * zv.y, sc * zv.z, sc * zv.w);
}

__global__ void __launch_bounds__(256)
k_ffnmid2bf(const float* __restrict__ u, __nv_bfloat16* __restrict__ hi,
            __nv_bfloat16* __restrict__ lo) {
    int r = blockIdx.x, tid = threadIdx.x;
    const float* ur = u + (size_t)r * FFn;
    float4 u0 = *(const float4*)(ur + tid * 4);
    float4 u1 = *(const float4*)(ur + 1024 + tid * 4);
    float ss = u0.x * u0.x + u0.y * u0.y + u0.z * u0.z + u0.w * u0.w
             + u1.x * u1.x + u1.y * u1.y + u1.z * u1.z + u1.w * u1.w;
    ss = block_sum<256>(ss);
    float n0 = sqrtf(fmaxf(ss, EPSf * EPSf));
    float t0 = tanhf(n0);
    float s1 = t0 / n0;
    float c0 = fminf(fmaxf(t0, EPSf), MAXNf);
    float a0 = atanh_f(c0) / c0;
    float w  = a0 * s1;
    float4 r0 = make_float4(fmaxf(w * u0.x, 0.f), fmaxf(w * u0.y, 0.f),
                            fmaxf(w * u0.z, 0.f), fmaxf(w * u0.w, 0.f));
    float4 r1 = make_float4(fmaxf(w * u1.x, 0.f), fmaxf(w * u1.y, 0.f),
                            fmaxf(w * u1.z, 0.f), fmaxf(w * u1.w, 0.f));
    float st = r0.x * r0.x + r0.y * r0.y + r0.z * r0.z + r0.w * r0.w
             + r1.x * r1.x + r1.y * r1.y + r1.z * r1.z + r1.w * r1.w;
    st = block_sum<256>(st);
    float n1 = sqrtf(fmaxf(st, EPSf * EPSf));
    float e1 = tanhf(n1) / n1;
    float t1 = tanhf(n1);
    float c1 = fminf(fmaxf(t1, EPSf), MAXNf);
    float a1 = atanh_f(c1) / c1;
    float sc = a1 * e1;
    store_split4(hi, lo, (size_t)r * FFn + tid * 4,
                 make_float4(sc * r0.x, sc * r0.y, sc * r0.z, sc * r0.w));
    store_split4(hi, lo, (size_t)r * FFn + 1024 + tid * 4,
                 make_float4(sc * r1.x, sc * r1.y, sc * r1.z, sc * r1.w));
}

__global__ void __launch_bounds__(128)
k_log2bf(const float* __restrict__ x, __nv_bfloat16* __restrict__ hi,
         __nv_bfloat16* __restrict__ lo) {
    int r = blockIdx.x, tid = threadIdx.x;
    float4 xv = *(const float4*)(x + (size_t)r * Dn + tid * 4);
    float ss = xv.x * xv.x + xv.y * xv.y + xv.z * xv.z + xv.w * xv.w;
    ss = block_sum<128>(ss);
    float n  = sqrtf(fmaxf(ss, EPSf * EPSf));
    float nc = fminf(fmaxf(n, EPSf), MAXNf);
    float s  = atanh_f(nc) / nc;
    store_split4(hi, lo, (size_t)r * Dn + tid * 4,
                 make_float4(s * xv.x, s * xv.y, s * xv.z, s * xv.w));
}

__global__ void __launch_bounds__(128)
k_expmap_out(const float* __restrict__ x, float* __restrict__ out) {
    int r = blockIdx.x, tid = threadIdx.x;
    float4 xv = *(const float4*)(x + (size_t)r * Dn + tid * 4);
    float ss = xv.x * xv.x + xv.y * xv.y + xv.z * xv.z + xv.w * xv.w;
    ss = block_sum<128>(ss);
    float n = sqrtf(fmaxf(ss, EPSf * EPSf));
    float s = tanhf(n) / n;
    *(float4*)(out + (size_t)r * Dn + tid * 4) =
        make_float4(s * xv.x, s * xv.y, s * xv.z, s * xv.w);
}

// ---------------- host orchestration ----------------
extern "C" void kernel_launch(void* const* d_in, const int* in_sizes, int n_in,
                              void* d_out, int out_size) {
    (void)in_sizes; (void)n_in; (void)out_size;
    const float* x    = (const float*)d_in[0];
    const float* pos  = (const float*)d_in[1];
    const float* ln1w = (const float*)d_in[2];
    const float* ln1b = (const float*)d_in[3];
    const float* ln2w = (const float*)d_in[4];
    const float* ln2b = (const float*)d_in[5];
    const float* Wq   = (const float*)d_in[6];
    const float* bq   = (const float*)d_in[7];
    const float* Wk   = (const float*)d_in[8];
    const float* bk   = (const float*)d_in[9];
    const float* Wv   = (const float*)d_in[10];
    const float* bv   = (const float*)d_in[11];
    const float* Wo   = (const float*)d_in[12];
    const float* bo   = (const float*)d_in[13];
    const float* W1   = (const float*)d_in[14];
    const float* b1   = (const float*)d_in[15];
    const float* W2   = (const float*)d_in[16];
    const float* b2   = (const float*)d_in[17];
    const float* tau  = (const float*)d_in[18];
    const float* gam  = (const float*)d_in[19];
    const float* Wout = (const float*)d_in[20];
    const float* bout = (const float*)d_in[21];
    float* outp = (float*)d_out;

    float *px, *pu, *pm, *pqf, *pkf, *pbq, *pq2, *pk2, *plm;
    __nv_bfloat16 *pahi, *palo, *pwhi, *pwlo, *plh, *pll;
    cudaGetSymbolAddress((void**)&px,  g_x);
    cudaGetSymbolAddress((void**)&pu,  g_u);
    cudaGetSymbolAddress((void**)&pm,  g_mid);
    cudaGetSymbolAddress((void**)&pqf, g_qf);
    cudaGetSymbolAddress((void**)&pkf, g_kf);
    cudaGetSymbolAddress((void**)&pbq, g_bqkv);
    cudaGetSymbolAddress((void**)&pq2, g_q2);
    cudaGetSymbolAddress((void**)&pk2, g_k2);
    cudaGetSymbolAddress((void**)&plm, g_lm1);
    cudaGetSymbolAddress((void**)&plh, g_lvh);
    cudaGetSymbolAddress((void**)&pll, g_lvl);
    cudaGetSymbolAddress((void**)&pahi, g_ahi);
    cudaGetSymbolAddress((void**)&palo, g_alo);
    cudaGetSymbolAddress((void**)&pwhi, g_Whi);
    cudaGetSymbolAddress((void**)&pwlo, g_Wlo);

    cudaFuncSetAttribute((const void*)k_gemm_mma,
                         cudaFuncAttributeMaxDynamicSharedMemorySize, GEMM_SMEM);
    cudaFuncSetAttribute((const void*)k_gemm_mma,
                         cudaFuncAttributePreferredSharedMemoryCarveout, 100);
    cudaFuncSetAttribute((const void*)k_attn3,
                         cudaFuncAttributeMaxDynamicSharedMemorySize, ATT2_SMEM);
    cudaFuncSetAttribute((const void*)k_attn3,
                         cudaFuncAttributePreferredSharedMemoryCarveout, 100);

    double betaD  = std::exp(std::lgamma(Dn / 2.0)  + std::lgamma(0.5) - std::lgamma(Dn / 2.0 + 0.5));
    double betaHD = std::exp(std::lgamma(HDn / 2.0) + std::lgamma(0.5) - std::lgamma(HDn / 2.0 + 0.5));
    float ratio_split = (float)(betaHD / betaD);
    float ratio_cat   = (float)(betaD / betaHD);

    constexpr int DD = Dn * Dn, FD = FFn * Dn;
    WCvtArgs wa;
    int idx = 0;
    auto add = [&](const float* s, long long off, int n) {
        wa.src[idx] = s; wa.off[idx] = off; wa.n4[idx] = n / 4; idx++;
    };
    for (int l = 0; l < Ln; l++) {
        long long base = l * WLL;
        add(Wq + (size_t)l * DD, base,               DD);
        add(Wk + (size_t)l * DD, base + DD,          DD);
        add(Wv + (size_t)l * DD, base + 2 * DD,      DD);
        add(Wo + (size_t)l * DD, base + 3 * DD,      DD);
        add(W1 + (size_t)l * FD, base + 4 * DD,      FD);
        add(W2 + (size_t)l * FD, base + 4 * DD + FD, FD);
    }
    add(Wout, 4 * WLL, DD);
    k_wcvt<<<dim3(1024, 25), 256>>>(wa, pwhi, pwlo);
    k_bfill<<<dim3(6, Ln), 256>>>(bq, bk, bv, pbq);

    auto gemm = [&](long long woff, const float* bias, float* Cout, int Ni, int Ki) {
        k_gemm_mma<<<dim3(Ni / 64, Mn / 64), 128, GEMM_SMEM>>>(
            pahi, palo, pwhi + woff, pwlo + woff, bias, Cout, Ni, Ki);
    };

    k_mobius_add<128><<<Mn, 128>>>(x, pos, px, Sn);

    for (int l = 0; l < Ln; l++) {
        long long base = l * WLL;
        // ---- attention ----
        if (l == 0)
            k_pln2bf<<<Mn, 128>>>(px, ln1w, ln1b, pahi, palo);
        gemm(base, pbq + l * 3 * Dn, pu, 3 * Dn, Dn);   // fused QKV
        k_post_qkv3<<<dim3(Mn, 3), 128>>>(pu, pqf, pkf, plh, pll,
                                          pq2, pk2, plm, ratio_split);
        k_attn3<<<dim3(Sn / 128, BHn), 256, ATT2_SMEM>>>(
            pqf, pkf, plh, pll, pq2, pk2, plm, tau, gam, l, pm);

        k_concat2bf<<<Mn, 128>>>(pm, pahi, palo, ratio_cat);
        gemm(base + 3 * DD, bo + l * Dn, pu, Dn, Dn);
        // residual + pln(ln2) + bf16 for FFN1, fused
        k_expmadd_pln<<<Mn, 128>>>(pu, px, ln2w + l * Dn, ln2b + l * Dn, pahi, palo);

        // ---- FFN ----
        gemm(base + 4 * DD, b1 + l * FFn, pu, FFn, Dn);
        k_ffnmid2bf<<<Mn, 256>>>(pu, pahi, palo);
        gemm(base + 4 * DD + FD, b2 + l * Dn, pu, Dn, FFn);
        if (l < Ln - 1) {
            // residual + pln(next ln1) + bf16 for next QKV, fused
            k_expmadd_pln<<<Mn, 128>>>(pu, px, ln1w + (l + 1) * Dn, ln1b + (l + 1) * Dn,
                                       pahi, palo);
        } else {
            k_exp_madd<<<Mn, 128>>>(pu, px);
        }
    }

    // ---- head ----
    k_log2bf<<<Mn, 128>>>(px, pahi, palo);
    gemm(4 * WLL, bout, pu, Dn, Dn);
    k_expmap_out<<<Mn, 128>>>(pu, outp);
}

// round 13
// speedup vs baseline: 3.0747x; 1.0003x over previous
#include <cuda_runtime.h>
#include <cuda_bf16.h>
#include <cstdint>
#include <cmath>

// ---------------- problem constants ----------------
constexpr int Bn  = 2;
constexpr int Sn  = 1024;
constexpr int Dn  = 512;
constexpr int Hn  = 8;
constexpr int HDn = 64;
constexpr int FFn = 2048;
constexpr int Ln  = 4;
constexpr int Mn  = Bn * Sn;   // 2048
constexpr int BHn = Bn * Hn;   // 16
constexpr long long WLL = 4LL * Dn * Dn + 2LL * FFn * Dn;

#define EPSf   1e-7f
#define MAXNf  (1.0f - 1e-3f)

// ---------------- scratch ----------------
__device__ float g_x   [Mn * Dn];
__device__ float g_u   [Mn * FFn];
__device__ float g_mid [Mn * Dn];
__device__ float g_qf  [Mn * Dn];
__device__ float g_kf  [Mn * Dn];
__device__ float g_bqkv[Ln * 3 * Dn];
__device__ float g_q2  [BHn * Sn];
__device__ float g_k2  [BHn * Sn];
__device__ float g_lm1 [BHn * Sn];
__device__ __nv_bfloat16 g_lvh[Mn * Dn];
__device__ __nv_bfloat16 g_lvl[Mn * Dn];
__device__ __nv_bfloat16 g_ahi[Mn * FFn];
__device__ __nv_bfloat16 g_alo[Mn * FFn];
__device__ __nv_bfloat16 g_Whi[4 * WLL + Dn * Dn];
__device__ __nv_bfloat16 g_Wlo[4 * WLL + Dn * Dn];

// ---------------- PTX helpers ----------------
static __device__ __forceinline__ uint32_t smem_u32(const void* p) {
    return (uint32_t)__cvta_generic_to_shared(p);
}
static __device__ __forceinline__ void cp16(uint32_t dst, const void* src) {
    asm volatile("cp.async.cg.shared.global [%0], [%1], 16;" :: "r"(dst), "l"(src));
}
static __device__ __forceinline__ void cp_commit() {
    asm volatile("cp.async.commit_group;" ::: "memory");
}
template<int N>
static __device__ __forceinline__ void cp_wait() {
    asm volatile("cp.async.wait_group %0;" :: "n"(N) : "memory");
}
static __device__ __forceinline__ void ldm4(uint32_t* r, uint32_t addr) {
    asm volatile("ldmatrix.sync.aligned.m8n8.x4.shared.b16 {%0,%1,%2,%3}, [%4];"
                 : "=r"(r[0]), "=r"(r[1]), "=r"(r[2]), "=r"(r[3]) : "r"(addr));
}
static __device__ __forceinline__ void ldm4t(uint32_t* r, uint32_t addr) {
    asm volatile("ldmatrix.sync.aligned.m8n8.x4.trans.shared.b16 {%0,%1,%2,%3}, [%4];"
                 : "=r"(r[0]), "=r"(r[1]), "=r"(r[2]), "=r"(r[3]) : "r"(addr));
}
static __device__ __forceinline__ void mma16816(float* d, const uint32_t* a, const uint32_t* b) {
    asm volatile("mma.sync.aligned.m16n8k16.row.col.f32.bf16.bf16.f32 "
                 "{%0,%1,%2,%3}, {%4,%5,%6,%7}, {%8,%9}, {%0,%1,%2,%3};"
                 : "+f"(d[0]), "+f"(d[1]), "+f"(d[2]), "+f"(d[3])
                 : "r"(a[0]), "r"(a[1]), "r"(a[2]), "r"(a[3]), "r"(b[0]), "r"(b[1]));
}
static __device__ __forceinline__ uint32_t f2tf(float x) {
    uint32_t r; asm("cvt.rna.tf32.f32 %0, %1;" : "=r"(r) : "f"(x)); return r;
}
static __device__ __forceinline__ void mma_tf32(float* d, const uint32_t* a, const uint32_t* b) {
    asm volatile("mma.sync.aligned.m16n8k8.row.col.f32.tf32.tf32.f32 "
                 "{%0,%1,%2,%3}, {%4,%5,%6,%7}, {%8,%9}, {%0,%1,%2,%3};"
                 : "+f"(d[0]), "+f"(d[1]), "+f"(d[2]), "+f"(d[3])
                 : "r"(a[0]), "r"(a[1]), "r"(a[2]), "r"(a[3]), "r"(b[0]), "r"(b[1]));
}

// ---------------- math helpers ----------------
static __device__ __forceinline__ float atanh_f(float x) {
    return 0.5f * (log1pf(x) - log1pf(-x));
}
template<int NT>
__device__ __forceinline__ float block_sum(float v) {
    __shared__ float sh[NT / 32];
#pragma unroll
    for (int o = 16; o > 0; o >>= 1) v += __shfl_xor_sync(0xffffffffu, v, o);
    int w = threadIdx.x >> 5;
    if ((threadIdx.x & 31) == 0) sh[w] = v;
    __syncthreads();
    float r = sh[0];
#pragma unroll
    for (int i = 1; i < NT / 32; i++) r += sh[i];
    __syncthreads();
    return r;
}
__device__ __forceinline__ float warp_sum(float v) {
#pragma unroll
    for (int o = 16; o > 0; o >>= 1) v += __shfl_xor_sync(0xffffffffu, v, o);
    return v;
}
__device__ __forceinline__ float group16_sum(float v) {
#pragma unroll
    for (int o = 8; o > 0; o >>= 1) v += __shfl_xor_sync(0xffffffffu, v, o);
    return v;
}
static __device__ __forceinline__ void store_split4(__nv_bfloat16* hi, __nv_bfloat16* lo,
                                                    size_t idx, float4 v) {
    __nv_bfloat16 h0 = __float2bfloat16(v.x), h1 = __float2bfloat16(v.y);
    __nv_bfloat16 h2 = __float2bfloat16(v.z), h3 = __float2bfloat16(v.w);
    __nv_bfloat16 l0 = __float2bfloat16(v.x - __bfloat162float(h0));
    __nv_bfloat16 l1 = __float2bfloat16(v.y - __bfloat162float(h1));
    __nv_bfloat16 l2 = __float2bfloat16(v.z - __bfloat162float(h2));
    __nv_bfloat16 l3 = __float2bfloat16(v.w - __bfloat162float(h3));
    ((__nv_bfloat162*)(hi + idx))[0] = __halves2bfloat162(h0, h1);
    ((__nv_bfloat162*)(hi + idx))[1] = __halves2bfloat162(h2, h3);
    ((__nv_bfloat162*)(lo + idx))[0] = __halves2bfloat162(l0, l1);
    ((__nv_bfloat162*)(lo + idx))[1] = __halves2bfloat162(l2, l3);
}

// ---------------- weight conversion ----------------
struct WCvtArgs {
    const float* src[25];
    long long    off[25];
    int          n4[25];
};
__global__ void k_wcvt(WCvtArgs a, __nv_bfloat16* __restrict__ hi, __nv_bfloat16* __restrict__ lo) {
    int t = blockIdx.y;
    int i = blockIdx.x * blockDim.x + threadIdx.x;
    if (i >= a.n4[t]) return;
    float4 v = ((const float4*)a.src[t])[i];
    store_split4(hi, lo, (size_t)a.off[t] + 4 * (size_t)i, v);
}
__global__ void k_bfill(const float* __restrict__ bq, const float* __restrict__ bk,
                        const float* __restrict__ bv, float* __restrict__ out) {
    int l = blockIdx.y;
    int i = blockIdx.x * blockDim.x + threadIdx.x;
    float v;
    if (i < Dn)            v = bq[l * Dn + i];
    else if (i < 2 * Dn)   v = bk[l * Dn + i - Dn];
    else                   v = bv[l * Dn + i - 2 * Dn];
    out[l * 3 * Dn + i] = v;
}

// ---------------- HMMA GEMM (3-pass split-bf16, 2-stage, 2 CTA/SM) ----------------
constexpr int LDS = 72;
constexpr int STAGE_E = 4 * 64 * LDS;
constexpr int GEMM_SMEM = 2 * STAGE_E * 2;   // 73728 B

__global__ void __launch_bounds__(128, 2)
k_gemm_mma(const __nv_bfloat16* __restrict__ Ahi, const __nv_bfloat16* __restrict__ Alo,
           const __nv_bfloat16* __restrict__ Whi, const __nv_bfloat16* __restrict__ Wlo,
           const float* __restrict__ bias, float* __restrict__ C, int Ni, int Ki)
{
    extern __shared__ __nv_bfloat16 sm[];
    const int tid = threadIdx.x, wid = tid >> 5, lane = tid & 31;
    const int bm = blockIdx.y * 64, bn = blockIdx.x * 64;
    const int wm = (wid >> 1) * 32, wn = (wid & 1) * 32;
    const uint32_t sbase = smem_u32(sm);

    float acc[2][4][4];
#pragma unroll
    for (int a = 0; a < 2; a++)
#pragma unroll
        for (int b = 0; b < 4; b++)
#pragma unroll
            for (int c = 0; c < 4; c++) acc[a][b][c] = 0.f;

    const int NC = Ki >> 6;

    auto load_stage = [&](int c) {
        const uint32_t sb = sbase + (uint32_t)(c & 1) * STAGE_E * 2;
        const size_t k0 = (size_t)c * 64;
#pragma unroll
        for (int i = tid; i < 512; i += 128) {
            int row = i >> 3, seg = i & 7;
            const size_t gA = (size_t)(bm + row) * Ki + k0 + seg * 8;
            const size_t gB = (size_t)(bn + row) * Ki + k0 + seg * 8;
            uint32_t ro = (uint32_t)(row * LDS + seg * 8) * 2;
            cp16(sb + ro,                 Ahi + gA);
            cp16(sb + 64 * LDS * 2 + ro,  Alo + gA);
            cp16(sb + 128 * LDS * 2 + ro, Whi + gB);
            cp16(sb + 192 * LDS * 2 + ro, Wlo + gB);
        }
        cp_commit();
    };

    uint32_t ah[2][2][4], al[2][2][4], bh[2][4][2], bl[2][4][2];
    auto ldfrag = [&](uint32_t sb, int kk, int bf) {
        uint32_t koff = (uint32_t)(kk * 16) * 2 + (lane >> 4) * 16;
#pragma unroll
        for (int mt = 0; mt < 2; mt++) {
            uint32_t rA = (uint32_t)(wm + mt * 16 + (lane & 15));
            ldm4(ah[bf][mt], sb + rA * (LDS * 2) + koff);
            ldm4(al[bf][mt], sb + (64 + rA) * (LDS * 2) + koff);
        }
#pragma unroll
        for (int nt2 = 0; nt2 < 2; nt2++) {
            uint32_t rB = (uint32_t)(128 + wn + nt2 * 16 + (lane & 15));
            uint32_t t[4];
            ldm4(t, sb + rB * (LDS * 2) + koff);
            bh[bf][nt2 * 2][0] = t[0]; bh[bf][nt2 * 2 + 1][0] = t[1];
            bh[bf][nt2 * 2][1] = t[2]; bh[bf][nt2 * 2 + 1][1] = t[3];
            ldm4(t, sb + (64 + rB) * (LDS * 2) + koff);
            bl[bf][nt2 * 2][0] = t[0]; bl[bf][nt2 * 2 + 1][0] = t[1];
            bl[bf][nt2 * 2][1] = t[2]; bl[bf][nt2 * 2 + 1][1] = t[3];
        }
    };

    load_stage(0);
    if (NC > 1) load_stage(1);

    for (int c = 0; c < NC; c++) {
        const uint32_t sb = sbase + (uint32_t)(c & 1) * STAGE_E * 2;
        cp_wait<1>();
        __syncthreads();

        ldfrag(sb, 0, 0);
#pragma unroll
        for (int kk = 0; kk < 4; kk++) {
            const int cur = kk & 1, nxt = cur ^ 1;
            if (kk < 3) ldfrag(sb, kk + 1, nxt);
#pragma unroll
            for (int mt = 0; mt < 2; mt++)
#pragma unroll
                for (int nt = 0; nt < 4; nt++)
                    mma16816(acc[mt][nt], ah[cur][mt], bh[cur][nt]);
#pragma unroll
            for (int mt = 0; mt < 2; mt++)
#pragma unroll
                for (int nt = 0; nt < 4; nt++)
                    mma16816(acc[mt][nt], ah[cur][mt], bl[cur][nt]);
#pragma unroll
            for (int mt = 0; mt < 2; mt++)
#pragma unroll
                for (int nt = 0; nt < 4; nt++)
                    mma16816(acc[mt][nt], al[cur][mt], bh[cur][nt]);
        }
        __syncthreads();
        if (c + 2 < NC) load_stage(c + 2);
    }

#pragma unroll
    for (int mt = 0; mt < 2; mt++) {
        int r0 = bm + wm + mt * 16 + (lane >> 2);
#pragma unroll
        for (int nt = 0; nt < 4; nt++) {
            int col = bn + wn + nt * 8 + 2 * (lane & 3);
            float b0 = bias[col], b1 = bias[col + 1];
            float2 v0 = make_float2(acc[mt][nt][0] + b0, acc[mt][nt][1] + b1);
            float2 v1 = make_float2(acc[mt][nt][2] + b0, acc[mt][nt][3] + b1);
            *(float2*)(C + (size_t)r0 * Ni + col) = v0;
            *(float2*)(C + (size_t)(r0 + 8) * Ni + col) = v1;
        }
    }
}

// ---------------- fused elementwise kernels (Round-10 block versions) ----------------

template<int NT>
__global__ void k_mobius_add(const float* __restrict__ x, const float* __restrict__ y,
                             float* __restrict__ out, int ymod) {
    constexpr int P = Dn / NT;
    int r = blockIdx.x;
    const float* xr = x + (size_t)r * Dn;
    const float* yr = y + (size_t)(r % ymod) * Dn;
    float xl[P], yl[P];
    float x2 = 0.f, y2 = 0.f, xy = 0.f;
#pragma unroll
    for (int i = 0; i < P; i++) {
        int j = threadIdx.x + i * NT;
        xl[i] = xr[j]; yl[i] = yr[j];
        x2 += xl[i] * xl[i]; y2 += yl[i] * yl[i]; xy += xl[i] * yl[i];
    }
    x2 = block_sum<NT>(x2);
    y2 = block_sum<NT>(y2);
    xy = block_sum<NT>(xy);
    float den = fmaxf(1.f + 2.f * xy + x2 * y2, EPSf);
    float ca = (1.f + 2.f * xy + y2) / den;
    float cb = (1.f - x2) / den;
    float zl[P]; float n2 = 0.f;
#pragma unroll
    for (int i = 0; i < P; i++) { zl[i] = ca * xl[i] + cb * yl[i]; n2 += zl[i] * zl[i]; }
    n2 = block_sum<NT>(n2);
    float n = sqrtf(fmaxf(n2, EPSf * EPSf));
    float sc = fminf(1.f, MAXNf / n);
#pragma unroll
    for (int i = 0; i < P; i++) out[(size_t)r * Dn + threadIdx.x + i * NT] = zl[i] * sc;
}

__global__ void __launch_bounds__(128)
k_pln2bf(const float* __restrict__ x, const float* __restrict__ w, const float* __restrict__ b,
         __nv_bfloat16* __restrict__ hi, __nv_bfloat16* __restrict__ lo) {
    int r = blockIdx.x, tid = threadIdx.x;
    const float* xr = x + (size_t)r * Dn;
    float4 xv = *(const float4*)(xr + tid * 4);
    float ss = xv.x * xv.x + xv.y * xv.y + xv.z * xv.z + xv.w * xv.w;
    ss = block_sum<128>(ss);
    float n  = sqrtf(fmaxf(ss, EPSf * EPSf));
    float nc = fminf(fmaxf(n, EPSf), MAXNf);
    float ls = atanh_f(nc) / nc;
    float4 tl = make_float4(ls * xv.x, ls * xv.y, ls * xv.z, ls * xv.w);
    float st = tl.x + tl.y + tl.z + tl.w;
    st = block_sum<128>(st);
    float mu = st / (float)Dn;
    float d0 = tl.x - mu, d1 = tl.y - mu, d2 = tl.z - mu, d3 = tl.w - mu;
    float sv = d0 * d0 + d1 * d1 + d2 * d2 + d3 * d3;
    sv = block_sum<128>(sv);
    float inv = rsqrtf(sv / (float)Dn + 1e-5f);
    float4 wv = *(const float4*)(w + tid * 4);
    float4 bv = *(const float4*)(b + tid * 4);
    float4 yv = make_float4(d0 * inv * wv.x + bv.x, d1 * inv * wv.y + bv.y,
                            d2 * inv * wv.z + bv.z, d3 * inv * wv.w + bv.w);
    float sy = yv.x * yv.x + yv.y * yv.y + yv.z * yv.z + yv.w * yv.w;
    sy = block_sum<128>(sy);
    float ny = sqrtf(fmaxf(sy, EPSf * EPSf));
    float es = tanhf(ny) / ny;
    float tb = tanhf(ny);
    float cb = fminf(fmaxf(tb, EPSf), MAXNf);
    float s2 = atanh_f(cb) / cb;
    float sc = es * s2;
    store_split4(hi, lo, (size_t)r * Dn + tid * 4,
                 make_float4(sc * yv.x, sc * yv.y, sc * yv.z, sc * yv.w));
}

// fused: x = project(mobius_add(x, expmap0(g))); then pln(x) -> logmap0 -> bf16 hi/lo
__global__ void __launch_bounds__(128)
k_expmadd_pln(const float* __restrict__ g, float* __restrict__ x,
              const float* __restrict__ w, const float* __restrict__ b,
              __nv_bfloat16* __restrict__ hi, __nv_bfloat16* __restrict__ lo) {
    int r = blockIdx.x, tid = threadIdx.x;
    float4 gv = *(const float4*)(g + (size_t)r * Dn + tid * 4);
    float4 xv = *(const float4*)(x + (size_t)r * Dn + tid * 4);
    float lg = gv.x * gv.x + gv.y * gv.y + gv.z * gv.z + gv.w * gv.w;
    float lx = xv.x * xv.x + xv.y * xv.y + xv.z * xv.z + xv.w * xv.w;
    float lxg = xv.x * gv.x + xv.y * gv.y + xv.z * gv.z + xv.w * gv.w;
    float g2 = block_sum<128>(lg);
    float x2 = block_sum<128>(lx);
    float xg = block_sum<128>(lxg);
    float ng = sqrtf(fmaxf(g2, EPSf * EPSf));
    float s  = tanhf(ng) / ng;
    float y2 = s * s * g2;
    float xy = s * xg;
    float den = fmaxf(1.f + 2.f * xy + x2 * y2, EPSf);
    float ca = (1.f + 2.f * xy + y2) / den;
    float cb2 = (1.f - x2) / den * s;
    float4 zv = make_float4(ca * xv.x + cb2 * gv.x, ca * xv.y + cb2 * gv.y,
                            ca * xv.z + cb2 * gv.z, ca * xv.w + cb2 * gv.w);
    float n2 = zv.x * zv.x + zv.y * zv.y + zv.z * zv.z + zv.w * zv.w;
    n2 = block_sum<128>(n2);
    float n = sqrtf(fmaxf(n2, EPSf * EPSf));
    float scp = fminf(1.f, MAXNf / n);
    float4 nx = make_float4(scp * zv.x, scp * zv.y, scp * zv.z, scp * zv.w);
    *(float4*)(x + (size_t)r * Dn + tid * 4) = nx;

    float ss = scp * scp * n2;
    float n1  = sqrtf(fmaxf(ss, EPSf * EPSf));
    float nc1 = fminf(fmaxf(n1, EPSf), MAXNf);
    float ls = atanh_f(nc1) / nc1;
    float4 tl = make_float4(ls * nx.x, ls * nx.y, ls * nx.z, ls * nx.w);
    float st = tl.x + tl.y + tl.z + tl.w;
    st = block_sum<128>(st);
    float mu = st / (float)Dn;
    float d0 = tl.x - mu, d1 = tl.y - mu, d2 = tl.z - mu, d3 = tl.w - mu;
    float sv = d0 * d0 + d1 * d1 + d2 * d2 + d3 * d3;
    sv = block_sum<128>(sv);
    float inv = rsqrtf(sv / (float)Dn + 1e-5f);
    float4 wv = *(const float4*)(w + tid * 4);
    float4 bv = *(const float4*)(b + tid * 4);
    float4 yv = make_float4(d0 * inv * wv.x + bv.x, d1 * inv * wv.y + bv.y,
                            d2 * inv * wv.z + bv.z, d3 * inv * wv.w + bv.w);
    float sy = yv.x * yv.x + yv.y * yv.y + yv.z * yv.z + yv.w * yv.w;
    sy = block_sum<128>(sy);
    float ny = sqrtf(fmaxf(sy, EPSf * EPSf));
    float es = tanhf(ny) / ny;
    float tb = tanhf(ny);
    float cb3 = fminf(fmaxf(tb, EPSf), MAXNf);
    float s2 = atanh_f(cb3) / cb3;
    float sc = es * s2;
    store_split4(hi, lo, (size_t)r * Dn + tid * 4,
                 make_float4(sc * yv.x, sc * yv.y, sc * yv.z, sc * yv.w));
}

// NEW (final-layer only): x' = project(mobius_add(x, expmap0(g))); logmap0(x') -> bf16 hi/lo
// Exact same block-reduction pattern as k_expmadd_pln; no x writeback (dead afterwards).
__global__ void __launch_bounds__(128)
k_expmadd_log2bf(const float* __restrict__ g, const float* __restrict__ x,
                 __nv_bfloat16* __restrict__ hi, __nv_bfloat16* __restrict__ lo) {
    int r = blockIdx.x, tid = threadIdx.x;
    float4 gv = *(const float4*)(g + (size_t)r * Dn + tid * 4);
    float4 xv = *(const float4*)(x + (size_t)r * Dn + tid * 4);
    float lg = gv.x * gv.x + gv.y * gv.y + gv.z * gv.z + gv.w * gv.w;
    float lx = xv.x * xv.x + xv.y * xv.y + xv.z * xv.z + xv.w * xv.w;
    float lxg = xv.x * gv.x + xv.y * gv.y + xv.z * gv.z + xv.w * gv.w;
    float g2 = block_sum<128>(lg);
    float x2 = block_sum<128>(lx);
    float xg = block_sum<128>(lxg);
    float ng = sqrtf(fmaxf(g2, EPSf * EPSf));
    float s  = tanhf(ng) / ng;
    float y2 = s * s * g2;
    float xy = s * xg;
    float den = fmaxf(1.f + 2.f * xy + x2 * y2, EPSf);
    float ca = (1.f + 2.f * xy + y2) / den;
    float cb2 = (1.f - x2) / den * s;
    float4 zv = make_float4(ca * xv.x + cb2 * gv.x, ca * xv.y + cb2 * gv.y,
                            ca * xv.z + cb2 * gv.z, ca * xv.w + cb2 * gv.w);
    float n2 = zv.x * zv.x + zv.y * zv.y + zv.z * zv.z + zv.w * zv.w;
    n2 = block_sum<128>(n2);
    float n = sqrtf(fmaxf(n2, EPSf * EPSf));
    float scp = fminf(1.f, MAXNf / n);
    // logmap0(scp*zv): norm = sqrt(scp^2 * n2)
    float ss = scp * scp * n2;
    float n1  = sqrtf(fmaxf(ss, EPSf * EPSf));
    float nc1 = fminf(fmaxf(n1, EPSf), MAXNf);
    float ls = atanh_f(nc1) / nc1;
    float sc = ls * scp;
    store_split4(hi, lo, (size_t)r * Dn + tid * 4,
                 make_float4(sc * zv.x, sc * zv.y, sc * zv.z, sc * zv.w));
}

// fused-QKV post (Round-10 block version): Q/K -> fp32 (+q2/k2), V -> lamv bf16 hi/lo (+lm1)
__global__ void __launch_bounds__(128)
k_post_qkv3(const float* __restrict__ u,
            float* __restrict__ qf, float* __restrict__ kf,
            __nv_bfloat16* __restrict__ lvh, __nv_bfloat16* __restrict__ lvl,
            float* __restrict__ q2g, float* __restrict__ k2g, float* __restrict__ lmg,
            float ratio) {
    int which = blockIdx.y;
    int r = blockIdx.x, tid = threadIdx.x;
    int b = r / Sn, s = r % Sn;
    float4 uv = *(const float4*)(u + (size_t)r * (3 * Dn) + which * Dn + tid * 4);
    float ss = uv.x * uv.x + uv.y * uv.y + uv.z * uv.z + uv.w * uv.w;
    float bs = block_sum<128>(ss);
    float n  = sqrtf(fmaxf(bs, EPSf * EPSf));
    float s1 = tanhf(n) / n;
    float t  = tanhf(n);
    float c  = fminf(fmaxf(t, EPSf), MAXNf);
    float s2 = atanh_f(c) / c;
    float sc = s1 * s2 * ratio;
    float4 th = make_float4(sc * uv.x, sc * uv.y, sc * uv.z, sc * uv.w);
    float hs = sc * sc * ss;
    hs = group16_sum(hs);
    float nh = sqrtf(fmaxf(hs, EPSf * EPSf));
    float es = tanhf(nh) / nh;
    int h = tid >> 4;
    size_t row = (size_t)(b * Hn + h) * Sn + s;
    size_t dst = row * HDn + (tid & 15) * 4;
    if (which == 0) {
        *(float4*)(qf + dst) = make_float4(es * th.x, es * th.y, es * th.z, es * th.w);
        if ((tid & 15) == 0) q2g[row] = es * es * hs;
    } else if (which == 1) {
        *(float4*)(kf + dst) = make_float4(es * th.x, es * th.y, es * th.z, es * th.w);
        if ((tid & 15) == 0) k2g[row] = es * es * hs;
    } else {
        float vsq = es * es * hs;
        float lam = 2.f / fmaxf(1.f - vsq, EPSf);
        float ls2 = lam * es;
        store_split4(lvh, lvl, dst, make_float4(ls2 * th.x, ls2 * th.y, ls2 * th.z, ls2 * th.w));
        if ((tid & 15) == 0) lmg[row] = lam - 1.f;
    }
}

// ---------------- fused attention: 3xTF32 HMMA QK + MUFU transform + HMMA PV ----------------
// (Round-10 version, verbatim)
constexpr int ALD = 72;
constexpr int O_QS  = 0;
constexpr int O_KS  = 17408;
constexpr int O_LVH = 34816;
constexpr int O_LVL = 44032;
constexpr int O_PHI = 53248;
constexpr int O_PLO = 62464;
constexpr int O_Q2  = 71680;
constexpr int O_K2  = 71936;
constexpr int O_LMS = 72192;
constexpr int O_RS  = 72448;
constexpr int O_DS  = 72960;
constexpr int O_INV = 73472;
constexpr int ATT2_SMEM = 73728;

__global__ void __launch_bounds__(256)
k_attn3(const float* __restrict__ qf, const float* __restrict__ kf,
        const __nv_bfloat16* __restrict__ lvh, const __nv_bfloat16* __restrict__ lvl,
        const float* __restrict__ q2g, const float* __restrict__ k2g,
        const float* __restrict__ lmg,
        const float* __restrict__ tau, const float* __restrict__ gam, int l,
        float* __restrict__ mid)
{
    extern __shared__ char smb[];
    float* smf = (float*)smb;
    const uint32_t sb = smem_u32(smb);
    const int tid = threadIdx.x, wid = tid >> 5, lane = tid & 31;
    const int gid = lane >> 2, tig = lane & 3;
    const int bh = blockIdx.y;
    const int wm = (wid >> 1) * 16, wn = (wid & 1) * 32;
    const float tv = tau[l], gv = gam[l];

    for (int p = 0; p < 2; p++) {
        const int it = p ? (15 - (int)blockIdx.x) : (int)blockIdx.x;

        {   // Q -> row-major fp32 smem [i][d] (stride 68), q2
            const float* Q = qf + ((size_t)bh * Sn + it * 64) * HDn;
#pragma unroll
            for (int f = tid; f < 1024; f += 256) {
                int row = f >> 4, c = (f & 15) * 4;
                *(float4*)&smf[row * 68 + c] = *(const float4*)(Q + row * HDn + c);
            }
            if (tid < 64) smf[O_Q2 / 4 + tid] = q2g[(size_t)bh * Sn + it * 64 + tid];
        }
        float acc2[4][4];
#pragma unroll
        for (int a = 0; a < 4; a++)
#pragma unroll
            for (int c = 0; c < 4; c++) acc2[a][c] = 0.f;
        float rs_t[2] = {0.f, 0.f};
        float ds_t[2] = {0.f, 0.f};
        __syncthreads();

        for (int jt = 0; jt <= it; jt++) {
            {   // K -> row-major fp32 smem [j][d]; lamv bf16 hi/lo; k2/lms
                const float* K = kf + ((size_t)bh * Sn + jt * 64) * HDn;
#pragma unroll
                for (int f = tid; f < 1024; f += 256) {
                    int row = f >> 4, c = (f & 15) * 4;
                    *(float4*)&smf[O_KS / 4 + row * 68 + c] = *(const float4*)(K + row * HDn + c);
                }
                const size_t rb = ((size_t)bh * Sn + jt * 64) * HDn;
#pragma unroll
                for (int i = tid; i < 512; i += 256) {
                    int row = i >> 3, seg = i & 7;
                    uint32_t ro = (uint32_t)(row * ALD + seg * 8) * 2;
                    cp16(sb + O_LVH + ro, lvh + rb + row * HDn + seg * 8);
                    cp16(sb + O_LVL + ro, lvl + rb + row * HDn + seg * 8);
                }
                cp_commit();
                if (tid < 64) {
                    smf[O_K2 / 4 + tid]  = k2g[(size_t)bh * Sn + jt * 64 + tid];
                    smf[O_LMS / 4 + tid] = lmg[(size_t)bh * Sn + jt * 64 + tid];
                }
            }
            cp_wait<0>();
            __syncthreads();

            // ---- QK^T via 3xTF32 mma (m16n8k8) ----
            float sacc[4][4];
#pragma unroll
            for (int a = 0; a < 4; a++)
#pragma unroll
                for (int c = 0; c < 4; c++) sacc[a][c] = 0.f;
#pragma unroll
            for (int kc = 0; kc < 8; kc++) {
                const int d0 = kc * 8 + tig;
                float a0 = smf[(wm + gid) * 68 + d0];
                float a1 = smf[(wm + gid + 8) * 68 + d0];
                float a2 = smf[(wm + gid) * 68 + d0 + 4];
                float a3 = smf[(wm + gid + 8) * 68 + d0 + 4];
                uint32_t ah[4] = {f2tf(a0), f2tf(a1), f2tf(a2), f2tf(a3)};
                uint32_t al[4] = {f2tf(a0 - __uint_as_float(ah[0])),
                                  f2tf(a1 - __uint_as_float(ah[1])),
                                  f2tf(a2 - __uint_as_float(ah[2])),
                                  f2tf(a3 - __uint_as_float(ah[3]))};
                uint32_t bhv[4][2], blv[4][2];
#pragma unroll
                for (int nt = 0; nt < 4; nt++) {
                    float b0 = smf[O_KS / 4 + (wn + nt * 8 + gid) * 68 + d0];
                    float b1 = smf[O_KS / 4 + (wn + nt * 8 + gid) * 68 + d0 + 4];
                    bhv[nt][0] = f2tf(b0); bhv[nt][1] = f2tf(b1);
                    blv[nt][0] = f2tf(b0 - __uint_as_float(bhv[nt][0]));
                    blv[nt][1] = f2tf(b1 - __uint_as_float(bhv[nt][1]));
                }
#pragma unroll
                for (int nt = 0; nt < 4; nt++) mma_tf32(sacc[nt], ah, bhv[nt]);
#pragma unroll
                for (int nt = 0; nt < 4; nt++) mma_tf32(sacc[nt], ah, blv[nt]);
#pragma unroll
                for (int nt = 0; nt < 4; nt++) mma_tf32(sacc[nt], al, bhv[nt]);
            }

            // ---- MUFU score transform + bf16-split P + row partials ----
            const bool diag = (jt == it);
            {
                const int r0 = wm + gid;
                float qq0 = smf[O_Q2 / 4 + r0], qq1 = smf[O_Q2 / 4 + r0 + 8];
                float di0 = 1.f - qq0, di1 = 1.f - qq1;
#pragma unroll
                for (int nt = 0; nt < 4; nt++) {
                    int c0 = wn + nt * 8 + 2 * tig;
                    float kk0 = smf[O_K2 / 4 + c0],  kk1 = smf[O_K2 / 4 + c0 + 1];
                    float lm0 = smf[O_LMS / 4 + c0], lm1v = smf[O_LMS / 4 + c0 + 1];
                    float dj0 = 1.f - kk0, dj1 = 1.f - kk1;
                    float e[4];
#pragma unroll
                    for (int z = 0; z < 4; z++) {
                        float qq = (z < 2) ? qq0 : qq1;
                        float di = (z < 2) ? di0 : di1;
                        float kk2 = (z & 1) ? kk1 : kk0;
                        float dj = (z & 1) ? dj1 : dj0;
                        float d2 = fmaxf(qq + kk2 - 2.f * sacc[nt][z], 0.f);
                        float dn = fmaxf(di * dj, EPSf);
                        float uu = fmaxf(__fdividef(2.f * d2, dn), 1.1920929e-7f);
                        float ar = uu * (uu + 2.f);
                        float w = 1.f + uu + ar * rsqrtf(ar);
                        e[z] = __expf(fmaf(-tv, __logf(w), -gv));
                    }
                    if (diag) {
                        if (c0 > r0)         e[0] = 0.f;
                        if (c0 + 1 > r0)     e[1] = 0.f;
                        if (c0 > r0 + 8)     e[2] = 0.f;
                        if (c0 + 1 > r0 + 8) e[3] = 0.f;
                    }
                    rs_t[0] += e[0] + e[1];
                    ds_t[0] += e[0] * lm0 + e[1] * lm1v;
                    rs_t[1] += e[2] + e[3];
                    ds_t[1] += e[2] * lm0 + e[3] * lm1v;
                    __nv_bfloat16 h00 = __float2bfloat16(e[0]), h01 = __float2bfloat16(e[1]);
                    __nv_bfloat16 h10 = __float2bfloat16(e[2]), h11 = __float2bfloat16(e[3]);
                    *(__nv_bfloat162*)(smb + O_PHI + (r0 * ALD + c0) * 2) = __halves2bfloat162(h00, h01);
                    *(__nv_bfloat162*)(smb + O_PHI + ((r0 + 8) * ALD + c0) * 2) = __halves2bfloat162(h10, h11);
                    *(__nv_bfloat162*)(smb + O_PLO + (r0 * ALD + c0) * 2) = __halves2bfloat162(
                        __float2bfloat16(e[0] - __bfloat162float(h00)),
                        __float2bfloat16(e[1] - __bfloat162float(h01)));
                    *(__nv_bfloat162*)(smb + O_PLO + ((r0 + 8) * ALD + c0) * 2) = __halves2bfloat162(
                        __float2bfloat16(e[2] - __bfloat162float(h10)),
                        __float2bfloat16(e[3] - __bfloat162float(h11)));
                }
            }
            __syncthreads();

            // ---- HMMA PV: acc2 += P · λv (3-pass bf16 split) ----
#pragma unroll
            for (int kk = 0; kk < 4; kk++) {
                uint32_t koff = (uint32_t)(kk * 16) * 2 + (lane >> 4) * 16;
                uint32_t ph[4], pl[4], vh_[4][2], vl_[4][2];
                uint32_t rA = (uint32_t)(wm + (lane & 15));
                ldm4(ph, sb + O_PHI + rA * (ALD * 2) + koff);
                ldm4(pl, sb + O_PLO + rA * (ALD * 2) + koff);
#pragma unroll
                for (int q = 0; q < 2; q++) {
                    uint32_t row = (uint32_t)(kk * 16 + (lane & 15));
                    uint32_t col = (uint32_t)(wn + q * 16 + ((lane >> 4) << 3));
                    uint32_t t[4];
                    ldm4t(t, sb + O_LVH + (row * ALD + col) * 2);
                    vh_[q * 2][0] = t[0]; vh_[q * 2][1] = t[1];
                    vh_[q * 2 + 1][0] = t[2]; vh_[q * 2 + 1][1] = t[3];
                    ldm4t(t, sb + O_LVL + (row * ALD + col) * 2);
                    vl_[q * 2][0] = t[0]; vl_[q * 2][1] = t[1];
                    vl_[q * 2 + 1][0] = t[2]; vl_[q * 2 + 1][1] = t[3];
                }
#pragma unroll
                for (int nt = 0; nt < 4; nt++) mma16816(acc2[nt], ph, vh_[nt]);
#pragma unroll
                for (int nt = 0; nt < 4; nt++) mma16816(acc2[nt], ph, vl_[nt]);
#pragma unroll
                for (int nt = 0; nt < 4; nt++) mma16816(acc2[nt], pl, vh_[nt]);
            }
            __syncthreads();
        }

        // ---- reduce row sums across tig lanes + the two n-warps ----
#pragma unroll
        for (int hf = 0; hf < 2; hf++) {
            float v = rs_t[hf];
            v += __shfl_xor_sync(0xffffffffu, v, 1);
            v += __shfl_xor_sync(0xffffffffu, v, 2);
            float w = ds_t[hf];
            w += __shfl_xor_sync(0xffffffffu, w, 1);
            w += __shfl_xor_sync(0xffffffffu, w, 2);
            if (tig == 0) {
                int r = wm + hf * 8 + gid;
                int half = (wid & 1) * 64;
                smf[O_RS / 4 + half + r] = v;
                smf[O_DS / 4 + half + r] = w;
            }
        }
        __syncthreads();
        if (tid < 64) {
            float rst = smf[O_RS / 4 + tid] + smf[O_RS / 4 + 64 + tid];
            float dst = smf[O_DS / 4 + tid] + smf[O_DS / 4 + 64 + tid];
            smf[O_INV / 4 + tid] = __fdividef(1.f, fmaxf(dst, EPSf * rst));
        }
        __syncthreads();

        // ---- num = acc2 * inv -> NUM smem (alias Ks region, stride 68) ----
        {
            int r0 = wm + gid;
            float i0 = smf[O_INV / 4 + r0], i1 = smf[O_INV / 4 + r0 + 8];
#pragma unroll
            for (int nt = 0; nt < 4; nt++) {
                int c0 = wn + nt * 8 + 2 * tig;
                smf[O_KS / 4 + r0 * 68 + c0]           = acc2[nt][0] * i0;
                smf[O_KS / 4 + r0 * 68 + c0 + 1]       = acc2[nt][1] * i0;
                smf[O_KS / 4 + (r0 + 8) * 68 + c0]     = acc2[nt][2] * i1;
                smf[O_KS / 4 + (r0 + 8) * 68 + c0 + 1] = acc2[nt][3] * i1;
            }
        }
        __syncthreads();

        // ---- mobius_scalar_mul(0.5) + project, write mid ----
        {
            int r = tid >> 2, cg = (tid & 3) * 16;
            const float* nr = smf + O_KS / 4 + r * 68 + cg;
            float ss2 = 0.f;
#pragma unroll
            for (int c = 0; c < 16; c++) { float m = nr[c]; ss2 += m * m; }
            ss2 += __shfl_xor_sync(0xffffffffu, ss2, 1);
            ss2 += __shfl_xor_sync(0xffffffffu, ss2, 2);
            float n  = sqrtf(fmaxf(ss2, EPSf * EPSf));
            float nc = fminf(fmaxf(n, EPSf), MAXNf);
            float tt = tanhf(0.5f * atanh_f(nc));
            float s1 = tt / nc;
            float ny = sqrtf(fmaxf(s1 * s1 * ss2, EPSf * EPSf));
            float s2 = fminf(1.f, MAXNf / ny);
            float sc = s1 * s2;
            float* dst = mid + ((size_t)bh * Sn + it * 64 + r) * HDn + cg;
#pragma unroll
            for (int c = 0; c < 16; c += 4)
                *(float4*)(dst + c) = make_float4(sc * nr[c], sc * nr[c + 1],
                                                  sc * nr[c + 2], sc * nr[c + 3]);
        }
        __syncthreads();
    }
}

// concat heads -> expmap0 -> logmap0 -> bf16 hi/lo (Round-10 block version)
__global__ void __launch_bounds__(128)
k_concat2bf(const float* __restrict__ mh, __nv_bfloat16* __restrict__ hi,
            __nv_bfloat16* __restrict__ lo, float ratio) {
    int r = blockIdx.x, tid = threadIdx.x;
    int b = r / Sn, s = r % Sn;
    __shared__ float row[Dn];
    int warp = tid >> 5, lane = tid & 31;
#pragma unroll
    for (int hh = 0; hh < 2; hh++) {
        int h = warp * 2 + hh;
        const float* src = mh + ((size_t)((b * Hn + h) * Sn + s)) * HDn;
        float v0 = src[lane], v1 = src[lane + 32];
        float ss = warp_sum(v0 * v0 + v1 * v1);
        float n  = sqrtf(fmaxf(ss, EPSf * EPSf));
        float nc = fminf(fmaxf(n, EPSf), MAXNf);
        float sc = atanh_f(nc) / nc * ratio;
        row[h * HDn + lane]      = sc * v0;
        row[h * HDn + lane + 32] = sc * v1;
    }
    __syncthreads();
    float4 vl = *(const float4*)&row[tid * 4];
    float ss = vl.x * vl.x + vl.y * vl.y + vl.z * vl.z + vl.w * vl.w;
    ss = block_sum<128>(ss);
    float n  = sqrtf(fmaxf(ss, EPSf * EPSf));
    float es = tanhf(n) / n;
    float tb = tanhf(n);
    float cb = fminf(fmaxf(tb, EPSf), MAXNf);
    float s2 = atanh_f(cb) / cb;
    float sc = es * s2;
    store_split4(hi, lo, (size_t)r * Dn + tid * 4,
                 make_float4(sc * vl.x, sc * vl.y, sc * vl.z, sc * vl.w));
}

__global__ void __launch_bounds__(256)
k_ffnmid2bf(const float* __restrict__ u, __nv_bfloat16* __restrict__ hi,
            __nv_bfloat16* __restrict__ lo) {
    int r = blockIdx.x, tid = threadIdx.x;
    const float* ur = u + (size_t)r * FFn;
    float4 u0 = *(const float4*)(ur + tid * 4);
    float4 u1 = *(const float4*)(ur + 1024 + tid * 4);
    float ss = u0.x * u0.x + u0.y * u0.y + u0.z * u0.z + u0.w * u0.w
             + u1.x * u1.x + u1.y * u1.y + u1.z * u1.z + u1.w * u1.w;
    ss = block_sum<256>(ss);
    float n0 = sqrtf(fmaxf(ss, EPSf * EPSf));
    float t0 = tanhf(n0);
    float s1 = t0 / n0;
    float c0 = fminf(fmaxf(t0, EPSf), MAXNf);
    float a0 = atanh_f(c0) / c0;
    float w  = a0 * s1;
    float4 r0 = make_float4(fmaxf(w * u0.x, 0.f), fmaxf(w * u0.y, 0.f),
                            fmaxf(w * u0.z, 0.f), fmaxf(w * u0.w, 0.f));
    float4 r1 = make_float4(fmaxf(w * u1.x, 0.f), fmaxf(w * u1.y, 0.f),
                            fmaxf(w * u1.z, 0.f), fmaxf(w * u1.w, 0.f));
    float st = r0.x * r0.x + r0.y * r0.y + r0.z * r0.z + r0.w * r0.w
             + r1.x * r1.x + r1.y * r1.y + r1.z * r1.z + r1.w * r1.w;
    st = block_sum<256>(st);
    float n1 = sqrtf(fmaxf(st, EPSf * EPSf));
    float e1 = tanhf(n1) / n1;
    float t1 = tanhf(n1);
    float c1 = fminf(fmaxf(t1, EPSf), MAXNf);
    float a1 = atanh_f(c1) / c1;
    float sc = a1 * e1;
    store_split4(hi, lo, (size_t)r * FFn + tid * 4,
                 make_float4(sc * r0.x, sc * r0.y, sc * r0.z, sc * r0.w));
    store_split4(hi, lo, (size_t)r * FFn + 1024 + tid * 4,
                 make_float4(sc * r1.x, sc * r1.y, sc * r1.z, sc * r1.w));
}

__global__ void __launch_bounds__(128)
k_expmap_out(const float* __restrict__ x, float* __restrict__ out) {
    int r = blockIdx.x, tid = threadIdx.x;
    float4 xv = *(const float4*)(x + (size_t)r * Dn + tid * 4);
    float ss = xv.x * xv.x + xv.y * xv.y + xv.z * xv.z + xv.w * xv.w;
    ss = block_sum<128>(ss);
    float n = sqrtf(fmaxf(ss, EPSf * EPSf));
    float s = tanhf(n) / n;
    *(float4*)(out + (size_t)r * Dn + tid * 4) =
        make_float4(s * xv.x, s * xv.y, s * xv.z, s * xv.w);
}

// ---------------- host orchestration ----------------
extern "C" void kernel_launch(void* const* d_in, const int* in_sizes, int n_in,
                              void* d_out, int out_size) {
    (void)in_sizes; (void)n_in; (void)out_size;
    const float* x    = (const float*)d_in[0];
    const float* pos  = (const float*)d_in[1];
    const float* ln1w = (const float*)d_in[2];
    const float* ln1b = (const float*)d_in[3];
    const float* ln2w = (const float*)d_in[4];
    const float* ln2b = (const float*)d_in[5];
    const float* Wq   = (const float*)d_in[6];
    const float* bq   = (const float*)d_in[7];
    const float* Wk   = (const float*)d_in[8];
    const float* bk   = (const float*)d_in[9];
    const float* Wv   = (const float*)d_in[10];
    const float* bv   = (const float*)d_in[11];
    const float* Wo   = (const float*)d_in[12];
    const float* bo   = (const float*)d_in[13];
    const float* W1   = (const float*)d_in[14];
    const float* b1   = (const float*)d_in[15];
    const float* W2   = (const float*)d_in[16];
    const float* b2   = (const float*)d_in[17];
    const float* tau  = (const float*)d_in[18];
    const float* gam  = (const float*)d_in[19];
    const float* Wout = (const float*)d_in[20];
    const float* bout = (const float*)d_in[21];
    float* outp = (float*)d_out;

    float *px, *pu, *pm, *pqf, *pkf, *pbq, *pq2, *pk2, *plm;
    __nv_bfloat16 *pahi, *palo, *pwhi, *pwlo, *plh, *pll;
    cudaGetSymbolAddress((void**)&px,  g_x);
    cudaGetSymbolAddress((void**)&pu,  g_u);
    cudaGetSymbolAddress((void**)&pm,  g_mid);
    cudaGetSymbolAddress((void**)&pqf, g_qf);
    cudaGetSymbolAddress((void**)&pkf, g_kf);
    cudaGetSymbolAddress((void**)&pbq, g_bqkv);
    cudaGetSymbolAddress((void**)&pq2, g_q2);
    cudaGetSymbolAddress((void**)&pk2, g_k2);
    cudaGetSymbolAddress((void**)&plm, g_lm1);
    cudaGetSymbolAddress((void**)&plh, g_lvh);
    cudaGetSymbolAddress((void**)&pll, g_lvl);
    cudaGetSymbolAddress((void**)&pahi, g_ahi);
    cudaGetSymbolAddress((void**)&palo, g_alo);
    cudaGetSymbolAddress((void**)&pwhi, g_Whi);
    cudaGetSymbolAddress((void**)&pwlo, g_Wlo);

    cudaFuncSetAttribute((const void*)k_gemm_mma,
                         cudaFuncAttributeMaxDynamicSharedMemorySize, GEMM_SMEM);
    cudaFuncSetAttribute((const void*)k_gemm_mma,
                         cudaFuncAttributePreferredSharedMemoryCarveout, 100);
    cudaFuncSetAttribute((const void*)k_attn3,
                         cudaFuncAttributeMaxDynamicSharedMemorySize, ATT2_SMEM);
    cudaFuncSetAttribute((const void*)k_attn3,
                         cudaFuncAttributePreferredSharedMemoryCarveout, 100);

    double betaD  = std::exp(std::lgamma(Dn / 2.0)  + std::lgamma(0.5) - std::lgamma(Dn / 2.0 + 0.5));
    double betaHD = std::exp(std::lgamma(HDn / 2.0) + std::lgamma(0.5) - std::lgamma(HDn / 2.0 + 0.5));
    float ratio_split = (float)(betaHD / betaD);
    float ratio_cat   = (float)(betaD / betaHD);

    constexpr int DD = Dn * Dn, FD = FFn * Dn;
    WCvtArgs wa;
    int idx = 0;
    auto add = [&](const float* s, long long off, int n) {
        wa.src[idx] = s; wa.off[idx] = off; wa.n4[idx] = n / 4; idx++;
    };
    for (int l = 0; l < Ln; l++) {
        long long base = l * WLL;
        add(Wq + (size_t)l * DD, base,               DD);
        add(Wk + (size_t)l * DD, base + DD,          DD);
        add(Wv + (size_t)l * DD, base + 2 * DD,      DD);
        add(Wo + (size_t)l * DD, base + 3 * DD,      DD);
        add(W1 + (size_t)l * FD, base + 4 * DD,      FD);
        add(W2 + (size_t)l * FD, base + 4 * DD + FD, FD);
    }
    add(Wout, 4 * WLL, DD);
    k_wcvt<<<dim3(1024, 25), 256>>>(wa, pwhi, pwlo);
    k_bfill<<<dim3(6, Ln), 256>>>(bq, bk, bv, pbq);

    auto gemm = [&](long long woff, const float* bias, float* Cout, int Ni, int Ki) {
        k_gemm_mma<<<dim3(Ni / 64, Mn / 64), 128, GEMM_SMEM>>>(
            pahi, palo, pwhi + woff, pwlo + woff, bias, Cout, Ni, Ki);
    };

    k_mobius_add<128><<<Mn, 128>>>(x, pos, px, Sn);

    for (int l = 0; l < Ln; l++) {
        long long base = l * WLL;
        // ---- attention ----
        if (l == 0)
            k_pln2bf<<<Mn, 128>>>(px, ln1w, ln1b, pahi, palo);
        gemm(base, pbq + l * 3 * Dn, pu, 3 * Dn, Dn);   // fused QKV
        k_post_qkv3<<<dim3(Mn, 3), 128>>>(pu, pqf, pkf, plh, pll,
                                          pq2, pk2, plm, ratio_split);
        k_attn3<<<dim3(Sn / 128, BHn), 256, ATT2_SMEM>>>(
            pqf, pkf, plh, pll, pq2, pk2, plm, tau, gam, l, pm);

        k_concat2bf<<<Mn, 128>>>(pm, pahi, palo, ratio_cat);
        gemm(base + 3 * DD, bo + l * Dn, pu, Dn, Dn);
        k_expmadd_pln<<<Mn, 128>>>(pu, px, ln2w + l * Dn, ln2b + l * Dn, pahi, palo);

        // ---- FFN ----
        gemm(base + 4 * DD, b1 + l * FFn, pu, FFn, Dn);
        k_ffnmid2bf<<<Mn, 256>>>(pu, pahi, palo);
        gemm(base + 4 * DD + FD, b2 + l * Dn, pu, Dn, FFn);
        if (l < Ln - 1) {
            k_expmadd_pln<<<Mn, 128>>>(pu, px, ln1w + (l + 1) * Dn, ln1b + (l + 1) * Dn,
                                       pahi, palo);
        } else {
            // final layer: fused residual + logmap -> bf16 (no x writeback needed)
            k_expmadd_log2bf<<<Mn, 128>>>(pu, px, pahi, palo);
        }
    }

    // ---- head ----
    gemm(4 * WLL, bout, pu, Dn, Dn);
    k_expmap_out<<<Mn, 128>>>(pu, outp);
}